// round 1
// baseline (speedup 1.0000x reference)
#include <cuda_runtime.h>
#include <cuda_bf16.h>
#include <math.h>

#define Nc 50000
#define Ec 25000
#define Mc 300000
// dims: INPUT=VERTEX=EDGE=256, QUERY=64, NUM_CLASS=10

// ---------------- scratch (static device globals; no runtime alloc) ----------------
__device__ float g_feat_v[(size_t)Nc * 256];
__device__ float g_Wh[(size_t)Nc * 256];
__device__ float g_q[(size_t)Nc * 64];
__device__ float g_k[(size_t)Ec * 64];
__device__ float g_v[(size_t)Ec * 256];
__device__ float g_attn[Mc];
__device__ int g_eoff[Ec + 1];
__device__ int g_voff[Nc + 1];
__device__ int g_ecnt[Ec];
__device__ int g_vcnt[Nc];
__device__ int g_ecur[Ec];
__device__ int g_vcur[Nc];
__device__ int g_elist[Mc];  // per-hyperedge incidence list: stores src vertex id
__device__ int g_vlist[Mc];  // per-vertex incidence list: stores dst hyperedge id

// ---------------- CSR build ----------------
__global__ void zero_cnts_kernel() {
    int i = blockIdx.x * blockDim.x + threadIdx.x;
    if (i < Ec) { g_ecnt[i] = 0; g_ecur[i] = 0; }
    if (i < Nc) { g_vcnt[i] = 0; g_vcur[i] = 0; }
}

__global__ void hist_kernel(const int* __restrict__ in_src, const int* __restrict__ in_dst) {
    int m = blockIdx.x * blockDim.x + threadIdx.x;
    if (m >= Mc) return;
    atomicAdd(&g_ecnt[in_dst[m]], 1);
    atomicAdd(&g_vcnt[in_src[m]], 1);
}

// which==0: scan g_ecnt -> g_eoff (len Ec); which==1: g_vcnt -> g_voff (len Nc)
__global__ void scan_kernel(int which) {
    __shared__ int buf[1024];
    __shared__ int carry;
    const int* cnt = (which == 0) ? g_ecnt : g_vcnt;
    int* off = (which == 0) ? g_eoff : g_voff;
    int L = (which == 0) ? Ec : Nc;
    int t = threadIdx.x;
    if (t == 0) carry = 0;
    __syncthreads();
    for (int base = 0; base < L; base += 1024) {
        int i = base + t;
        int x = (i < L) ? cnt[i] : 0;
        buf[t] = x;
        __syncthreads();
        for (int s = 1; s < 1024; s <<= 1) {
            int v = (t >= s) ? buf[t - s] : 0;
            __syncthreads();
            buf[t] += v;
            __syncthreads();
        }
        if (i < L) off[i] = carry + buf[t] - x;  // exclusive
        __syncthreads();
        if (t == 0) carry += buf[1023];
        __syncthreads();
    }
    if (t == 0) off[L] = carry;
}

__global__ void scatter_kernel(const int* __restrict__ in_src, const int* __restrict__ in_dst) {
    int m = blockIdx.x * blockDim.x + threadIdx.x;
    if (m >= Mc) return;
    int s = in_src[m];
    int e = in_dst[m];
    int pe = atomicAdd(&g_ecur[e], 1);
    g_elist[g_eoff[e] + pe] = s;
    int pv = atomicAdd(&g_vcur[s], 1);
    g_vlist[g_voff[s] + pv] = e;
}

// ---------------- GEMM: C[M,N] = A[M,K=256] * W[N,K]^T + bias ----------------
// 64x64 block tile, 16 K-slice, 16x16 threads each computing 4x4.
__global__ __launch_bounds__(256) void gemm_nt_bias(
    const float* __restrict__ A, const float* __restrict__ W,
    const float* __restrict__ bias, float* __restrict__ C,
    int Mrows, int Nout) {
    __shared__ float As[16][68];  // [k][m], stride 68 (aligned for float4, reduced STS conflicts)
    __shared__ float Bs[16][68];  // [k][n]
    const int K = 256;
    int tid = threadIdx.x;
    int tx = tid & 15, ty = tid >> 4;
    int bm = blockIdx.x * 64, bn = blockIdx.y * 64;
    int lrow = tid >> 2;          // 0..63
    int lk4 = (tid & 3) * 4;      // 0,4,8,12
    const float* Ag = A + (size_t)(bm + lrow) * K + lk4;
    const float* Wg = W + (size_t)(bn + lrow) * K + lk4;
    bool arow_ok = (bm + lrow) < Mrows;

    float acc[4][4];
#pragma unroll
    for (int i = 0; i < 4; i++)
#pragma unroll
        for (int j = 0; j < 4; j++) acc[i][j] = 0.f;

    for (int k0 = 0; k0 < K; k0 += 16) {
        float4 a = arow_ok ? *(const float4*)(Ag + k0) : make_float4(0.f, 0.f, 0.f, 0.f);
        float4 b = *(const float4*)(Wg + k0);
        As[lk4 + 0][lrow] = a.x; As[lk4 + 1][lrow] = a.y;
        As[lk4 + 2][lrow] = a.z; As[lk4 + 3][lrow] = a.w;
        Bs[lk4 + 0][lrow] = b.x; Bs[lk4 + 1][lrow] = b.y;
        Bs[lk4 + 2][lrow] = b.z; Bs[lk4 + 3][lrow] = b.w;
        __syncthreads();
#pragma unroll
        for (int kk = 0; kk < 16; kk++) {
            float4 av = *(const float4*)&As[kk][ty * 4];
            float4 bv = *(const float4*)&Bs[kk][tx * 4];
            float aa[4] = {av.x, av.y, av.z, av.w};
            float bb[4] = {bv.x, bv.y, bv.z, bv.w};
#pragma unroll
            for (int i = 0; i < 4; i++)
#pragma unroll
                for (int j = 0; j < 4; j++) acc[i][j] += aa[i] * bb[j];
        }
        __syncthreads();
    }
#pragma unroll
    for (int i = 0; i < 4; i++) {
        int r = bm + ty * 4 + i;
        if (r < Mrows) {
#pragma unroll
            for (int j = 0; j < 4; j++) {
                int c = bn + tx * 4 + j;
                C[(size_t)r * Nout + c] = acc[i][j] + bias[c];
            }
        }
    }
}

// ---------------- hyperedge aggregation: feat_e[e] = (sum_i vrw[src_i]*Wh[src_i]) / ers[e]
__global__ __launch_bounds__(256) void edge_agg_kernel(
    const float* __restrict__ vrw, const float* __restrict__ ers,
    float* __restrict__ feat_e) {
    int e = blockIdx.x;
    int t = threadIdx.x;
    int beg = g_eoff[e], end = g_eoff[e + 1];
    float acc = 0.f;
    for (int i = beg; i < end; i++) {
        int s = g_elist[i];
        acc += vrw[s] * g_Wh[(size_t)s * 256 + t];
    }
    feat_e[(size_t)e * 256 + t] = acc / ers[e];
}

// ---------------- per-vertex attention (one warp per vertex) ----------------
__global__ __launch_bounds__(256) void attn_kernel(float* __restrict__ out_fv) {
    int gw = (blockIdx.x * blockDim.x + threadIdx.x) >> 5;
    int lane = threadIdx.x & 31;
    if (gw >= Nc) return;
    int n = gw;
    int beg = g_voff[n], end = g_voff[n + 1];
    float q0 = g_q[(size_t)n * 64 + lane];
    float q1 = g_q[(size_t)n * 64 + 32 + lane];
    const float scale = 0.125f;  // 1/sqrt(64)

    float mx = -1e30f;
    for (int i = beg; i < end; i++) {
        int e = g_vlist[i];
        float s = q0 * g_k[(size_t)e * 64 + lane] + q1 * g_k[(size_t)e * 64 + 32 + lane];
#pragma unroll
        for (int o = 16; o; o >>= 1) s += __shfl_xor_sync(0xffffffffu, s, o);
        s = (s > 0.f ? s : 0.01f * s) * scale;  // leaky_relu then scale
        g_attn[i] = s;  // every lane writes identical value -> each lane's later read is self-RAW
        mx = fmaxf(mx, s);
    }

    float denom = 0.f;
    float4 a0 = make_float4(0.f, 0.f, 0.f, 0.f);
    float4 a1 = make_float4(0.f, 0.f, 0.f, 0.f);
    for (int i = beg; i < end; i++) {
        int e = g_vlist[i];
        float p = __expf(g_attn[i] - mx);
        denom += p;
        const float4* vp = (const float4*)(g_v + (size_t)e * 256);
        float4 v0 = vp[lane];
        float4 v1 = vp[32 + lane];
        a0.x += p * v0.x; a0.y += p * v0.y; a0.z += p * v0.z; a0.w += p * v0.w;
        a1.x += p * v1.x; a1.y += p * v1.y; a1.z += p * v1.z; a1.w += p * v1.w;
    }
    float inv = 1.f / fmaxf(denom, 1e-20f);
    a0.x *= inv; a0.y *= inv; a0.z *= inv; a0.w *= inv;
    a1.x *= inv; a1.y *= inv; a1.z *= inv; a1.w *= inv;
    float4* op = (float4*)(out_fv + (size_t)n * 256);
    op[lane] = a0;
    op[32 + lane] = a1;
}

// ---------------- classification head: pred = feat_v_out @ Wcls^T + bcls ----------------
__global__ __launch_bounds__(256) void pred_kernel(
    const float* __restrict__ fv, const float* __restrict__ Wc,
    const float* __restrict__ bc, float* __restrict__ pred) {
    __shared__ float sW[10 * 256];
    __shared__ float sb[10];
    int t = threadIdx.x;
    for (int i = t; i < 2560; i += 256) sW[i] = Wc[i];
    if (t < 10) sb[t] = bc[t];
    __syncthreads();
    int warp = t >> 5, lane = t & 31;
    int r = blockIdx.x * 8 + warp;
    if (r >= Nc) return;
    float acc[10];
#pragma unroll
    for (int c = 0; c < 10; c++) acc[c] = 0.f;
    for (int kk = lane; kk < 256; kk += 32) {
        float x = fv[(size_t)r * 256 + kk];
#pragma unroll
        for (int c = 0; c < 10; c++) acc[c] += x * sW[c * 256 + kk];
    }
#pragma unroll
    for (int c = 0; c < 10; c++) {
#pragma unroll
        for (int o = 16; o; o >>= 1) acc[c] += __shfl_xor_sync(0xffffffffu, acc[c], o);
    }
    if (lane == 0) {
#pragma unroll
        for (int c = 0; c < 10; c++) pred[(size_t)r * 10 + c] = acc[c] + sb[c];
    }
}

// ---------------- launch ----------------
extern "C" void kernel_launch(void* const* d_in, const int* in_sizes, int n_in,
                              void* d_out, int out_size) {
    const float* vfeat = (const float*)d_in[0];
    // d_in[1] efeat: unused by reference
    const float* vrw = (const float*)d_in[2];   // v_reg_weight
    // d_in[3] v_reg_sum: unused
    // d_in[4] e_reg_weight: unused
    const float* ers = (const float*)d_in[5];   // e_reg_sum
    const float* W1 = (const float*)d_in[6];
    const float* b1 = (const float*)d_in[7];
    const float* Wve = (const float*)d_in[8];
    const float* bve = (const float*)d_in[9];
    const float* Wqv = (const float*)d_in[10];
    const float* bqv = (const float*)d_in[11];
    const float* Wke = (const float*)d_in[12];
    const float* bke = (const float*)d_in[13];
    const float* Wvale = (const float*)d_in[14];
    const float* bvale = (const float*)d_in[15];
    const float* Wcls = (const float*)d_in[16];
    const float* bcls = (const float*)d_in[17];
    const int* in_src = (const int*)d_in[18];
    const int* in_dst = (const int*)d_in[19];

    float* out = (float*)d_out;
    float* out_fv = out;                                  // [N,256]
    float* out_fe = out + (size_t)Nc * 256;               // [E,256]
    float* out_pred = out_fe + (size_t)Ec * 256;          // [N,10]

    float* p_feat_v; float* p_Wh; float* p_q; float* p_k; float* p_v;
    cudaGetSymbolAddress((void**)&p_feat_v, g_feat_v);
    cudaGetSymbolAddress((void**)&p_Wh, g_Wh);
    cudaGetSymbolAddress((void**)&p_q, g_q);
    cudaGetSymbolAddress((void**)&p_k, g_k);
    cudaGetSymbolAddress((void**)&p_v, g_v);

    // CSR build
    zero_cnts_kernel<<<(Nc + 255) / 256, 256>>>();
    hist_kernel<<<(Mc + 255) / 256, 256>>>(in_src, in_dst);
    scan_kernel<<<1, 1024>>>(0);
    scan_kernel<<<1, 1024>>>(1);
    scatter_kernel<<<(Mc + 255) / 256, 256>>>(in_src, in_dst);

    const int gN = (Nc + 63) / 64;  // 782
    const int gE = (Ec + 63) / 64;  // 391

    // feat_v = vfeat @ W1^T + b1
    gemm_nt_bias<<<dim3(gN, 4), 256>>>(vfeat, W1, b1, p_feat_v, Nc, 256);
    // Wh = feat_v @ Wve^T + bve
    gemm_nt_bias<<<dim3(gN, 4), 256>>>(p_feat_v, Wve, bve, p_Wh, Nc, 256);
    // q = feat_v @ Wqv^T + bqv
    gemm_nt_bias<<<dim3(gN, 1), 256>>>(p_feat_v, Wqv, bqv, p_q, Nc, 64);
    // feat_e (written straight into output slot 2)
    edge_agg_kernel<<<Ec, 256>>>(vrw, ers, out_fe);
    // k = feat_e @ Wke^T + bke ; v = feat_e @ Wvale^T + bvale
    gemm_nt_bias<<<dim3(gE, 1), 256>>>(out_fe, Wke, bke, p_k, Ec, 64);
    gemm_nt_bias<<<dim3(gE, 4), 256>>>(out_fe, Wvale, bvale, p_v, Ec, 256);
    // attention -> feat_v_out (output slot 1)
    attn_kernel<<<(Nc + 7) / 8, 256>>>(out_fv);
    // pred (output slot 3)
    pred_kernel<<<(Nc + 7) / 8, 256>>>(out_fv, Wcls, bcls, out_pred);
}

// round 3
// speedup vs baseline: 1.6239x; 1.6239x over previous
#include <cuda_runtime.h>
#include <cuda_bf16.h>
#include <math.h>
#include <stdint.h>

#define Nc 50000
#define Ec 25000
#define Mc 300000
// dims: INPUT=VERTEX=EDGE=256, QUERY=64, NUM_CLASS=10

// ---------------- scratch (static device globals; no runtime alloc) ----------------
__device__ float g_feat_v[(size_t)Nc * 256];
__device__ float g_Wh[(size_t)Nc * 256];
__device__ float g_q[(size_t)Nc * 64];
__device__ float g_k[(size_t)Ec * 64];
__device__ float g_v[(size_t)Ec * 256];
__device__ float g_attn[Mc];
__device__ int g_eoff[Ec + 1];
__device__ int g_voff[Nc + 1];
__device__ int g_ecnt[Ec];
__device__ int g_vcnt[Nc];
__device__ int g_ecur[Ec];
__device__ int g_vcur[Nc];
__device__ int g_elist[Mc];  // per-hyperedge incidence list: stores src vertex id
__device__ int g_vlist[Mc];  // per-vertex incidence list: stores dst hyperedge id

// ---------------- CSR build ----------------
__global__ void zero_cnts_kernel() {
    int i = blockIdx.x * blockDim.x + threadIdx.x;
    if (i < Ec) { g_ecnt[i] = 0; g_ecur[i] = 0; }
    if (i < Nc) { g_vcnt[i] = 0; g_vcur[i] = 0; }
}

__global__ void hist_kernel(const int* __restrict__ in_src, const int* __restrict__ in_dst) {
    int m = blockIdx.x * blockDim.x + threadIdx.x;
    if (m >= Mc) return;
    atomicAdd(&g_ecnt[in_dst[m]], 1);
    atomicAdd(&g_vcnt[in_src[m]], 1);
}

// chunked single-block scan: each thread owns ceil(L/1024) elements serially
__global__ void scan_kernel(int which) {
    __shared__ int buf[1024];
    const int* cnt = (which == 0) ? g_ecnt : g_vcnt;
    int* off = (which == 0) ? g_eoff : g_voff;
    int L = (which == 0) ? Ec : Nc;
    int t = threadIdx.x;
    int chunk = (L + 1023) >> 10;
    int beg = t * chunk;
    int end = min(beg + chunk, L);
    int s = 0;
    for (int i = beg; i < end; i++) s += cnt[i];
    buf[t] = s;
    __syncthreads();
    for (int d = 1; d < 1024; d <<= 1) {
        int v = (t >= d) ? buf[t - d] : 0;
        __syncthreads();
        buf[t] += v;
        __syncthreads();
    }
    int run = buf[t] - s;  // exclusive prefix of this thread's chunk
    for (int i = beg; i < end; i++) { off[i] = run; run += cnt[i]; }
    if (t == 1023) off[L] = buf[1023];
}

__global__ void scatter_kernel(const int* __restrict__ in_src, const int* __restrict__ in_dst) {
    int m = blockIdx.x * blockDim.x + threadIdx.x;
    if (m >= Mc) return;
    int s = in_src[m];
    int e = in_dst[m];
    int pe = atomicAdd(&g_ecur[e], 1);
    g_elist[g_eoff[e] + pe] = s;
    int pv = atomicAdd(&g_vcur[s], 1);
    g_vlist[g_voff[s] + pv] = e;
}

// ---------------- bf16 split helpers ----------------
__device__ __forceinline__ void pack4(float4 v, uint2& hi, uint2& lo) {
    __nv_bfloat16 h0 = __float2bfloat16(v.x);
    __nv_bfloat16 h1 = __float2bfloat16(v.y);
    __nv_bfloat16 h2 = __float2bfloat16(v.z);
    __nv_bfloat16 h3 = __float2bfloat16(v.w);
    __nv_bfloat16 l0 = __float2bfloat16(v.x - __bfloat162float(h0));
    __nv_bfloat16 l1 = __float2bfloat16(v.y - __bfloat162float(h1));
    __nv_bfloat16 l2 = __float2bfloat16(v.z - __bfloat162float(h2));
    __nv_bfloat16 l3 = __float2bfloat16(v.w - __bfloat162float(h3));
    hi.x = ((uint32_t)__bfloat16_as_ushort(h1) << 16) | __bfloat16_as_ushort(h0);
    hi.y = ((uint32_t)__bfloat16_as_ushort(h3) << 16) | __bfloat16_as_ushort(h2);
    lo.x = ((uint32_t)__bfloat16_as_ushort(l1) << 16) | __bfloat16_as_ushort(l0);
    lo.y = ((uint32_t)__bfloat16_as_ushort(l3) << 16) | __bfloat16_as_ushort(l2);
}

__device__ __forceinline__ void mma16816(float* d, const uint32_t* a, uint32_t b0, uint32_t b1) {
    asm volatile(
        "mma.sync.aligned.m16n8k16.row.col.f32.bf16.bf16.f32 "
        "{%0,%1,%2,%3},{%4,%5,%6,%7},{%8,%9},{%0,%1,%2,%3};"
        : "+f"(d[0]), "+f"(d[1]), "+f"(d[2]), "+f"(d[3])
        : "r"(a[0]), "r"(a[1]), "r"(a[2]), "r"(a[3]), "r"(b0), "r"(b1));
}

// ---------------- bf16x3 tensor-core GEMM: C[M,NOUT] = A[M,256] @ W[NOUT,256]^T + bias ----
// CTA tile 128 x BN, K staged in chunks of 32. 8 warps as 4(M) x 2(N); warp tile 32 x BN/2.
// Error-compensated: D += Ahi*Bhi + Ahi*Blo + Alo*Bhi (drops ~2^-16 Alo*Blo term).
template <int BN, int NOUT>
__global__ __launch_bounds__(256) void gemm_bf16x3(
    const float* __restrict__ A, const float* __restrict__ W,
    const float* __restrict__ bias, float* __restrict__ C, int Mrows) {
    constexpr int WN = BN / 2;
    constexpr int NF = WN / 8;
    constexpr int RBN = BN / 32;  // B float4s per thread per chunk
    constexpr int AH = 0;
    constexpr int AL = 128 * 40;
    constexpr int BH = 2 * 128 * 40;
    constexpr int BL = BH + BN * 40;
    extern __shared__ __nv_bfloat16 sm[];

    int tid = threadIdx.x;
    int lane = tid & 31, wid = tid >> 5;
    int wm = wid & 3, wn = wid >> 2;
    int qr = lane >> 2;          // 0..7
    int qc = (lane & 3) * 2;     // 0,2,4,6
    int bm = blockIdx.x * 128;
    int bn = blockIdx.y * BN;

    float acc[2][NF][4];
#pragma unroll
    for (int mf = 0; mf < 2; mf++)
#pragma unroll
        for (int nf = 0; nf < NF; nf++)
#pragma unroll
            for (int j = 0; j < 4; j++) acc[mf][nf][j] = 0.f;

    float4 ra[4];
    float4 rb[RBN];

    // prefetch chunk 0
    {
        const int c = 0;
#pragma unroll
        for (int i = 0; i < 4; i++) {
            int f = tid + i * 256;
            int row = f >> 3, c4 = f & 7;
            ra[i] = (bm + row < Mrows)
                        ? *(const float4*)(A + (size_t)(bm + row) * 256 + c * 32 + c4 * 4)
                        : make_float4(0.f, 0.f, 0.f, 0.f);
        }
#pragma unroll
        for (int i = 0; i < RBN; i++) {
            int f = tid + i * 256;
            int row = f >> 3, c4 = f & 7;
            rb[i] = *(const float4*)(W + (size_t)(bn + row) * 256 + c * 32 + c4 * 4);
        }
    }

    for (int c = 0; c < 8; c++) {
        __syncthreads();  // previous compute done reading smem
        // store staged chunk (split into hi/lo bf16)
#pragma unroll
        for (int i = 0; i < 4; i++) {
            int f = tid + i * 256;
            int row = f >> 3, c4 = f & 7;
            uint2 hi, lo;
            pack4(ra[i], hi, lo);
            *(uint2*)&sm[AH + row * 40 + c4 * 4] = hi;
            *(uint2*)&sm[AL + row * 40 + c4 * 4] = lo;
        }
#pragma unroll
        for (int i = 0; i < RBN; i++) {
            int f = tid + i * 256;
            int row = f >> 3, c4 = f & 7;
            uint2 hi, lo;
            pack4(rb[i], hi, lo);
            *(uint2*)&sm[BH + row * 40 + c4 * 4] = hi;
            *(uint2*)&sm[BL + row * 40 + c4 * 4] = lo;
        }
        __syncthreads();
        // prefetch next chunk (overlaps with MMAs below)
        if (c < 7) {
#pragma unroll
            for (int i = 0; i < 4; i++) {
                int f = tid + i * 256;
                int row = f >> 3, c4 = f & 7;
                ra[i] = (bm + row < Mrows)
                            ? *(const float4*)(A + (size_t)(bm + row) * 256 + (c + 1) * 32 + c4 * 4)
                            : make_float4(0.f, 0.f, 0.f, 0.f);
            }
#pragma unroll
            for (int i = 0; i < RBN; i++) {
                int f = tid + i * 256;
                int row = f >> 3, c4 = f & 7;
                rb[i] = *(const float4*)(W + (size_t)(bn + row) * 256 + (c + 1) * 32 + c4 * 4);
            }
        }
        // compute: two k16 sub-steps
#pragma unroll
        for (int ks = 0; ks < 32; ks += 16) {
            uint32_t ah[2][4], al[2][4];
#pragma unroll
            for (int mf = 0; mf < 2; mf++) {
                int r0 = wm * 32 + mf * 16 + qr;
                int cc = ks + qc;
                ah[mf][0] = *(const uint32_t*)&sm[AH + r0 * 40 + cc];
                ah[mf][1] = *(const uint32_t*)&sm[AH + (r0 + 8) * 40 + cc];
                ah[mf][2] = *(const uint32_t*)&sm[AH + r0 * 40 + cc + 8];
                ah[mf][3] = *(const uint32_t*)&sm[AH + (r0 + 8) * 40 + cc + 8];
                al[mf][0] = *(const uint32_t*)&sm[AL + r0 * 40 + cc];
                al[mf][1] = *(const uint32_t*)&sm[AL + (r0 + 8) * 40 + cc];
                al[mf][2] = *(const uint32_t*)&sm[AL + r0 * 40 + cc + 8];
                al[mf][3] = *(const uint32_t*)&sm[AL + (r0 + 8) * 40 + cc + 8];
            }
#pragma unroll
            for (int nf = 0; nf < NF; nf++) {
                int rB = wn * WN + nf * 8 + qr;
                int cc = ks + qc;
                uint32_t bh0 = *(const uint32_t*)&sm[BH + rB * 40 + cc];
                uint32_t bh1 = *(const uint32_t*)&sm[BH + rB * 40 + cc + 8];
                uint32_t bl0 = *(const uint32_t*)&sm[BL + rB * 40 + cc];
                uint32_t bl1 = *(const uint32_t*)&sm[BL + rB * 40 + cc + 8];
#pragma unroll
                for (int mf = 0; mf < 2; mf++) {
                    mma16816(acc[mf][nf], ah[mf], bh0, bh1);
                    mma16816(acc[mf][nf], ah[mf], bl0, bl1);
                    mma16816(acc[mf][nf], al[mf], bh0, bh1);
                }
            }
        }
    }

    // epilogue: bias + store (float2 per fragment row-pair)
#pragma unroll
    for (int mf = 0; mf < 2; mf++) {
#pragma unroll
        for (int nf = 0; nf < NF; nf++) {
            int m0 = bm + wm * 32 + mf * 16 + qr;
            int n0 = bn + wn * WN + nf * 8 + qc;
            float bv0 = bias[n0], bv1 = bias[n0 + 1];
            if (m0 < Mrows) {
                float2 o = make_float2(acc[mf][nf][0] + bv0, acc[mf][nf][1] + bv1);
                *(float2*)(C + (size_t)m0 * NOUT + n0) = o;
            }
            if (m0 + 8 < Mrows) {
                float2 o = make_float2(acc[mf][nf][2] + bv0, acc[mf][nf][3] + bv1);
                *(float2*)(C + (size_t)(m0 + 8) * NOUT + n0) = o;
            }
        }
    }
}

// ---------------- hyperedge aggregation: feat_e[e] = (sum_i vrw[src_i]*Wh[src_i]) / ers[e]
__global__ __launch_bounds__(256) void edge_agg_kernel(
    const float* __restrict__ vrw, const float* __restrict__ ers,
    float* __restrict__ feat_e) {
    int e = blockIdx.x;
    int t = threadIdx.x;
    int beg = g_eoff[e], end = g_eoff[e + 1];
    float acc = 0.f;
    for (int i = beg; i < end; i++) {
        int s = g_elist[i];
        acc += vrw[s] * g_Wh[(size_t)s * 256 + t];
    }
    feat_e[(size_t)e * 256 + t] = acc / ers[e];
}

// ---------------- per-vertex attention (one warp per vertex) ----------------
__global__ __launch_bounds__(256) void attn_kernel(float* __restrict__ out_fv) {
    int gw = (blockIdx.x * blockDim.x + threadIdx.x) >> 5;
    int lane = threadIdx.x & 31;
    if (gw >= Nc) return;
    int n = gw;
    int beg = g_voff[n], end = g_voff[n + 1];
    float q0 = g_q[(size_t)n * 64 + lane];
    float q1 = g_q[(size_t)n * 64 + 32 + lane];
    const float scale = 0.125f;  // 1/sqrt(64)

    float mx = -1e30f;
    for (int i = beg; i < end; i++) {
        int e = g_vlist[i];
        float s = q0 * g_k[(size_t)e * 64 + lane] + q1 * g_k[(size_t)e * 64 + 32 + lane];
#pragma unroll
        for (int o = 16; o; o >>= 1) s += __shfl_xor_sync(0xffffffffu, s, o);
        s = (s > 0.f ? s : 0.01f * s) * scale;  // leaky_relu then scale
        g_attn[i] = s;
        mx = fmaxf(mx, s);
    }

    float denom = 0.f;
    float4 a0 = make_float4(0.f, 0.f, 0.f, 0.f);
    float4 a1 = make_float4(0.f, 0.f, 0.f, 0.f);
    for (int i = beg; i < end; i++) {
        int e = g_vlist[i];
        float p = __expf(g_attn[i] - mx);
        denom += p;
        const float4* vp = (const float4*)(g_v + (size_t)e * 256);
        float4 v0 = vp[lane];
        float4 v1 = vp[32 + lane];
        a0.x += p * v0.x; a0.y += p * v0.y; a0.z += p * v0.z; a0.w += p * v0.w;
        a1.x += p * v1.x; a1.y += p * v1.y; a1.z += p * v1.z; a1.w += p * v1.w;
    }
    float inv = 1.f / fmaxf(denom, 1e-20f);
    a0.x *= inv; a0.y *= inv; a0.z *= inv; a0.w *= inv;
    a1.x *= inv; a1.y *= inv; a1.z *= inv; a1.w *= inv;
    float4* op = (float4*)(out_fv + (size_t)n * 256);
    op[lane] = a0;
    op[32 + lane] = a1;
}

// ---------------- classification head: pred = feat_v_out @ Wcls^T + bcls ----------------
__global__ __launch_bounds__(256) void pred_kernel(
    const float* __restrict__ fv, const float* __restrict__ Wc,
    const float* __restrict__ bc, float* __restrict__ pred) {
    __shared__ float sW[10 * 256];
    __shared__ float sb_[10];
    int t = threadIdx.x;
    for (int i = t; i < 2560; i += 256) sW[i] = Wc[i];
    if (t < 10) sb_[t] = bc[t];
    __syncthreads();
    int warp = t >> 5, lane = t & 31;
    int r = blockIdx.x * 8 + warp;
    if (r >= Nc) return;
    float acc[10];
#pragma unroll
    for (int c = 0; c < 10; c++) acc[c] = 0.f;
    for (int kk = lane; kk < 256; kk += 32) {
        float x = fv[(size_t)r * 256 + kk];
#pragma unroll
        for (int c = 0; c < 10; c++) acc[c] += x * sW[c * 256 + kk];
    }
#pragma unroll
    for (int c = 0; c < 10; c++) {
#pragma unroll
        for (int o = 16; o; o >>= 1) acc[c] += __shfl_xor_sync(0xffffffffu, acc[c], o);
    }
    if (lane == 0) {
#pragma unroll
        for (int c = 0; c < 10; c++) pred[(size_t)r * 10 + c] = acc[c] + sb_[c];
    }
}

// ---------------- launch ----------------
extern "C" void kernel_launch(void* const* d_in, const int* in_sizes, int n_in,
                              void* d_out, int out_size) {
    const float* vfeat = (const float*)d_in[0];
    const float* vrw = (const float*)d_in[2];   // v_reg_weight
    const float* ers = (const float*)d_in[5];   // e_reg_sum
    const float* W1 = (const float*)d_in[6];
    const float* b1 = (const float*)d_in[7];
    const float* Wve = (const float*)d_in[8];
    const float* bve = (const float*)d_in[9];
    const float* Wqv = (const float*)d_in[10];
    const float* bqv = (const float*)d_in[11];
    const float* Wke = (const float*)d_in[12];
    const float* bke = (const float*)d_in[13];
    const float* Wvale = (const float*)d_in[14];
    const float* bvale = (const float*)d_in[15];
    const float* Wcls = (const float*)d_in[16];
    const float* bcls = (const float*)d_in[17];
    const int* in_src = (const int*)d_in[18];
    const int* in_dst = (const int*)d_in[19];

    float* out = (float*)d_out;
    float* out_fv = out;                                  // [N,256]
    float* out_fe = out + (size_t)Nc * 256;               // [E,256]
    float* out_pred = out_fe + (size_t)Ec * 256;          // [N,10]

    float* p_feat_v; float* p_Wh; float* p_q; float* p_k; float* p_v;
    cudaGetSymbolAddress((void**)&p_feat_v, g_feat_v);
    cudaGetSymbolAddress((void**)&p_Wh, g_Wh);
    cudaGetSymbolAddress((void**)&p_q, g_q);
    cudaGetSymbolAddress((void**)&p_k, g_k);
    cudaGetSymbolAddress((void**)&p_v, g_v);

    // CSR build
    zero_cnts_kernel<<<(Nc + 255) / 256, 256>>>();
    hist_kernel<<<(Mc + 255) / 256, 256>>>(in_src, in_dst);
    scan_kernel<<<1, 1024>>>(0);
    scan_kernel<<<1, 1024>>>(1);
    scatter_kernel<<<(Mc + 255) / 256, 256>>>(in_src, in_dst);

    const int gN = (Nc + 127) / 128;  // 391
    const int gE = (Ec + 127) / 128;  // 196
    const int SM128 = 20480 * 2 + 128 * 160;  // 61440? no: bytes = 2*(128*40 + 128*40)*2... computed below
    // smem bytes: (2*128*40 + 2*BN*40) halfs * 2B = 20480 + BN*160
    const int SMEM_BN128 = 20480 + 128 * 160;  // 40960
    const int SMEM_BN64 = 20480 + 64 * 160;    // 30720
    (void)SM128;

    // feat_v = vfeat @ W1^T + b1
    gemm_bf16x3<128, 256><<<dim3(gN, 2), 256, SMEM_BN128>>>(vfeat, W1, b1, p_feat_v, Nc);
    // Wh = feat_v @ Wve^T + bve
    gemm_bf16x3<128, 256><<<dim3(gN, 2), 256, SMEM_BN128>>>(p_feat_v, Wve, bve, p_Wh, Nc);
    // q = feat_v @ Wqv^T + bqv
    gemm_bf16x3<64, 64><<<dim3(gN, 1), 256, SMEM_BN64>>>(p_feat_v, Wqv, bqv, p_q, Nc);
    // feat_e (written straight into output slot 2)
    edge_agg_kernel<<<Ec, 256>>>(vrw, ers, out_fe);
    // k = feat_e @ Wke^T + bke ; v = feat_e @ Wvale^T + bvale
    gemm_bf16x3<64, 64><<<dim3(gE, 1), 256, SMEM_BN64>>>(out_fe, Wke, bke, p_k, Ec);
    gemm_bf16x3<128, 256><<<dim3(gE, 2), 256, SMEM_BN128>>>(out_fe, Wvale, bvale, p_v, Ec);
    // attention -> feat_v_out (output slot 1)
    attn_kernel<<<(Nc + 7) / 8, 256>>>(out_fv);
    // pred (output slot 3)
    pred_kernel<<<(Nc + 7) / 8, 256>>>(out_fv, Wcls, bcls, out_pred);
}

// round 4
// speedup vs baseline: 1.8910x; 1.1645x over previous
#include <cuda_runtime.h>
#include <cuda_bf16.h>
#include <math.h>
#include <stdint.h>

#define Nc 50000
#define Ec 25000
#define Mc 300000
// dims: INPUT=VERTEX=EDGE=256, QUERY=64, NUM_CLASS=10

// ---------------- scratch (static device globals; no runtime alloc) ----------------
__device__ float g_feat_v[(size_t)Nc * 256];
__device__ float g_Wh[(size_t)Nc * 256];
__device__ float g_q[(size_t)Nc * 64];
__device__ float g_k[(size_t)Ec * 64];
__device__ float g_v[(size_t)Ec * 256];
__device__ int g_ebeg[Ec];
__device__ int g_vbeg[Nc];
__device__ int g_ecnt[Ec];
__device__ int g_vcnt[Nc];
__device__ int g_ecur[Ec];
__device__ int g_vcur[Nc];
__device__ int g_tote, g_totn;
__device__ int g_elist[Mc];  // per-hyperedge incidence list: stores src vertex id
__device__ int g_vlist[Mc];  // per-vertex incidence list: stores dst hyperedge id

// ---------------- CSR build ----------------
__global__ void zero_cnts_kernel() {
    int i = blockIdx.x * blockDim.x + threadIdx.x;
    if (i < Ec) g_ecnt[i] = 0;
    if (i < Nc) g_vcnt[i] = 0;
    if (i == 0) { g_tote = 0; g_totn = 0; }
}

__global__ void hist_kernel(const int* __restrict__ in_src, const int* __restrict__ in_dst) {
    int m = blockIdx.x * blockDim.x + threadIdx.x;
    if (m >= Mc) return;
    atomicAdd(&g_ecnt[in_dst[m]], 1);
    atomicAdd(&g_vcnt[in_src[m]], 1);
}

// Assign each segment a contiguous range: warp-scan of counts + one atomicAdd per warp.
// Segment base order is arbitrary (atomic), which is fine: consumers only use [beg, beg+cnt).
__global__ void assign_off_kernel() {
    int i = blockIdx.x * blockDim.x + threadIdx.x;
    int lane = threadIdx.x & 31;
    // hyperedge side
    {
        int c = (i < Ec) ? g_ecnt[i] : 0;
        int x = c;
#pragma unroll
        for (int o = 1; o < 32; o <<= 1) {
            int y = __shfl_up_sync(0xffffffffu, x, o);
            if (lane >= o) x += y;
        }
        int wsum = __shfl_sync(0xffffffffu, x, 31);
        int base = 0;
        if (lane == 31 && wsum > 0) base = atomicAdd(&g_tote, wsum);
        base = __shfl_sync(0xffffffffu, base, 31);
        if (i < Ec) {
            int b = base + x - c;
            g_ebeg[i] = b;
            g_ecur[i] = b;
        }
    }
    // vertex side
    {
        int c = (i < Nc) ? g_vcnt[i] : 0;
        int x = c;
#pragma unroll
        for (int o = 1; o < 32; o <<= 1) {
            int y = __shfl_up_sync(0xffffffffu, x, o);
            if (lane >= o) x += y;
        }
        int wsum = __shfl_sync(0xffffffffu, x, 31);
        int base = 0;
        if (lane == 31 && wsum > 0) base = atomicAdd(&g_totn, wsum);
        base = __shfl_sync(0xffffffffu, base, 31);
        if (i < Nc) {
            int b = base + x - c;
            g_vbeg[i] = b;
            g_vcur[i] = b;
        }
    }
}

__global__ void scatter_kernel(const int* __restrict__ in_src, const int* __restrict__ in_dst) {
    int m = blockIdx.x * blockDim.x + threadIdx.x;
    if (m >= Mc) return;
    int s = in_src[m];
    int e = in_dst[m];
    int pe = atomicAdd(&g_ecur[e], 1);
    g_elist[pe] = s;
    int pv = atomicAdd(&g_vcur[s], 1);
    g_vlist[pv] = e;
}

// ---------------- bf16 split helpers ----------------
__device__ __forceinline__ void pack4(float4 v, uint2& hi, uint2& lo) {
    __nv_bfloat16 h0 = __float2bfloat16(v.x);
    __nv_bfloat16 h1 = __float2bfloat16(v.y);
    __nv_bfloat16 h2 = __float2bfloat16(v.z);
    __nv_bfloat16 h3 = __float2bfloat16(v.w);
    __nv_bfloat16 l0 = __float2bfloat16(v.x - __bfloat162float(h0));
    __nv_bfloat16 l1 = __float2bfloat16(v.y - __bfloat162float(h1));
    __nv_bfloat16 l2 = __float2bfloat16(v.z - __bfloat162float(h2));
    __nv_bfloat16 l3 = __float2bfloat16(v.w - __bfloat162float(h3));
    hi.x = ((uint32_t)__bfloat16_as_ushort(h1) << 16) | __bfloat16_as_ushort(h0);
    hi.y = ((uint32_t)__bfloat16_as_ushort(h3) << 16) | __bfloat16_as_ushort(h2);
    lo.x = ((uint32_t)__bfloat16_as_ushort(l1) << 16) | __bfloat16_as_ushort(l0);
    lo.y = ((uint32_t)__bfloat16_as_ushort(l3) << 16) | __bfloat16_as_ushort(l2);
}

__device__ __forceinline__ void mma16816(float* d, const uint32_t* a, uint32_t b0, uint32_t b1) {
    asm volatile(
        "mma.sync.aligned.m16n8k16.row.col.f32.bf16.bf16.f32 "
        "{%0,%1,%2,%3},{%4,%5,%6,%7},{%8,%9},{%0,%1,%2,%3};"
        : "+f"(d[0]), "+f"(d[1]), "+f"(d[2]), "+f"(d[3])
        : "r"(a[0]), "r"(a[1]), "r"(a[2]), "r"(a[3]), "r"(b0), "r"(b1));
}

// ---------------- bf16x3 tensor-core GEMM: C[M,NOUT] = A[M,256] @ W[NOUT,256]^T + bias ----
// CTA tile 128 x BN, K staged in chunks of 32. 8 warps as 4(M) x 2(N); warp tile 32 x BN/2.
// Error-compensated: D += Ahi*Bhi + Ahi*Blo + Alo*Bhi (drops ~2^-16 Alo*Blo term).
template <int BN, int NOUT>
__global__ __launch_bounds__(256) void gemm_bf16x3(
    const float* __restrict__ A, const float* __restrict__ W,
    const float* __restrict__ bias, float* __restrict__ C, int Mrows) {
    constexpr int WN = BN / 2;
    constexpr int NF = WN / 8;
    constexpr int RBN = BN / 32;  // B float4s per thread per chunk
    constexpr int AH = 0;
    constexpr int AL = 128 * 40;
    constexpr int BH = 2 * 128 * 40;
    constexpr int BL = BH + BN * 40;
    extern __shared__ __nv_bfloat16 sm[];

    int tid = threadIdx.x;
    int lane = tid & 31, wid = tid >> 5;
    int wm = wid & 3, wn = wid >> 2;
    int qr = lane >> 2;          // 0..7
    int qc = (lane & 3) * 2;     // 0,2,4,6
    int bm = blockIdx.x * 128;
    int bn = blockIdx.y * BN;

    float acc[2][NF][4];
#pragma unroll
    for (int mf = 0; mf < 2; mf++)
#pragma unroll
        for (int nf = 0; nf < NF; nf++)
#pragma unroll
            for (int j = 0; j < 4; j++) acc[mf][nf][j] = 0.f;

    float4 ra[4];
    float4 rb[RBN];

    // prefetch chunk 0
    {
        const int c = 0;
#pragma unroll
        for (int i = 0; i < 4; i++) {
            int f = tid + i * 256;
            int row = f >> 3, c4 = f & 7;
            ra[i] = (bm + row < Mrows)
                        ? *(const float4*)(A + (size_t)(bm + row) * 256 + c * 32 + c4 * 4)
                        : make_float4(0.f, 0.f, 0.f, 0.f);
        }
#pragma unroll
        for (int i = 0; i < RBN; i++) {
            int f = tid + i * 256;
            int row = f >> 3, c4 = f & 7;
            rb[i] = *(const float4*)(W + (size_t)(bn + row) * 256 + c * 32 + c4 * 4);
        }
    }

    for (int c = 0; c < 8; c++) {
        __syncthreads();  // previous compute done reading smem
        // store staged chunk (split into hi/lo bf16)
#pragma unroll
        for (int i = 0; i < 4; i++) {
            int f = tid + i * 256;
            int row = f >> 3, c4 = f & 7;
            uint2 hi, lo;
            pack4(ra[i], hi, lo);
            *(uint2*)&sm[AH + row * 40 + c4 * 4] = hi;
            *(uint2*)&sm[AL + row * 40 + c4 * 4] = lo;
        }
#pragma unroll
        for (int i = 0; i < RBN; i++) {
            int f = tid + i * 256;
            int row = f >> 3, c4 = f & 7;
            uint2 hi, lo;
            pack4(rb[i], hi, lo);
            *(uint2*)&sm[BH + row * 40 + c4 * 4] = hi;
            *(uint2*)&sm[BL + row * 40 + c4 * 4] = lo;
        }
        __syncthreads();
        // prefetch next chunk (overlaps with MMAs below)
        if (c < 7) {
#pragma unroll
            for (int i = 0; i < 4; i++) {
                int f = tid + i * 256;
                int row = f >> 3, c4 = f & 7;
                ra[i] = (bm + row < Mrows)
                            ? *(const float4*)(A + (size_t)(bm + row) * 256 + (c + 1) * 32 + c4 * 4)
                            : make_float4(0.f, 0.f, 0.f, 0.f);
            }
#pragma unroll
            for (int i = 0; i < RBN; i++) {
                int f = tid + i * 256;
                int row = f >> 3, c4 = f & 7;
                rb[i] = *(const float4*)(W + (size_t)(bn + row) * 256 + (c + 1) * 32 + c4 * 4);
            }
        }
        // compute: two k16 sub-steps
#pragma unroll
        for (int ks = 0; ks < 32; ks += 16) {
            uint32_t ah[2][4], al[2][4];
#pragma unroll
            for (int mf = 0; mf < 2; mf++) {
                int r0 = wm * 32 + mf * 16 + qr;
                int cc = ks + qc;
                ah[mf][0] = *(const uint32_t*)&sm[AH + r0 * 40 + cc];
                ah[mf][1] = *(const uint32_t*)&sm[AH + (r0 + 8) * 40 + cc];
                ah[mf][2] = *(const uint32_t*)&sm[AH + r0 * 40 + cc + 8];
                ah[mf][3] = *(const uint32_t*)&sm[AH + (r0 + 8) * 40 + cc + 8];
                al[mf][0] = *(const uint32_t*)&sm[AL + r0 * 40 + cc];
                al[mf][1] = *(const uint32_t*)&sm[AL + (r0 + 8) * 40 + cc];
                al[mf][2] = *(const uint32_t*)&sm[AL + r0 * 40 + cc + 8];
                al[mf][3] = *(const uint32_t*)&sm[AL + (r0 + 8) * 40 + cc + 8];
            }
#pragma unroll
            for (int nf = 0; nf < NF; nf++) {
                int rB = wn * WN + nf * 8 + qr;
                int cc = ks + qc;
                uint32_t bh0 = *(const uint32_t*)&sm[BH + rB * 40 + cc];
                uint32_t bh1 = *(const uint32_t*)&sm[BH + rB * 40 + cc + 8];
                uint32_t bl0 = *(const uint32_t*)&sm[BL + rB * 40 + cc];
                uint32_t bl1 = *(const uint32_t*)&sm[BL + rB * 40 + cc + 8];
#pragma unroll
                for (int mf = 0; mf < 2; mf++) {
                    mma16816(acc[mf][nf], ah[mf], bh0, bh1);
                    mma16816(acc[mf][nf], ah[mf], bl0, bl1);
                    mma16816(acc[mf][nf], al[mf], bh0, bh1);
                }
            }
        }
    }

    // epilogue: bias + store (float2 per fragment row-pair)
#pragma unroll
    for (int mf = 0; mf < 2; mf++) {
#pragma unroll
        for (int nf = 0; nf < NF; nf++) {
            int m0 = bm + wm * 32 + mf * 16 + qr;
            int n0 = bn + wn * WN + nf * 8 + qc;
            float bv0 = bias[n0], bv1 = bias[n0 + 1];
            if (m0 < Mrows) {
                float2 o = make_float2(acc[mf][nf][0] + bv0, acc[mf][nf][1] + bv1);
                *(float2*)(C + (size_t)m0 * NOUT + n0) = o;
            }
            if (m0 + 8 < Mrows) {
                float2 o = make_float2(acc[mf][nf][2] + bv0, acc[mf][nf][3] + bv1);
                *(float2*)(C + (size_t)(m0 + 8) * NOUT + n0) = o;
            }
        }
    }
}

// ---------------- hyperedge aggregation: feat_e[e] = (sum_i vrw[src_i]*Wh[src_i]) / ers[e]
__global__ __launch_bounds__(256) void edge_agg_kernel(
    const float* __restrict__ vrw, const float* __restrict__ ers,
    float* __restrict__ feat_e) {
    int e = blockIdx.x;
    int t = threadIdx.x;
    int beg = g_ebeg[e], end = beg + g_ecnt[e];
    float acc = 0.f;
    for (int i = beg; i < end; i++) {
        int s = g_elist[i];
        acc += vrw[s] * g_Wh[(size_t)s * 256 + t];
    }
    feat_e[(size_t)e * 256 + t] = acc / ers[e];
}

// ---------------- per-vertex attention: single-pass online softmax (one warp/vertex) ----
__global__ __launch_bounds__(256) void attn_kernel(float* __restrict__ out_fv) {
    int gw = (blockIdx.x * blockDim.x + threadIdx.x) >> 5;
    int lane = threadIdx.x & 31;
    if (gw >= Nc) return;
    int n = gw;
    int beg = g_vbeg[n], end = beg + g_vcnt[n];
    float q0 = g_q[(size_t)n * 64 + lane];
    float q1 = g_q[(size_t)n * 64 + 32 + lane];
    const float scale = 0.125f;  // 1/sqrt(64)

    float m = -1e30f;
    float denom = 0.f;
    float4 a0 = make_float4(0.f, 0.f, 0.f, 0.f);
    float4 a1 = make_float4(0.f, 0.f, 0.f, 0.f);
    for (int i = beg; i < end; i++) {
        int e = g_vlist[i];
        float s = q0 * g_k[(size_t)e * 64 + lane] + q1 * g_k[(size_t)e * 64 + 32 + lane];
#pragma unroll
        for (int o = 16; o; o >>= 1) s += __shfl_xor_sync(0xffffffffu, s, o);
        s = (s > 0.f ? s : 0.01f * s) * scale;  // leaky_relu then scale
        float mnew = fmaxf(m, s);
        float corr = __expf(m - mnew);  // exp(-inf)=0 handles first iteration
        float p = __expf(s - mnew);
        m = mnew;
        denom = denom * corr + p;
        const float4* vp = (const float4*)(g_v + (size_t)e * 256);
        float4 v0 = vp[lane];
        float4 v1 = vp[32 + lane];
        a0.x = a0.x * corr + p * v0.x; a0.y = a0.y * corr + p * v0.y;
        a0.z = a0.z * corr + p * v0.z; a0.w = a0.w * corr + p * v0.w;
        a1.x = a1.x * corr + p * v1.x; a1.y = a1.y * corr + p * v1.y;
        a1.z = a1.z * corr + p * v1.z; a1.w = a1.w * corr + p * v1.w;
    }
    float inv = 1.f / fmaxf(denom, 1e-20f);
    a0.x *= inv; a0.y *= inv; a0.z *= inv; a0.w *= inv;
    a1.x *= inv; a1.y *= inv; a1.z *= inv; a1.w *= inv;
    float4* op = (float4*)(out_fv + (size_t)n * 256);
    op[lane] = a0;
    op[32 + lane] = a1;
}

// ---------------- classification head: pred = feat_v_out @ Wcls^T + bcls ----------------
__global__ __launch_bounds__(256) void pred_kernel(
    const float* __restrict__ fv, const float* __restrict__ Wc,
    const float* __restrict__ bc, float* __restrict__ pred) {
    __shared__ float sW[10 * 256];
    __shared__ float sb_[10];
    int t = threadIdx.x;
    for (int i = t; i < 2560; i += 256) sW[i] = Wc[i];
    if (t < 10) sb_[t] = bc[t];
    __syncthreads();
    int warp = t >> 5, lane = t & 31;
    int r = blockIdx.x * 8 + warp;
    if (r >= Nc) return;
    float acc[10];
#pragma unroll
    for (int c = 0; c < 10; c++) acc[c] = 0.f;
    for (int kk = lane; kk < 256; kk += 32) {
        float x = fv[(size_t)r * 256 + kk];
#pragma unroll
        for (int c = 0; c < 10; c++) acc[c] += x * sW[c * 256 + kk];
    }
#pragma unroll
    for (int c = 0; c < 10; c++) {
#pragma unroll
        for (int o = 16; o; o >>= 1) acc[c] += __shfl_xor_sync(0xffffffffu, acc[c], o);
    }
    if (lane == 0) {
#pragma unroll
        for (int c = 0; c < 10; c++) pred[(size_t)r * 10 + c] = acc[c] + sb_[c];
    }
}

// ---------------- launch ----------------
extern "C" void kernel_launch(void* const* d_in, const int* in_sizes, int n_in,
                              void* d_out, int out_size) {
    const float* vfeat = (const float*)d_in[0];
    const float* vrw = (const float*)d_in[2];   // v_reg_weight
    const float* ers = (const float*)d_in[5];   // e_reg_sum
    const float* W1 = (const float*)d_in[6];
    const float* b1 = (const float*)d_in[7];
    const float* Wve = (const float*)d_in[8];
    const float* bve = (const float*)d_in[9];
    const float* Wqv = (const float*)d_in[10];
    const float* bqv = (const float*)d_in[11];
    const float* Wke = (const float*)d_in[12];
    const float* bke = (const float*)d_in[13];
    const float* Wvale = (const float*)d_in[14];
    const float* bvale = (const float*)d_in[15];
    const float* Wcls = (const float*)d_in[16];
    const float* bcls = (const float*)d_in[17];
    const int* in_src = (const int*)d_in[18];
    const int* in_dst = (const int*)d_in[19];

    float* out = (float*)d_out;
    float* out_fv = out;                                  // [N,256]
    float* out_fe = out + (size_t)Nc * 256;               // [E,256]
    float* out_pred = out_fe + (size_t)Ec * 256;          // [N,10]

    float* p_feat_v; float* p_Wh; float* p_q; float* p_k; float* p_v;
    cudaGetSymbolAddress((void**)&p_feat_v, g_feat_v);
    cudaGetSymbolAddress((void**)&p_Wh, g_Wh);
    cudaGetSymbolAddress((void**)&p_q, g_q);
    cudaGetSymbolAddress((void**)&p_k, g_k);
    cudaGetSymbolAddress((void**)&p_v, g_v);

    // CSR build (no prefix scan: warp-aggregated atomic range assignment)
    zero_cnts_kernel<<<(Nc + 255) / 256, 256>>>();
    hist_kernel<<<(Mc + 255) / 256, 256>>>(in_src, in_dst);
    assign_off_kernel<<<(Nc + 255) / 256, 256>>>();
    scatter_kernel<<<(Mc + 255) / 256, 256>>>(in_src, in_dst);

    const int gN = (Nc + 127) / 128;  // 391
    const int gE = (Ec + 127) / 128;  // 196
    // smem bytes: (2*128*40 + 2*BN*40) halfs * 2B = 20480 + BN*160
    const int SMEM_BN128 = 20480 + 128 * 160;  // 40960
    const int SMEM_BN64 = 20480 + 64 * 160;    // 30720

    // feat_v = vfeat @ W1^T + b1
    gemm_bf16x3<128, 256><<<dim3(gN, 2), 256, SMEM_BN128>>>(vfeat, W1, b1, p_feat_v, Nc);
    // Wh = feat_v @ Wve^T + bve
    gemm_bf16x3<128, 256><<<dim3(gN, 2), 256, SMEM_BN128>>>(p_feat_v, Wve, bve, p_Wh, Nc);
    // q = feat_v @ Wqv^T + bqv
    gemm_bf16x3<64, 64><<<dim3(gN, 1), 256, SMEM_BN64>>>(p_feat_v, Wqv, bqv, p_q, Nc);
    // feat_e (written straight into output slot 2)
    edge_agg_kernel<<<Ec, 256>>>(vrw, ers, out_fe);
    // k = feat_e @ Wke^T + bke ; v = feat_e @ Wvale^T + bvale
    gemm_bf16x3<64, 64><<<dim3(gE, 1), 256, SMEM_BN64>>>(out_fe, Wke, bke, p_k, Ec);
    gemm_bf16x3<128, 256><<<dim3(gE, 2), 256, SMEM_BN128>>>(out_fe, Wvale, bvale, p_v, Ec);
    // attention -> feat_v_out (output slot 1)
    attn_kernel<<<(Nc + 7) / 8, 256>>>(out_fv);
    // pred (output slot 3)
    pred_kernel<<<(Nc + 7) / 8, 256>>>(out_fv, Wcls, bcls, out_pred);
}

// round 5
// speedup vs baseline: 2.1017x; 1.1114x over previous
#include <cuda_runtime.h>
#include <cuda_bf16.h>
#include <math.h>
#include <stdint.h>

#define Nc 50000
#define Ec 25000
#define Mc 300000
// dims: INPUT=VERTEX=EDGE=256, QUERY=64, NUM_CLASS=10

// ---------------- scratch (static device globals; no runtime alloc) ----------------
__device__ float g_feat_v[(size_t)Nc * 256];
__device__ float g_nfused[(size_t)Nc * 320];  // cols 0-255: Wh, cols 256-319: q
__device__ float g_efused[(size_t)Ec * 320];  // cols 0-63: k, cols 64-319: v
__device__ int g_ebeg[Ec];
__device__ int g_vbeg[Nc];
__device__ int g_ecnt[Ec];
__device__ int g_vcnt[Nc];
__device__ int g_ecur[Ec];
__device__ int g_vcur[Nc];
__device__ int g_tote, g_totn;
__device__ int g_elist[Mc];  // per-hyperedge incidence list: stores src vertex id
__device__ int g_vlist[Mc];  // per-vertex incidence list: stores dst hyperedge id

// ---------------- CSR build ----------------
__global__ void zero_cnts_kernel() {
    int i = blockIdx.x * blockDim.x + threadIdx.x;
    if (i < Ec) g_ecnt[i] = 0;
    if (i < Nc) g_vcnt[i] = 0;
    if (i == 0) { g_tote = 0; g_totn = 0; }
}

__global__ void hist_kernel(const int* __restrict__ in_src, const int* __restrict__ in_dst) {
    int m = blockIdx.x * blockDim.x + threadIdx.x;
    if (m >= Mc) return;
    atomicAdd(&g_ecnt[in_dst[m]], 1);
    atomicAdd(&g_vcnt[in_src[m]], 1);
}

// Assign each segment a contiguous range: warp-scan of counts + one atomicAdd per warp.
__global__ void assign_off_kernel() {
    int i = blockIdx.x * blockDim.x + threadIdx.x;
    int lane = threadIdx.x & 31;
    {
        int c = (i < Ec) ? g_ecnt[i] : 0;
        int x = c;
#pragma unroll
        for (int o = 1; o < 32; o <<= 1) {
            int y = __shfl_up_sync(0xffffffffu, x, o);
            if (lane >= o) x += y;
        }
        int wsum = __shfl_sync(0xffffffffu, x, 31);
        int base = 0;
        if (lane == 31 && wsum > 0) base = atomicAdd(&g_tote, wsum);
        base = __shfl_sync(0xffffffffu, base, 31);
        if (i < Ec) {
            int b = base + x - c;
            g_ebeg[i] = b;
            g_ecur[i] = b;
        }
    }
    {
        int c = (i < Nc) ? g_vcnt[i] : 0;
        int x = c;
#pragma unroll
        for (int o = 1; o < 32; o <<= 1) {
            int y = __shfl_up_sync(0xffffffffu, x, o);
            if (lane >= o) x += y;
        }
        int wsum = __shfl_sync(0xffffffffu, x, 31);
        int base = 0;
        if (lane == 31 && wsum > 0) base = atomicAdd(&g_totn, wsum);
        base = __shfl_sync(0xffffffffu, base, 31);
        if (i < Nc) {
            int b = base + x - c;
            g_vbeg[i] = b;
            g_vcur[i] = b;
        }
    }
}

__global__ void scatter_kernel(const int* __restrict__ in_src, const int* __restrict__ in_dst) {
    int m = blockIdx.x * blockDim.x + threadIdx.x;
    if (m >= Mc) return;
    int s = in_src[m];
    int e = in_dst[m];
    int pe = atomicAdd(&g_ecur[e], 1);
    g_elist[pe] = s;
    int pv = atomicAdd(&g_vcur[s], 1);
    g_vlist[pv] = e;
}

// ---------------- bf16 split + MMA helpers ----------------
__device__ __forceinline__ void pack4(float4 v, uint2& hi, uint2& lo) {
    __nv_bfloat16 h0 = __float2bfloat16(v.x);
    __nv_bfloat16 h1 = __float2bfloat16(v.y);
    __nv_bfloat16 h2 = __float2bfloat16(v.z);
    __nv_bfloat16 h3 = __float2bfloat16(v.w);
    __nv_bfloat16 l0 = __float2bfloat16(v.x - __bfloat162float(h0));
    __nv_bfloat16 l1 = __float2bfloat16(v.y - __bfloat162float(h1));
    __nv_bfloat16 l2 = __float2bfloat16(v.z - __bfloat162float(h2));
    __nv_bfloat16 l3 = __float2bfloat16(v.w - __bfloat162float(h3));
    hi.x = ((uint32_t)__bfloat16_as_ushort(h1) << 16) | __bfloat16_as_ushort(h0);
    hi.y = ((uint32_t)__bfloat16_as_ushort(h3) << 16) | __bfloat16_as_ushort(h2);
    lo.x = ((uint32_t)__bfloat16_as_ushort(l1) << 16) | __bfloat16_as_ushort(l0);
    lo.y = ((uint32_t)__bfloat16_as_ushort(l3) << 16) | __bfloat16_as_ushort(l2);
}

__device__ __forceinline__ void mma16816(float* d, const uint32_t* a, uint32_t b0, uint32_t b1) {
    asm volatile(
        "mma.sync.aligned.m16n8k16.row.col.f32.bf16.bf16.f32 "
        "{%0,%1,%2,%3},{%4,%5,%6,%7},{%8,%9},{%0,%1,%2,%3};"
        : "+f"(d[0]), "+f"(d[1]), "+f"(d[2]), "+f"(d[3])
        : "r"(a[0]), "r"(a[1]), "r"(a[2]), "r"(a[3]), "r"(b0), "r"(b1));
}

__device__ __forceinline__ void ldsm_x4(uint32_t* r, uint32_t addr) {
    asm volatile("ldmatrix.sync.aligned.m8n8.x4.shared.b16 {%0,%1,%2,%3}, [%4];"
                 : "=r"(r[0]), "=r"(r[1]), "=r"(r[2]), "=r"(r[3]) : "r"(addr));
}

__device__ __forceinline__ uint32_t smem_u32(const void* p) {
    uint32_t a;
    asm("{ .reg .u64 t; cvta.to.shared.u64 t, %1; cvt.u32.u64 %0, t; }" : "=r"(a) : "l"(p));
    return a;
}

// ---------------- bf16x3 tensor-core GEMM with column-fused weights ----------------
// C[M, NOUT] = A[M,256] @ [W1;W2]^T + [b1;b2], SPLIT = rows of W1.
// CTA tile 128 x BN; 8 warps 4(M) x 2(N). K chunks of 32, ldmatrix fragment loads.
template <int BN, int NOUT, int SPLIT>
__global__ __launch_bounds__(256) void gemm_bf16x3(
    const float* __restrict__ A,
    const float* __restrict__ W1, const float* __restrict__ b1,
    const float* __restrict__ W2, const float* __restrict__ b2,
    float* __restrict__ C, int Mrows) {
    constexpr int WN = BN / 2;
    constexpr int NF = WN / 8;
    constexpr int RBN = BN / 32;  // B float4s per thread per chunk
    constexpr int AH = 0;
    constexpr int AL = 128 * 40;
    constexpr int BH = 2 * 128 * 40;
    constexpr int BL = BH + BN * 40;
    extern __shared__ __nv_bfloat16 sm[];
    const uint32_t smb = smem_u32(sm);

    int tid = threadIdx.x;
    int lane = tid & 31, wid = tid >> 5;
    int wm = wid & 3, wn = wid >> 2;
    int qr = lane >> 2;       // 0..7
    int qc = (lane & 3) * 2;  // 0,2,4,6
    int bm = blockIdx.x * 128;
    int bn = blockIdx.y * BN;

    // ldmatrix per-lane offsets (halfs)
    int a_row = wm * 32 + (lane & 7) + ((lane >> 3) & 1) * 8;
    int a_col = ((lane >> 4) & 1) * 8;
    int b_col = ((lane >> 3) & 1) * 8;
    int b_rowl = (lane & 7) + ((lane >> 4) & 1) * 8;

    float acc[2][NF][4];
#pragma unroll
    for (int mf = 0; mf < 2; mf++)
#pragma unroll
        for (int nf = 0; nf < NF; nf++)
#pragma unroll
            for (int j = 0; j < 4; j++) acc[mf][nf][j] = 0.f;

    float4 ra[4];
    float4 rb[RBN];

    // prefetch chunk 0
#pragma unroll
    for (int i = 0; i < 4; i++) {
        int f = tid + i * 256;
        int row = f >> 3, c4 = f & 7;
        ra[i] = (bm + row < Mrows)
                    ? *(const float4*)(A + (size_t)(bm + row) * 256 + c4 * 4)
                    : make_float4(0.f, 0.f, 0.f, 0.f);
    }
#pragma unroll
    for (int i = 0; i < RBN; i++) {
        int f = tid + i * 256;
        int row = f >> 3, c4 = f & 7;
        int gn = bn + row;
        const float* wr = (gn < SPLIT) ? (W1 + (size_t)gn * 256) : (W2 + (size_t)(gn - SPLIT) * 256);
        rb[i] = *(const float4*)(wr + c4 * 4);
    }

    for (int c = 0; c < 8; c++) {
        __syncthreads();
#pragma unroll
        for (int i = 0; i < 4; i++) {
            int f = tid + i * 256;
            int row = f >> 3, c4 = f & 7;
            uint2 hi, lo;
            pack4(ra[i], hi, lo);
            *(uint2*)&sm[AH + row * 40 + c4 * 4] = hi;
            *(uint2*)&sm[AL + row * 40 + c4 * 4] = lo;
        }
#pragma unroll
        for (int i = 0; i < RBN; i++) {
            int f = tid + i * 256;
            int row = f >> 3, c4 = f & 7;
            uint2 hi, lo;
            pack4(rb[i], hi, lo);
            *(uint2*)&sm[BH + row * 40 + c4 * 4] = hi;
            *(uint2*)&sm[BL + row * 40 + c4 * 4] = lo;
        }
        __syncthreads();
        // prefetch next chunk (overlaps MMAs)
        if (c < 7) {
#pragma unroll
            for (int i = 0; i < 4; i++) {
                int f = tid + i * 256;
                int row = f >> 3, c4 = f & 7;
                ra[i] = (bm + row < Mrows)
                            ? *(const float4*)(A + (size_t)(bm + row) * 256 + (c + 1) * 32 + c4 * 4)
                            : make_float4(0.f, 0.f, 0.f, 0.f);
            }
#pragma unroll
            for (int i = 0; i < RBN; i++) {
                int f = tid + i * 256;
                int row = f >> 3, c4 = f & 7;
                int gn = bn + row;
                const float* wr = (gn < SPLIT) ? (W1 + (size_t)gn * 256)
                                               : (W2 + (size_t)(gn - SPLIT) * 256);
                rb[i] = *(const float4*)(wr + (c + 1) * 32 + c4 * 4);
            }
        }
#pragma unroll
        for (int ks = 0; ks < 32; ks += 16) {
            uint32_t ah[2][4], al[2][4];
#pragma unroll
            for (int mf = 0; mf < 2; mf++) {
                uint32_t off = ((a_row + mf * 16) * 40 + a_col + ks) * 2;
                ldsm_x4(ah[mf], smb + AH * 2 + off);
                ldsm_x4(al[mf], smb + AL * 2 + off);
            }
            uint32_t bh[NF][2], bl[NF][2];
#pragma unroll
            for (int np = 0; np < NF / 2; np++) {
                uint32_t off = ((wn * WN + np * 16 + b_rowl) * 40 + b_col + ks) * 2;
                uint32_t t[4];
                ldsm_x4(t, smb + BH * 2 + off);
                bh[2 * np][0] = t[0]; bh[2 * np][1] = t[1];
                bh[2 * np + 1][0] = t[2]; bh[2 * np + 1][1] = t[3];
                ldsm_x4(t, smb + BL * 2 + off);
                bl[2 * np][0] = t[0]; bl[2 * np][1] = t[1];
                bl[2 * np + 1][0] = t[2]; bl[2 * np + 1][1] = t[3];
            }
#pragma unroll
            for (int nf = 0; nf < NF; nf++) {
#pragma unroll
                for (int mf = 0; mf < 2; mf++) {
                    mma16816(acc[mf][nf], ah[mf], bh[nf][0], bh[nf][1]);
                    mma16816(acc[mf][nf], ah[mf], bl[nf][0], bl[nf][1]);
                    mma16816(acc[mf][nf], al[mf], bh[nf][0], bh[nf][1]);
                }
            }
        }
    }

    // epilogue: bias + store
#pragma unroll
    for (int mf = 0; mf < 2; mf++) {
#pragma unroll
        for (int nf = 0; nf < NF; nf++) {
            int m0 = bm + wm * 32 + mf * 16 + qr;
            int n0 = bn + wn * WN + nf * 8 + qc;
            float bv0 = (n0 < SPLIT) ? b1[n0] : b2[n0 - SPLIT];
            float bv1 = (n0 + 1 < SPLIT) ? b1[n0 + 1] : b2[n0 + 1 - SPLIT];
            if (m0 < Mrows) {
                float2 o = make_float2(acc[mf][nf][0] + bv0, acc[mf][nf][1] + bv1);
                *(float2*)(C + (size_t)m0 * NOUT + n0) = o;
            }
            if (m0 + 8 < Mrows) {
                float2 o = make_float2(acc[mf][nf][2] + bv0, acc[mf][nf][3] + bv1);
                *(float2*)(C + (size_t)(m0 + 8) * NOUT + n0) = o;
            }
        }
    }
}

// ---------------- hyperedge aggregation: feat_e[e] = (sum_i vrw[src_i]*Wh[src_i]) / ers[e]
// Wh lives in g_nfused cols 0-255 (stride 320)
__global__ __launch_bounds__(256) void edge_agg_kernel(
    const float* __restrict__ vrw, const float* __restrict__ ers,
    float* __restrict__ feat_e) {
    int e = blockIdx.x;
    int t = threadIdx.x;
    int beg = g_ebeg[e], end = beg + g_ecnt[e];
    float acc = 0.f;
    for (int i = beg; i < end; i++) {
        int s = g_elist[i];
        acc += vrw[s] * g_nfused[(size_t)s * 320 + t];
    }
    feat_e[(size_t)e * 256 + t] = acc / ers[e];
}

// ---------------- per-vertex attention: single-pass online softmax (one warp/vertex) ----
// q in g_nfused cols 256-319; k in g_efused cols 0-63; v in g_efused cols 64-319.
__global__ __launch_bounds__(256) void attn_kernel(float* __restrict__ out_fv) {
    int gw = (blockIdx.x * blockDim.x + threadIdx.x) >> 5;
    int lane = threadIdx.x & 31;
    if (gw >= Nc) return;
    int n = gw;
    int beg = g_vbeg[n], end = beg + g_vcnt[n];
    float q0 = g_nfused[(size_t)n * 320 + 256 + lane];
    float q1 = g_nfused[(size_t)n * 320 + 288 + lane];
    const float scale = 0.125f;  // 1/sqrt(64)

    float m = -1e30f;
    float denom = 0.f;
    float4 a0 = make_float4(0.f, 0.f, 0.f, 0.f);
    float4 a1 = make_float4(0.f, 0.f, 0.f, 0.f);
    for (int i = beg; i < end; i++) {
        int e = g_vlist[i];
        const float* kv = g_efused + (size_t)e * 320;
        float s = q0 * kv[lane] + q1 * kv[32 + lane];
#pragma unroll
        for (int o = 16; o; o >>= 1) s += __shfl_xor_sync(0xffffffffu, s, o);
        s = (s > 0.f ? s : 0.01f * s) * scale;  // leaky_relu then scale
        float mnew = fmaxf(m, s);
        float corr = __expf(m - mnew);
        float p = __expf(s - mnew);
        m = mnew;
        denom = denom * corr + p;
        const float4* vp = (const float4*)(kv + 64);
        float4 v0 = vp[lane];
        float4 v1 = vp[32 + lane];
        a0.x = a0.x * corr + p * v0.x; a0.y = a0.y * corr + p * v0.y;
        a0.z = a0.z * corr + p * v0.z; a0.w = a0.w * corr + p * v0.w;
        a1.x = a1.x * corr + p * v1.x; a1.y = a1.y * corr + p * v1.y;
        a1.z = a1.z * corr + p * v1.z; a1.w = a1.w * corr + p * v1.w;
    }
    float inv = 1.f / fmaxf(denom, 1e-20f);
    a0.x *= inv; a0.y *= inv; a0.z *= inv; a0.w *= inv;
    a1.x *= inv; a1.y *= inv; a1.z *= inv; a1.w *= inv;
    float4* op = (float4*)(out_fv + (size_t)n * 256);
    op[lane] = a0;
    op[32 + lane] = a1;
}

// ---------------- classification head: pred = feat_v_out @ Wcls^T + bcls ----------------
__global__ __launch_bounds__(256) void pred_kernel(
    const float* __restrict__ fv, const float* __restrict__ Wc,
    const float* __restrict__ bc, float* __restrict__ pred) {
    __shared__ float sW[10 * 256];
    __shared__ float sb_[10];
    int t = threadIdx.x;
    for (int i = t; i < 2560; i += 256) sW[i] = Wc[i];
    if (t < 10) sb_[t] = bc[t];
    __syncthreads();
    int warp = t >> 5, lane = t & 31;
    int r = blockIdx.x * 8 + warp;
    if (r >= Nc) return;
    float acc[10];
#pragma unroll
    for (int c = 0; c < 10; c++) acc[c] = 0.f;
    for (int kk = lane; kk < 256; kk += 32) {
        float x = fv[(size_t)r * 256 + kk];
#pragma unroll
        for (int c = 0; c < 10; c++) acc[c] += x * sW[c * 256 + kk];
    }
#pragma unroll
    for (int c = 0; c < 10; c++) {
#pragma unroll
        for (int o = 16; o; o >>= 1) acc[c] += __shfl_xor_sync(0xffffffffu, acc[c], o);
    }
    if (lane == 0) {
#pragma unroll
        for (int c = 0; c < 10; c++) pred[(size_t)r * 10 + c] = acc[c] + sb_[c];
    }
}

// ---------------- launch ----------------
extern "C" void kernel_launch(void* const* d_in, const int* in_sizes, int n_in,
                              void* d_out, int out_size) {
    const float* vfeat = (const float*)d_in[0];
    const float* vrw = (const float*)d_in[2];   // v_reg_weight
    const float* ers = (const float*)d_in[5];   // e_reg_sum
    const float* W1 = (const float*)d_in[6];
    const float* b1 = (const float*)d_in[7];
    const float* Wve = (const float*)d_in[8];
    const float* bve = (const float*)d_in[9];
    const float* Wqv = (const float*)d_in[10];
    const float* bqv = (const float*)d_in[11];
    const float* Wke = (const float*)d_in[12];
    const float* bke = (const float*)d_in[13];
    const float* Wvale = (const float*)d_in[14];
    const float* bvale = (const float*)d_in[15];
    const float* Wcls = (const float*)d_in[16];
    const float* bcls = (const float*)d_in[17];
    const int* in_src = (const int*)d_in[18];
    const int* in_dst = (const int*)d_in[19];

    float* out = (float*)d_out;
    float* out_fv = out;                                  // [N,256]
    float* out_fe = out + (size_t)Nc * 256;               // [E,256]
    float* out_pred = out_fe + (size_t)Ec * 256;          // [N,10]

    float* p_feat_v; float* p_nf; float* p_ef;
    cudaGetSymbolAddress((void**)&p_feat_v, g_feat_v);
    cudaGetSymbolAddress((void**)&p_nf, g_nfused);
    cudaGetSymbolAddress((void**)&p_ef, g_efused);

    // CSR build (no prefix scan: warp-aggregated atomic range assignment)
    zero_cnts_kernel<<<(Nc + 255) / 256, 256>>>();
    hist_kernel<<<(Mc + 255) / 256, 256>>>(in_src, in_dst);
    assign_off_kernel<<<(Nc + 255) / 256, 256>>>();
    scatter_kernel<<<(Mc + 255) / 256, 256>>>(in_src, in_dst);

    const int gN = (Nc + 127) / 128;  // 391
    const int gE = (Ec + 127) / 128;  // 196
    // smem bytes: (2*128*40 + 2*BN*40) halfs * 2B
    const int SMEM_BN128 = 20480 + 128 * 160;  // 40960
    const int SMEM_BN64 = 20480 + 64 * 160;    // 30720

    // feat_v = vfeat @ W1^T + b1  (no fusion: SPLIT == NOUT)
    gemm_bf16x3<128, 256, 256><<<dim3(gN, 2), 256, SMEM_BN128>>>(
        vfeat, W1, b1, W1, b1, p_feat_v, Nc);
    // nfused = feat_v @ [Wve;Wqv]^T : cols 0-255 Wh, cols 256-319 q
    gemm_bf16x3<64, 320, 256><<<dim3(gN, 5), 256, SMEM_BN64>>>(
        p_feat_v, Wve, bve, Wqv, bqv, p_nf, Nc);
    // feat_e (written straight into output slot 2)
    edge_agg_kernel<<<Ec, 256>>>(vrw, ers, out_fe);
    // efused = feat_e @ [Wke;Wvale]^T : cols 0-63 k, cols 64-319 v
    gemm_bf16x3<64, 320, 64><<<dim3(gE, 5), 256, SMEM_BN64>>>(
        out_fe, Wke, bke, Wvale, bvale, p_ef, Ec);
    // attention -> feat_v_out (output slot 1)
    attn_kernel<<<(Nc + 7) / 8, 256>>>(out_fv);
    // pred (output slot 3)
    pred_kernel<<<(Nc + 7) / 8, 256>>>(out_fv, Wcls, bcls, out_pred);
}

// round 6
// speedup vs baseline: 2.1105x; 1.0042x over previous
#include <cuda_runtime.h>
#include <cuda_bf16.h>
#include <math.h>
#include <stdint.h>

#define Nc 50000
#define Ec 25000
#define Mc 300000
// dims: INPUT=VERTEX=EDGE=256, QUERY=64, NUM_CLASS=10

// ---------------- scratch (static device globals; no runtime alloc) ----------------
__device__ float g_nfused[(size_t)Nc * 320];  // cols 0-255: Wh, cols 256-319: q
__device__ float g_efused[(size_t)Ec * 320];  // cols 0-63: k, cols 64-319: v
__device__ __nv_bfloat16 g_vfhi[(size_t)Nc * 256], g_vflo[(size_t)Nc * 256];  // vfeat split
__device__ __nv_bfloat16 g_fvhi[(size_t)Nc * 256], g_fvlo[(size_t)Nc * 256];  // feat_v split
__device__ __nv_bfloat16 g_fehi[(size_t)Ec * 256], g_felo[(size_t)Ec * 256];  // feat_e split
__device__ __nv_bfloat16 g_w1hi[256 * 256], g_w1lo[256 * 256];
__device__ __nv_bfloat16 g_w2hi[320 * 256], g_w2lo[320 * 256];  // [Wve;Wqv]
__device__ __nv_bfloat16 g_w3hi[320 * 256], g_w3lo[320 * 256];  // [Wke;Wvale]
__device__ int g_ebeg[Ec];
__device__ int g_vbeg[Nc];
__device__ int g_ecnt[Ec];
__device__ int g_vcnt[Nc];
__device__ int g_ecur[Ec];
__device__ int g_vcur[Nc];
__device__ int g_tote, g_totn;
__device__ int g_elist[Mc];
__device__ int g_vlist[Mc];

// ---------------- CSR build ----------------
__global__ void zero_cnts_kernel() {
    int i = blockIdx.x * blockDim.x + threadIdx.x;
    if (i < Ec) g_ecnt[i] = 0;
    if (i < Nc) g_vcnt[i] = 0;
    if (i == 0) { g_tote = 0; g_totn = 0; }
}

__global__ void hist_kernel(const int* __restrict__ in_src, const int* __restrict__ in_dst) {
    int m = blockIdx.x * blockDim.x + threadIdx.x;
    if (m >= Mc) return;
    atomicAdd(&g_ecnt[in_dst[m]], 1);
    atomicAdd(&g_vcnt[in_src[m]], 1);
}

__global__ void assign_off_kernel() {
    int i = blockIdx.x * blockDim.x + threadIdx.x;
    int lane = threadIdx.x & 31;
    {
        int c = (i < Ec) ? g_ecnt[i] : 0;
        int x = c;
#pragma unroll
        for (int o = 1; o < 32; o <<= 1) {
            int y = __shfl_up_sync(0xffffffffu, x, o);
            if (lane >= o) x += y;
        }
        int wsum = __shfl_sync(0xffffffffu, x, 31);
        int base = 0;
        if (lane == 31 && wsum > 0) base = atomicAdd(&g_tote, wsum);
        base = __shfl_sync(0xffffffffu, base, 31);
        if (i < Ec) { int b = base + x - c; g_ebeg[i] = b; g_ecur[i] = b; }
    }
    {
        int c = (i < Nc) ? g_vcnt[i] : 0;
        int x = c;
#pragma unroll
        for (int o = 1; o < 32; o <<= 1) {
            int y = __shfl_up_sync(0xffffffffu, x, o);
            if (lane >= o) x += y;
        }
        int wsum = __shfl_sync(0xffffffffu, x, 31);
        int base = 0;
        if (lane == 31 && wsum > 0) base = atomicAdd(&g_totn, wsum);
        base = __shfl_sync(0xffffffffu, base, 31);
        if (i < Nc) { int b = base + x - c; g_vbeg[i] = b; g_vcur[i] = b; }
    }
}

__global__ void scatter_kernel(const int* __restrict__ in_src, const int* __restrict__ in_dst) {
    int m = blockIdx.x * blockDim.x + threadIdx.x;
    if (m >= Mc) return;
    int s = in_src[m];
    int e = in_dst[m];
    int pe = atomicAdd(&g_ecur[e], 1);
    g_elist[pe] = s;
    int pv = atomicAdd(&g_vcur[s], 1);
    g_vlist[pv] = e;
}

// ---------------- helpers ----------------
__device__ __forceinline__ void pack4(float4 v, uint2& hi, uint2& lo) {
    __nv_bfloat16 h0 = __float2bfloat16(v.x);
    __nv_bfloat16 h1 = __float2bfloat16(v.y);
    __nv_bfloat16 h2 = __float2bfloat16(v.z);
    __nv_bfloat16 h3 = __float2bfloat16(v.w);
    __nv_bfloat16 l0 = __float2bfloat16(v.x - __bfloat162float(h0));
    __nv_bfloat16 l1 = __float2bfloat16(v.y - __bfloat162float(h1));
    __nv_bfloat16 l2 = __float2bfloat16(v.z - __bfloat162float(h2));
    __nv_bfloat16 l3 = __float2bfloat16(v.w - __bfloat162float(h3));
    hi.x = ((uint32_t)__bfloat16_as_ushort(h1) << 16) | __bfloat16_as_ushort(h0);
    hi.y = ((uint32_t)__bfloat16_as_ushort(h3) << 16) | __bfloat16_as_ushort(h2);
    lo.x = ((uint32_t)__bfloat16_as_ushort(l1) << 16) | __bfloat16_as_ushort(l0);
    lo.y = ((uint32_t)__bfloat16_as_ushort(l3) << 16) | __bfloat16_as_ushort(l2);
}

__device__ __forceinline__ void mma16816(float* d, const uint32_t* a, uint32_t b0, uint32_t b1) {
    asm volatile(
        "mma.sync.aligned.m16n8k16.row.col.f32.bf16.bf16.f32 "
        "{%0,%1,%2,%3},{%4,%5,%6,%7},{%8,%9},{%0,%1,%2,%3};"
        : "+f"(d[0]), "+f"(d[1]), "+f"(d[2]), "+f"(d[3])
        : "r"(a[0]), "r"(a[1]), "r"(a[2]), "r"(a[3]), "r"(b0), "r"(b1));
}

__device__ __forceinline__ void ldsm_x4(uint32_t* r, uint32_t addr) {
    asm volatile("ldmatrix.sync.aligned.m8n8.x4.shared.b16 {%0,%1,%2,%3}, [%4];"
                 : "=r"(r[0]), "=r"(r[1]), "=r"(r[2]), "=r"(r[3]) : "r"(addr));
}

__device__ __forceinline__ uint32_t smem_u32(const void* p) {
    uint32_t a;
    asm("{ .reg .u64 t; cvta.to.shared.u64 t, %1; cvt.u32.u64 %0, t; }" : "=r"(a) : "l"(p));
    return a;
}

__device__ __forceinline__ void cp_async16(uint32_t dst, const void* src, int src_bytes) {
    asm volatile("cp.async.cg.shared.global [%0], [%1], 16, %2;"
                 :: "r"(dst), "l"(src), "r"(src_bytes) : "memory");
}
#define CP_COMMIT() asm volatile("cp.async.commit_group;" ::: "memory")
#define CP_WAIT(n) asm volatile("cp.async.wait_group %0;" :: "n"(n) : "memory")

// ---------------- fp32 -> bf16 hi/lo split (streaming) ----------------
__global__ void conv_split(const float4* __restrict__ src, __nv_bfloat16* __restrict__ hi,
                           __nv_bfloat16* __restrict__ lo, int n4) {
    int i = blockIdx.x * blockDim.x + threadIdx.x;
    if (i >= n4) return;
    float4 v = src[i];
    uint2 h, l;
    pack4(v, h, l);
    *(uint2*)(hi + (size_t)i * 4) = h;
    *(uint2*)(lo + (size_t)i * 4) = l;
}

// ---------------- pre-split bf16x3 GEMM: C[M,NOUT] = A @ W^T + bias ----------------
// A given as (ahi, alo) bf16 [M,256]; W prefused (whi, wlo) bf16 [NOUT,256].
// cp.async double-buffered; ldmatrix fragment loads; CTA 128 x BN; 8 warps 4x2.
// OUTMODE 0: write fp32 C. OUTMODE 1: write bf16 hi/lo split (chi, clo).
template <int BN, int NOUT, int SPLIT, int OUTMODE>
__global__ __launch_bounds__(256) void gemm_pre(
    const __nv_bfloat16* __restrict__ ahi, const __nv_bfloat16* __restrict__ alo,
    const __nv_bfloat16* __restrict__ whi, const __nv_bfloat16* __restrict__ wlo,
    const float* __restrict__ b1, const float* __restrict__ b2,
    float* __restrict__ C, __nv_bfloat16* __restrict__ chi, __nv_bfloat16* __restrict__ clo,
    int Mrows) {
    constexpr int WN = BN / 2;
    constexpr int NF = WN / 8;
    // per-stage layout in halfs (stride 40 halfs = 80B, conflict-free for ldmatrix)
    constexpr int AHo = 0;
    constexpr int ALo = 5120;
    constexpr int BHo = 10240;
    constexpr int BLo = 10240 + 40 * BN;
    constexpr int STG = 10240 + 80 * BN;  // halfs per stage
    extern __shared__ __nv_bfloat16 sm[];
    const uint32_t smb = smem_u32(sm);

    int tid = threadIdx.x;
    int lane = tid & 31, wid = tid >> 5;
    int wm = wid & 3, wn = wid >> 2;
    int qr = lane >> 2, qc = (lane & 3) * 2;
    int bm = blockIdx.x * 128, bn = blockIdx.y * BN;

    int a_row = wm * 32 + (lane & 7) + ((lane >> 3) & 1) * 8;
    int a_col = ((lane >> 4) & 1) * 8;
    int b_col = ((lane >> 3) & 1) * 8;
    int b_rowl = (lane & 7) + ((lane >> 4) & 1) * 8;

    float acc[2][NF][4];
#pragma unroll
    for (int mf = 0; mf < 2; mf++)
#pragma unroll
        for (int nf = 0; nf < NF; nf++)
#pragma unroll
            for (int j = 0; j < 4; j++) acc[mf][nf][j] = 0.f;

    auto load_chunk = [&](int ck, int stage) {
        uint32_t base = smb + (uint32_t)stage * (STG * 2);
        // A: 128 rows x 4 16B-segments, hi + lo
#pragma unroll
        for (int i = 0; i < 2; i++) {
            int f = tid + i * 256;
            int row = f >> 2, sg = f & 3;
            int ok = (bm + row < Mrows) ? 16 : 0;
            size_t goff = (size_t)(bm + row) * 256 + ck * 32 + sg * 8;
            uint32_t d = base + (AHo + row * 40 + sg * 8) * 2;
            cp_async16(d, ahi + goff, ok);
            cp_async16(d + (ALo - AHo) * 2, alo + goff, ok);
        }
        // B: BN rows x 4 segments, hi + lo (weights always in-bounds)
#pragma unroll
        for (int i = 0; i < BN / 64; i++) {
            int f = tid + i * 256;
            int row = f >> 2, sg = f & 3;
            size_t goff = (size_t)(bn + row) * 256 + ck * 32 + sg * 8;
            uint32_t d = base + (BHo + row * 40 + sg * 8) * 2;
            cp_async16(d, whi + goff, 16);
            cp_async16(d + (BLo - BHo) * 2, wlo + goff, 16);
        }
    };

    load_chunk(0, 0);
    CP_COMMIT();

    for (int c = 0; c < 8; c++) {
        if (c < 7) {
            load_chunk(c + 1, (c + 1) & 1);
            CP_COMMIT();
            CP_WAIT(1);
        } else {
            CP_WAIT(0);
        }
        __syncthreads();
        uint32_t base = smb + (uint32_t)(c & 1) * (STG * 2);
#pragma unroll
        for (int ks = 0; ks < 32; ks += 16) {
            uint32_t ah[2][4], al[2][4];
#pragma unroll
            for (int mf = 0; mf < 2; mf++) {
                uint32_t off = ((a_row + mf * 16) * 40 + a_col + ks) * 2;
                ldsm_x4(ah[mf], base + AHo * 2 + off);
                ldsm_x4(al[mf], base + ALo * 2 + off);
            }
            uint32_t bh[NF][2], bl[NF][2];
#pragma unroll
            for (int np = 0; np < NF / 2; np++) {
                uint32_t off = ((wn * WN + np * 16 + b_rowl) * 40 + b_col + ks) * 2;
                uint32_t t[4];
                ldsm_x4(t, base + BHo * 2 + off);
                bh[2 * np][0] = t[0]; bh[2 * np][1] = t[1];
                bh[2 * np + 1][0] = t[2]; bh[2 * np + 1][1] = t[3];
                ldsm_x4(t, base + BLo * 2 + off);
                bl[2 * np][0] = t[0]; bl[2 * np][1] = t[1];
                bl[2 * np + 1][0] = t[2]; bl[2 * np + 1][1] = t[3];
            }
#pragma unroll
            for (int nf = 0; nf < NF; nf++) {
#pragma unroll
                for (int mf = 0; mf < 2; mf++) {
                    mma16816(acc[mf][nf], ah[mf], bh[nf][0], bh[nf][1]);
                    mma16816(acc[mf][nf], ah[mf], bl[nf][0], bl[nf][1]);
                    mma16816(acc[mf][nf], al[mf], bh[nf][0], bh[nf][1]);
                }
            }
        }
        __syncthreads();
    }

    // epilogue
#pragma unroll
    for (int mf = 0; mf < 2; mf++) {
#pragma unroll
        for (int nf = 0; nf < NF; nf++) {
            int m0 = bm + wm * 32 + mf * 16 + qr;
            int n0 = bn + wn * WN + nf * 8 + qc;
            float bv0 = (n0 < SPLIT) ? b1[n0] : b2[n0 - SPLIT];
            float bv1 = (n0 + 1 < SPLIT) ? b1[n0 + 1] : b2[n0 + 1 - SPLIT];
            float c00 = acc[mf][nf][0] + bv0, c01 = acc[mf][nf][1] + bv1;
            float c10 = acc[mf][nf][2] + bv0, c11 = acc[mf][nf][3] + bv1;
            if (OUTMODE == 0) {
                if (m0 < Mrows) *(float2*)(C + (size_t)m0 * NOUT + n0) = make_float2(c00, c01);
                if (m0 + 8 < Mrows) *(float2*)(C + (size_t)(m0 + 8) * NOUT + n0) = make_float2(c10, c11);
            } else {
                if (m0 < Mrows) {
                    __nv_bfloat16 h0 = __float2bfloat16(c00), h1 = __float2bfloat16(c01);
                    uint32_t ph = ((uint32_t)__bfloat16_as_ushort(h1) << 16) | __bfloat16_as_ushort(h0);
                    uint32_t pl = ((uint32_t)__bfloat16_as_ushort(__float2bfloat16(c01 - __bfloat162float(h1))) << 16) |
                                  __bfloat16_as_ushort(__float2bfloat16(c00 - __bfloat162float(h0)));
                    *(uint32_t*)(chi + (size_t)m0 * NOUT + n0) = ph;
                    *(uint32_t*)(clo + (size_t)m0 * NOUT + n0) = pl;
                }
                if (m0 + 8 < Mrows) {
                    __nv_bfloat16 h0 = __float2bfloat16(c10), h1 = __float2bfloat16(c11);
                    uint32_t ph = ((uint32_t)__bfloat16_as_ushort(h1) << 16) | __bfloat16_as_ushort(h0);
                    uint32_t pl = ((uint32_t)__bfloat16_as_ushort(__float2bfloat16(c11 - __bfloat162float(h1))) << 16) |
                                  __bfloat16_as_ushort(__float2bfloat16(c10 - __bfloat162float(h0)));
                    *(uint32_t*)(chi + (size_t)(m0 + 8) * NOUT + n0) = ph;
                    *(uint32_t*)(clo + (size_t)(m0 + 8) * NOUT + n0) = pl;
                }
            }
        }
    }
}

// ---------------- hyperedge aggregation (+ bf16 split epilogue for next GEMM) ----------
__global__ __launch_bounds__(256) void edge_agg_kernel(
    const float* __restrict__ vrw, const float* __restrict__ ers,
    float* __restrict__ feat_e) {
    int e = blockIdx.x;
    int t = threadIdx.x;
    int beg = g_ebeg[e], end = beg + g_ecnt[e];
    float acc = 0.f;
    for (int i = beg; i < end; i++) {
        int s = g_elist[i];
        acc += vrw[s] * g_nfused[(size_t)s * 320 + t];
    }
    float val = acc / ers[e];
    feat_e[(size_t)e * 256 + t] = val;
    __nv_bfloat16 h = __float2bfloat16(val);
    g_fehi[(size_t)e * 256 + t] = h;
    g_felo[(size_t)e * 256 + t] = __float2bfloat16(val - __bfloat162float(h));
}

// ---------------- per-vertex attention: single-pass online softmax (one warp/vertex) ----
__global__ __launch_bounds__(256) void attn_kernel(float* __restrict__ out_fv) {
    int gw = (blockIdx.x * blockDim.x + threadIdx.x) >> 5;
    int lane = threadIdx.x & 31;
    if (gw >= Nc) return;
    int n = gw;
    int beg = g_vbeg[n], end = beg + g_vcnt[n];
    float q0 = g_nfused[(size_t)n * 320 + 256 + lane];
    float q1 = g_nfused[(size_t)n * 320 + 288 + lane];
    const float scale = 0.125f;

    float m = -1e30f;
    float denom = 0.f;
    float4 a0 = make_float4(0.f, 0.f, 0.f, 0.f);
    float4 a1 = make_float4(0.f, 0.f, 0.f, 0.f);
    for (int i = beg; i < end; i++) {
        int e = g_vlist[i];
        const float* kv = g_efused + (size_t)e * 320;
        float s = q0 * kv[lane] + q1 * kv[32 + lane];
#pragma unroll
        for (int o = 16; o; o >>= 1) s += __shfl_xor_sync(0xffffffffu, s, o);
        s = (s > 0.f ? s : 0.01f * s) * scale;
        float mnew = fmaxf(m, s);
        float corr = __expf(m - mnew);
        float p = __expf(s - mnew);
        m = mnew;
        denom = denom * corr + p;
        const float4* vp = (const float4*)(kv + 64);
        float4 v0 = vp[lane];
        float4 v1 = vp[32 + lane];
        a0.x = a0.x * corr + p * v0.x; a0.y = a0.y * corr + p * v0.y;
        a0.z = a0.z * corr + p * v0.z; a0.w = a0.w * corr + p * v0.w;
        a1.x = a1.x * corr + p * v1.x; a1.y = a1.y * corr + p * v1.y;
        a1.z = a1.z * corr + p * v1.z; a1.w = a1.w * corr + p * v1.w;
    }
    float inv = 1.f / fmaxf(denom, 1e-20f);
    a0.x *= inv; a0.y *= inv; a0.z *= inv; a0.w *= inv;
    a1.x *= inv; a1.y *= inv; a1.z *= inv; a1.w *= inv;
    float4* op = (float4*)(out_fv + (size_t)n * 256);
    op[lane] = a0;
    op[32 + lane] = a1;
}

// ---------------- classification head ----------------
__global__ __launch_bounds__(256) void pred_kernel(
    const float* __restrict__ fv, const float* __restrict__ Wc,
    const float* __restrict__ bc, float* __restrict__ pred) {
    __shared__ float sW[10 * 256];
    __shared__ float sb_[10];
    int t = threadIdx.x;
    for (int i = t; i < 2560; i += 256) sW[i] = Wc[i];
    if (t < 10) sb_[t] = bc[t];
    __syncthreads();
    int warp = t >> 5, lane = t & 31;
    int r = blockIdx.x * 8 + warp;
    if (r >= Nc) return;
    float acc[10];
#pragma unroll
    for (int c = 0; c < 10; c++) acc[c] = 0.f;
    for (int kk = lane; kk < 256; kk += 32) {
        float x = fv[(size_t)r * 256 + kk];
#pragma unroll
        for (int c = 0; c < 10; c++) acc[c] += x * sW[c * 256 + kk];
    }
#pragma unroll
    for (int c = 0; c < 10; c++) {
#pragma unroll
        for (int o = 16; o; o >>= 1) acc[c] += __shfl_xor_sync(0xffffffffu, acc[c], o);
    }
    if (lane == 0) {
#pragma unroll
        for (int c = 0; c < 10; c++) pred[(size_t)r * 10 + c] = acc[c] + sb_[c];
    }
}

// ---------------- launch ----------------
extern "C" void kernel_launch(void* const* d_in, const int* in_sizes, int n_in,
                              void* d_out, int out_size) {
    const float* vfeat = (const float*)d_in[0];
    const float* vrw = (const float*)d_in[2];
    const float* ers = (const float*)d_in[5];
    const float* W1 = (const float*)d_in[6];
    const float* b1 = (const float*)d_in[7];
    const float* Wve = (const float*)d_in[8];
    const float* bve = (const float*)d_in[9];
    const float* Wqv = (const float*)d_in[10];
    const float* bqv = (const float*)d_in[11];
    const float* Wke = (const float*)d_in[12];
    const float* bke = (const float*)d_in[13];
    const float* Wvale = (const float*)d_in[14];
    const float* bvale = (const float*)d_in[15];
    const float* Wcls = (const float*)d_in[16];
    const float* bcls = (const float*)d_in[17];
    const int* in_src = (const int*)d_in[18];
    const int* in_dst = (const int*)d_in[19];

    float* out = (float*)d_out;
    float* out_fv = out;
    float* out_fe = out + (size_t)Nc * 256;
    float* out_pred = out_fe + (size_t)Ec * 256;

    __nv_bfloat16 *p_vfhi, *p_vflo, *p_fvhi, *p_fvlo, *p_fehi, *p_felo;
    __nv_bfloat16 *p_w1hi, *p_w1lo, *p_w2hi, *p_w2lo, *p_w3hi, *p_w3lo;
    float *p_nf, *p_ef;
    cudaGetSymbolAddress((void**)&p_vfhi, g_vfhi);
    cudaGetSymbolAddress((void**)&p_vflo, g_vflo);
    cudaGetSymbolAddress((void**)&p_fvhi, g_fvhi);
    cudaGetSymbolAddress((void**)&p_fvlo, g_fvlo);
    cudaGetSymbolAddress((void**)&p_fehi, g_fehi);
    cudaGetSymbolAddress((void**)&p_felo, g_felo);
    cudaGetSymbolAddress((void**)&p_w1hi, g_w1hi);
    cudaGetSymbolAddress((void**)&p_w1lo, g_w1lo);
    cudaGetSymbolAddress((void**)&p_w2hi, g_w2hi);
    cudaGetSymbolAddress((void**)&p_w2lo, g_w2lo);
    cudaGetSymbolAddress((void**)&p_w3hi, g_w3hi);
    cudaGetSymbolAddress((void**)&p_w3lo, g_w3lo);
    cudaGetSymbolAddress((void**)&p_nf, g_nfused);
    cudaGetSymbolAddress((void**)&p_ef, g_efused);

    // smem for GEMM: 2 stages * (10240 + 80*64) halfs * 2B = 61440
    const int SMEM = 2 * (10240 + 80 * 64) * 2;
    cudaFuncSetAttribute(gemm_pre<64, 256, 256, 1>, cudaFuncAttributeMaxDynamicSharedMemorySize, SMEM);
    cudaFuncSetAttribute(gemm_pre<64, 320, 256, 0>, cudaFuncAttributeMaxDynamicSharedMemorySize, SMEM);
    cudaFuncSetAttribute(gemm_pre<64, 320, 64, 0>, cudaFuncAttributeMaxDynamicSharedMemorySize, SMEM);

    // CSR build
    zero_cnts_kernel<<<(Nc + 255) / 256, 256>>>();
    hist_kernel<<<(Mc + 255) / 256, 256>>>(in_src, in_dst);
    assign_off_kernel<<<(Nc + 255) / 256, 256>>>();
    scatter_kernel<<<(Mc + 255) / 256, 256>>>(in_src, in_dst);

    // operand conversions (once)
    conv_split<<<(Nc * 64 + 255) / 256, 256>>>((const float4*)vfeat, p_vfhi, p_vflo, Nc * 64);
    conv_split<<<(256 * 64 + 255) / 256, 256>>>((const float4*)W1, p_w1hi, p_w1lo, 256 * 64);
    conv_split<<<(256 * 64 + 255) / 256, 256>>>((const float4*)Wve, p_w2hi, p_w2lo, 256 * 64);
    conv_split<<<(64 * 64 + 255) / 256, 256>>>((const float4*)Wqv, p_w2hi + 256 * 256, p_w2lo + 256 * 256, 64 * 64);
    conv_split<<<(64 * 64 + 255) / 256, 256>>>((const float4*)Wke, p_w3hi, p_w3lo, 64 * 64);
    conv_split<<<(256 * 64 + 255) / 256, 256>>>((const float4*)Wvale, p_w3hi + 64 * 256, p_w3lo + 64 * 256, 256 * 64);

    const int gN = (Nc + 127) / 128;  // 391
    const int gE = (Ec + 127) / 128;  // 196

    // feat_v (bf16 split only) = vfeat @ W1^T + b1
    gemm_pre<64, 256, 256, 1><<<dim3(gN, 4), 256, SMEM>>>(
        p_vfhi, p_vflo, p_w1hi, p_w1lo, b1, b1, nullptr, p_fvhi, p_fvlo, Nc);
    // nfused = feat_v @ [Wve;Wqv]^T (cols 0-255 Wh, 256-319 q)
    gemm_pre<64, 320, 256, 0><<<dim3(gN, 5), 256, SMEM>>>(
        p_fvhi, p_fvlo, p_w2hi, p_w2lo, bve, bqv, p_nf, nullptr, nullptr, Nc);
    // feat_e -> out_fe (+ bf16 split for gemm3)
    edge_agg_kernel<<<Ec, 256>>>(vrw, ers, out_fe);
    // efused = feat_e @ [Wke;Wvale]^T (cols 0-63 k, 64-319 v)
    gemm_pre<64, 320, 64, 0><<<dim3(gE, 5), 256, SMEM>>>(
        p_fehi, p_felo, p_w3hi, p_w3lo, bke, bvale, p_ef, nullptr, nullptr, Ec);
    // attention -> out_fv
    attn_kernel<<<(Nc + 7) / 8, 256>>>(out_fv);
    // pred
    pred_kernel<<<(Nc + 7) / 8, 256>>>(out_fv, Wcls, bcls, out_pred);
}

// round 7
// speedup vs baseline: 2.4181x; 1.1457x over previous
#include <cuda_runtime.h>
#include <cuda_fp16.h>
#include <math.h>
#include <stdint.h>

#define Nc 50000
#define Ec 25000
#define Mc 300000
// dims: INPUT=VERTEX=EDGE=256, QUERY=64, NUM_CLASS=10

// ---------------- scratch ----------------
__device__ __half g_vf16[(size_t)Nc * 256];                    // vfeat fp16
__device__ __half g_ch[(size_t)Nc * 320], g_cl[(size_t)Nc * 320];  // [feat_v|q] hi/lo
__device__ __half g_aggd[(size_t)Ec * 256];                    // aggregated feat_v per edge (fp16)
__device__ float g_swd[Ec];
__device__ float g_efused[(size_t)Ec * 320];                   // cols 0-63 k, 64-319 v (fp32)
// composed weights (fp32 tmp) + fp16 hi/lo fused weight banks
__device__ float g_wq1[64 * 256], g_wk2[64 * 256], g_wv2[256 * 256];
__device__ __half g_wNh[320 * 256], g_wNl[320 * 256];          // [W1; Wqv@W1]
__device__ __half g_wEh[576 * 256], g_wEl[576 * 256];          // [Wve; Wke@Wve; Wvale@Wve]
__device__ float g_bN[320];                                     // [b1; Wqv@b1+bqv]
__device__ float g_cb1[576];                                    // [bve; Wke@bve; Wvale@bve]
__device__ float g_cb2[576];                                    // [0; bke; bvale]
// CSR
__device__ int g_ebeg[Ec], g_vbeg[Nc], g_ecnt[Ec], g_vcnt[Nc];
__device__ int g_ecur[Ec], g_vcur[Nc];
__device__ int g_tote, g_totn;
__device__ int g_elist[Mc], g_vlist[Mc];

// ---------------- CSR build ----------------
__global__ void zero_cnts_kernel() {
    int i = blockIdx.x * blockDim.x + threadIdx.x;
    if (i < Ec) g_ecnt[i] = 0;
    if (i < Nc) g_vcnt[i] = 0;
    if (i == 0) { g_tote = 0; g_totn = 0; }
}

__global__ void hist_kernel(const int* __restrict__ in_src, const int* __restrict__ in_dst) {
    int m = blockIdx.x * blockDim.x + threadIdx.x;
    if (m >= Mc) return;
    atomicAdd(&g_ecnt[in_dst[m]], 1);
    atomicAdd(&g_vcnt[in_src[m]], 1);
}

__global__ void assign_off_kernel() {
    int i = blockIdx.x * blockDim.x + threadIdx.x;
    int lane = threadIdx.x & 31;
    {
        int c = (i < Ec) ? g_ecnt[i] : 0;
        int x = c;
#pragma unroll
        for (int o = 1; o < 32; o <<= 1) {
            int y = __shfl_up_sync(0xffffffffu, x, o);
            if (lane >= o) x += y;
        }
        int wsum = __shfl_sync(0xffffffffu, x, 31);
        int base = 0;
        if (lane == 31 && wsum > 0) base = atomicAdd(&g_tote, wsum);
        base = __shfl_sync(0xffffffffu, base, 31);
        if (i < Ec) { int b = base + x - c; g_ebeg[i] = b; g_ecur[i] = b; }
    }
    {
        int c = (i < Nc) ? g_vcnt[i] : 0;
        int x = c;
#pragma unroll
        for (int o = 1; o < 32; o <<= 1) {
            int y = __shfl_up_sync(0xffffffffu, x, o);
            if (lane >= o) x += y;
        }
        int wsum = __shfl_sync(0xffffffffu, x, 31);
        int base = 0;
        if (lane == 31 && wsum > 0) base = atomicAdd(&g_totn, wsum);
        base = __shfl_sync(0xffffffffu, base, 31);
        if (i < Nc) { int b = base + x - c; g_vbeg[i] = b; g_vcur[i] = b; }
    }
}

__global__ void scatter_kernel(const int* __restrict__ in_src, const int* __restrict__ in_dst) {
    int m = blockIdx.x * blockDim.x + threadIdx.x;
    if (m >= Mc) return;
    int s = in_src[m];
    int e = in_dst[m];
    int pe = atomicAdd(&g_ecur[e], 1);
    g_elist[pe] = s;
    int pv = atomicAdd(&g_vcur[s], 1);
    g_vlist[pv] = e;
}

// ---------------- weight composition (exact fp32 algebra) ----------------
// blocks 0-63: Wqv@W1 -> g_wq1 ; 64-127: Wke@Wve -> g_wk2 ; 128-383: Wvale@Wve -> g_wv2
__global__ void compose_w(const float* __restrict__ Wqv, const float* __restrict__ W1,
                          const float* __restrict__ Wke, const float* __restrict__ Wve,
                          const float* __restrict__ Wvale) {
    int r = blockIdx.x, j = threadIdx.x;
    const float* A; const float* B; float* C; int rr;
    if (r < 64) { A = Wqv; B = W1; C = g_wq1; rr = r; }
    else if (r < 128) { A = Wke; B = Wve; C = g_wk2; rr = r - 64; }
    else { A = Wvale; B = Wve; C = g_wv2; rr = r - 128; }
    float acc = 0.f;
    for (int k = 0; k < 256; k++) acc += A[rr * 256 + k] * B[k * 256 + j];
    C[rr * 256 + j] = acc;
}

// bias composition + small copies (one launch: 48 blocks x 256 = 384 warps)
__global__ void compose_b(const float* __restrict__ Wqv, const float* __restrict__ b1,
                          const float* __restrict__ bqv, const float* __restrict__ Wke,
                          const float* __restrict__ Wvale, const float* __restrict__ bve,
                          const float* __restrict__ bke, const float* __restrict__ bvale) {
    int t = blockIdx.x * blockDim.x + threadIdx.x;
    int gw = t >> 5, lane = t & 31;
    if (gw < 384) {
        const float* M; const float* v; int i; float add = 0.f; float* dst;
        if (gw < 64) { M = Wqv; v = b1; i = gw; add = bqv[i]; dst = &g_bN[256 + i]; }
        else if (gw < 128) { M = Wke; v = bve; i = gw - 64; dst = &g_cb1[256 + i]; }
        else { M = Wvale; v = bve; i = gw - 128; dst = &g_cb1[320 + i]; }
        float s = 0.f;
        for (int k = lane; k < 256; k += 32) s += M[i * 256 + k] * v[k];
#pragma unroll
        for (int o = 16; o; o >>= 1) s += __shfl_xor_sync(0xffffffffu, s, o);
        if (lane == 0) *dst = s + add;
    }
    if (t < 256) { g_bN[t] = b1[t]; g_cb1[t] = bve[t]; g_cb2[t] = 0.f; }
    else if (t < 320) g_cb2[t] = bke[t - 256];
    else if (t < 576) g_cb2[t] = bvale[t - 320];
}

// ---------------- fp32 -> fp16 conversions ----------------
__global__ void split_hl(const float4* __restrict__ src, __half* __restrict__ hi,
                         __half* __restrict__ lo, int n4) {
    int i = blockIdx.x * blockDim.x + threadIdx.x;
    if (i >= n4) return;
    float4 v = src[i];
    __half h0 = __float2half_rn(v.x), h1 = __float2half_rn(v.y);
    __half h2 = __float2half_rn(v.z), h3 = __float2half_rn(v.w);
    __half l0 = __float2half_rn(v.x - __half2float(h0));
    __half l1 = __float2half_rn(v.y - __half2float(h1));
    __half l2 = __float2half_rn(v.z - __half2float(h2));
    __half l3 = __float2half_rn(v.w - __half2float(h3));
    uint2 H, L;
    H.x = ((uint32_t)__half_as_ushort(h1) << 16) | __half_as_ushort(h0);
    H.y = ((uint32_t)__half_as_ushort(h3) << 16) | __half_as_ushort(h2);
    L.x = ((uint32_t)__half_as_ushort(l1) << 16) | __half_as_ushort(l0);
    L.y = ((uint32_t)__half_as_ushort(l3) << 16) | __half_as_ushort(l2);
    *(uint2*)(hi + (size_t)i * 4) = H;
    *(uint2*)(lo + (size_t)i * 4) = L;
}

__global__ void conv_h(const float4* __restrict__ src, __half* __restrict__ dst, int n4) {
    int i = blockIdx.x * blockDim.x + threadIdx.x;
    if (i >= n4) return;
    float4 v = src[i];
    uint2 H;
    H.x = ((uint32_t)__half_as_ushort(__float2half_rn(v.y)) << 16) | __half_as_ushort(__float2half_rn(v.x));
    H.y = ((uint32_t)__half_as_ushort(__float2half_rn(v.w)) << 16) | __half_as_ushort(__float2half_rn(v.z));
    *(uint2*)(dst + (size_t)i * 4) = H;
}

// ---------------- MMA helpers ----------------
__device__ __forceinline__ void mma16816h(float* d, const uint32_t* a, uint32_t b0, uint32_t b1) {
    asm volatile(
        "mma.sync.aligned.m16n8k16.row.col.f32.f16.f16.f32 "
        "{%0,%1,%2,%3},{%4,%5,%6,%7},{%8,%9},{%0,%1,%2,%3};"
        : "+f"(d[0]), "+f"(d[1]), "+f"(d[2]), "+f"(d[3])
        : "r"(a[0]), "r"(a[1]), "r"(a[2]), "r"(a[3]), "r"(b0), "r"(b1));
}

__device__ __forceinline__ void ldsm_x4(uint32_t* r, uint32_t addr) {
    asm volatile("ldmatrix.sync.aligned.m8n8.x4.shared.b16 {%0,%1,%2,%3}, [%4];"
                 : "=r"(r[0]), "=r"(r[1]), "=r"(r[2]), "=r"(r[3]) : "r"(addr));
}

__device__ __forceinline__ uint32_t smem_u32(const void* p) {
    uint32_t a;
    asm("{ .reg .u64 t; cvta.to.shared.u64 t, %1; cvt.u32.u64 %0, t; }" : "=r"(a) : "l"(p));
    return a;
}

__device__ __forceinline__ void cp_async16(uint32_t dst, const void* src, int src_bytes) {
    asm volatile("cp.async.cg.shared.global [%0], [%1], 16, %2;"
                 :: "r"(dst), "l"(src), "r"(src_bytes) : "memory");
}
#define CP_COMMIT() asm volatile("cp.async.commit_group;" ::: "memory")
#define CP_WAIT(n) asm volatile("cp.async.wait_group %0;" :: "n"(n) : "memory")

// ---------------- fp16x2 GEMM: C[M,NOUT] = A[M,256] @ W^T (+epilogue) ----------------
// A single fp16; W as fp16 hi/lo (exact-split weights): D = A*Wh + A*Wl, residual ~2^-12.
// MODE 0: out = hi/lo fp16 split of (acc + bias[n])           -> chi, clo [M,NOUT]
// MODE 1: out fp32 = acc + swd[m]*cb1[n] + cb2[n]; cols<256 -> outA[M,256], else outB[M,320]
template <int BN, int NOUT, int MODE>
__global__ __launch_bounds__(256) void gemm_f16(
    const __half* __restrict__ A,
    const __half* __restrict__ whi, const __half* __restrict__ wlo,
    const float* __restrict__ bias,
    const float* __restrict__ cb1, const float* __restrict__ cb2,
    const float* __restrict__ swd,
    __half* __restrict__ chi, __half* __restrict__ clo,
    float* __restrict__ outA, float* __restrict__ outB,
    int Mrows) {
    constexpr int WN = BN / 2;
    constexpr int NF = WN / 8;
    constexpr int Ao = 0;
    constexpr int Bho = 5120;
    constexpr int Blo_ = 5120 + 40 * BN;
    constexpr int STG = 5120 + 80 * BN;  // halfs per stage
    extern __shared__ __half sm[];
    const uint32_t smb = smem_u32(sm);

    int tid = threadIdx.x;
    int lane = tid & 31, wid = tid >> 5;
    int wm = wid & 3, wn = wid >> 2;
    int qr = lane >> 2, qc = (lane & 3) * 2;
    int bm = blockIdx.x * 128, bn = blockIdx.y * BN;

    int a_row = wm * 32 + (lane & 7) + ((lane >> 3) & 1) * 8;
    int a_col = ((lane >> 4) & 1) * 8;
    int b_col = ((lane >> 3) & 1) * 8;
    int b_rowl = (lane & 7) + ((lane >> 4) & 1) * 8;

    float acc[2][NF][4];
#pragma unroll
    for (int mf = 0; mf < 2; mf++)
#pragma unroll
        for (int nf = 0; nf < NF; nf++)
#pragma unroll
            for (int j = 0; j < 4; j++) acc[mf][nf][j] = 0.f;

    auto load_chunk = [&](int ck, int stage) {
        uint32_t base = smb + (uint32_t)stage * (STG * 2);
        // A: 128 rows x 32 halfs (4 x 16B segments per row): 512 ops / 256 thr = 2 each
#pragma unroll
        for (int i = 0; i < 2; i++) {
            int f = tid + i * 256;
            int row = f >> 2, sg = f & 3;
            int ok = (bm + row < Mrows) ? 16 : 0;
            cp_async16(base + (Ao + row * 40 + sg * 8) * 2,
                       A + (size_t)(bm + row) * 256 + ck * 32 + sg * 8, ok);
        }
        // W hi+lo: BN rows x 4 segments each
        {
            int row = tid >> 2, sg = tid & 3;
            size_t goff = (size_t)(bn + row) * 256 + ck * 32 + sg * 8;
            cp_async16(base + (Bho + row * 40 + sg * 8) * 2, whi + goff, 16);
            cp_async16(base + (Blo_ + row * 40 + sg * 8) * 2, wlo + goff, 16);
        }
    };

    load_chunk(0, 0);
    CP_COMMIT();

    for (int c = 0; c < 8; c++) {
        if (c < 7) {
            load_chunk(c + 1, (c + 1) & 1);
            CP_COMMIT();
            CP_WAIT(1);
        } else {
            CP_WAIT(0);
        }
        __syncthreads();
        uint32_t base = smb + (uint32_t)(c & 1) * (STG * 2);
#pragma unroll
        for (int ks = 0; ks < 32; ks += 16) {
            uint32_t ah[2][4];
#pragma unroll
            for (int mf = 0; mf < 2; mf++) {
                uint32_t off = ((a_row + mf * 16) * 40 + a_col + ks) * 2;
                ldsm_x4(ah[mf], base + Ao * 2 + off);
            }
            uint32_t bh[NF][2], bl[NF][2];
#pragma unroll
            for (int np = 0; np < NF / 2; np++) {
                uint32_t off = ((wn * WN + np * 16 + b_rowl) * 40 + b_col + ks) * 2;
                uint32_t t[4];
                ldsm_x4(t, base + Bho * 2 + off);
                bh[2 * np][0] = t[0]; bh[2 * np][1] = t[1];
                bh[2 * np + 1][0] = t[2]; bh[2 * np + 1][1] = t[3];
                ldsm_x4(t, base + Blo_ * 2 + off);
                bl[2 * np][0] = t[0]; bl[2 * np][1] = t[1];
                bl[2 * np + 1][0] = t[2]; bl[2 * np + 1][1] = t[3];
            }
#pragma unroll
            for (int nf = 0; nf < NF; nf++) {
#pragma unroll
                for (int mf = 0; mf < 2; mf++) {
                    mma16816h(acc[mf][nf], ah[mf], bh[nf][0], bh[nf][1]);
                    mma16816h(acc[mf][nf], ah[mf], bl[nf][0], bl[nf][1]);
                }
            }
        }
        __syncthreads();
    }

    // epilogue
#pragma unroll
    for (int mf = 0; mf < 2; mf++) {
#pragma unroll
        for (int nf = 0; nf < NF; nf++) {
            int m0 = bm + wm * 32 + mf * 16 + qr;
            int n0 = bn + wn * WN + nf * 8 + qc;
            if (MODE == 0) {
                float bv0 = bias[n0], bv1 = bias[n0 + 1];
                float c00 = acc[mf][nf][0] + bv0, c01 = acc[mf][nf][1] + bv1;
                float c10 = acc[mf][nf][2] + bv0, c11 = acc[mf][nf][3] + bv1;
                if (m0 < Mrows) {
                    __half h0 = __float2half_rn(c00), h1 = __float2half_rn(c01);
                    uint32_t ph = ((uint32_t)__half_as_ushort(h1) << 16) | __half_as_ushort(h0);
                    uint32_t pl = ((uint32_t)__half_as_ushort(__float2half_rn(c01 - __half2float(h1))) << 16) |
                                  __half_as_ushort(__float2half_rn(c00 - __half2float(h0)));
                    *(uint32_t*)(chi + (size_t)m0 * NOUT + n0) = ph;
                    *(uint32_t*)(clo + (size_t)m0 * NOUT + n0) = pl;
                }
                if (m0 + 8 < Mrows) {
                    __half h0 = __float2half_rn(c10), h1 = __float2half_rn(c11);
                    uint32_t ph = ((uint32_t)__half_as_ushort(h1) << 16) | __half_as_ushort(h0);
                    uint32_t pl = ((uint32_t)__half_as_ushort(__float2half_rn(c11 - __half2float(h1))) << 16) |
                                  __half_as_ushort(__float2half_rn(c10 - __half2float(h0)));
                    *(uint32_t*)(chi + (size_t)(m0 + 8) * NOUT + n0) = ph;
                    *(uint32_t*)(clo + (size_t)(m0 + 8) * NOUT + n0) = pl;
                }
            } else {
                float e0 = cb1[n0], e1 = cb1[n0 + 1];
                float f0 = cb2[n0], f1 = cb2[n0 + 1];
                float sw0 = (m0 < Mrows) ? swd[m0] : 0.f;
                float sw1 = (m0 + 8 < Mrows) ? swd[m0 + 8] : 0.f;
                float c00 = acc[mf][nf][0] + sw0 * e0 + f0, c01 = acc[mf][nf][1] + sw0 * e1 + f1;
                float c10 = acc[mf][nf][2] + sw1 * e0 + f0, c11 = acc[mf][nf][3] + sw1 * e1 + f1;
                if (n0 < 256) {
                    if (m0 < Mrows) *(float2*)(outA + (size_t)m0 * 256 + n0) = make_float2(c00, c01);
                    if (m0 + 8 < Mrows) *(float2*)(outA + (size_t)(m0 + 8) * 256 + n0) = make_float2(c10, c11);
                } else {
                    if (m0 < Mrows) *(float2*)(outB + (size_t)m0 * 320 + n0 - 256) = make_float2(c00, c01);
                    if (m0 + 8 < Mrows) *(float2*)(outB + (size_t)(m0 + 8) * 320 + n0 - 256) = make_float2(c10, c11);
                }
            }
        }
    }
}

// ---------------- hyperedge aggregation in feat_v space ----------------
// aggd[e] = (sum_i vrw[s_i] * feat_v[s_i]) / ers[e] (fp16); swd[e] = (sum vrw)/ers[e]
__global__ __launch_bounds__(256) void edge_agg_kernel(
    const float* __restrict__ vrw, const float* __restrict__ ers) {
    int e = blockIdx.x;
    int t = threadIdx.x;
    int beg = g_ebeg[e], end = beg + g_ecnt[e];
    float acc = 0.f, sw = 0.f;
    for (int i = beg; i < end; i++) {
        int s = g_elist[i];
        float w = vrw[s];
        sw += w;
        float fv = __half2float(g_ch[(size_t)s * 320 + t]) + __half2float(g_cl[(size_t)s * 320 + t]);
        acc += w * fv;
    }
    float inv = 1.f / ers[e];
    g_aggd[(size_t)e * 256 + t] = __float2half_rn(acc * inv);
    if (t == 0) g_swd[e] = sw * inv;
}

// ---------------- per-vertex attention: single-pass online softmax ----------------
__global__ __launch_bounds__(256) void attn_kernel(float* __restrict__ out_fv) {
    int gw = (blockIdx.x * blockDim.x + threadIdx.x) >> 5;
    int lane = threadIdx.x & 31;
    if (gw >= Nc) return;
    int n = gw;
    int beg = g_vbeg[n], end = beg + g_vcnt[n];
    float q0 = __half2float(g_ch[(size_t)n * 320 + 256 + lane]) + __half2float(g_cl[(size_t)n * 320 + 256 + lane]);
    float q1 = __half2float(g_ch[(size_t)n * 320 + 288 + lane]) + __half2float(g_cl[(size_t)n * 320 + 288 + lane]);
    const float scale = 0.125f;

    float m = -1e30f;
    float denom = 0.f;
    float4 a0 = make_float4(0.f, 0.f, 0.f, 0.f);
    float4 a1 = make_float4(0.f, 0.f, 0.f, 0.f);
    for (int i = beg; i < end; i++) {
        int e = g_vlist[i];
        const float* kv = g_efused + (size_t)e * 320;
        float s = q0 * kv[lane] + q1 * kv[32 + lane];
#pragma unroll
        for (int o = 16; o; o >>= 1) s += __shfl_xor_sync(0xffffffffu, s, o);
        s = (s > 0.f ? s : 0.01f * s) * scale;
        float mnew = fmaxf(m, s);
        float corr = __expf(m - mnew);
        float p = __expf(s - mnew);
        m = mnew;
        denom = denom * corr + p;
        const float4* vp = (const float4*)(kv + 64);
        float4 v0 = vp[lane];
        float4 v1 = vp[32 + lane];
        a0.x = a0.x * corr + p * v0.x; a0.y = a0.y * corr + p * v0.y;
        a0.z = a0.z * corr + p * v0.z; a0.w = a0.w * corr + p * v0.w;
        a1.x = a1.x * corr + p * v1.x; a1.y = a1.y * corr + p * v1.y;
        a1.z = a1.z * corr + p * v1.z; a1.w = a1.w * corr + p * v1.w;
    }
    float inv = 1.f / fmaxf(denom, 1e-20f);
    a0.x *= inv; a0.y *= inv; a0.z *= inv; a0.w *= inv;
    a1.x *= inv; a1.y *= inv; a1.z *= inv; a1.w *= inv;
    float4* op = (float4*)(out_fv + (size_t)n * 256);
    op[lane] = a0;
    op[32 + lane] = a1;
}

// ---------------- classification head ----------------
__global__ __launch_bounds__(256) void pred_kernel(
    const float* __restrict__ fv, const float* __restrict__ Wc,
    const float* __restrict__ bc, float* __restrict__ pred) {
    __shared__ float sW[10 * 256];
    __shared__ float sb_[10];
    int t = threadIdx.x;
    for (int i = t; i < 2560; i += 256) sW[i] = Wc[i];
    if (t < 10) sb_[t] = bc[t];
    __syncthreads();
    int warp = t >> 5, lane = t & 31;
    int r = blockIdx.x * 8 + warp;
    if (r >= Nc) return;
    float acc[10];
#pragma unroll
    for (int c = 0; c < 10; c++) acc[c] = 0.f;
    for (int kk = lane; kk < 256; kk += 32) {
        float x = fv[(size_t)r * 256 + kk];
#pragma unroll
        for (int c = 0; c < 10; c++) acc[c] += x * sW[c * 256 + kk];
    }
#pragma unroll
    for (int c = 0; c < 10; c++) {
#pragma unroll
        for (int o = 16; o; o >>= 1) acc[c] += __shfl_xor_sync(0xffffffffu, acc[c], o);
    }
    if (lane == 0) {
#pragma unroll
        for (int c = 0; c < 10; c++) pred[(size_t)r * 10 + c] = acc[c] + sb_[c];
    }
}

// ---------------- launch ----------------
extern "C" void kernel_launch(void* const* d_in, const int* in_sizes, int n_in,
                              void* d_out, int out_size) {
    const float* vfeat = (const float*)d_in[0];
    const float* vrw = (const float*)d_in[2];
    const float* ers = (const float*)d_in[5];
    const float* W1 = (const float*)d_in[6];
    const float* b1 = (const float*)d_in[7];
    const float* Wve = (const float*)d_in[8];
    const float* bve = (const float*)d_in[9];
    const float* Wqv = (const float*)d_in[10];
    const float* bqv = (const float*)d_in[11];
    const float* Wke = (const float*)d_in[12];
    const float* bke = (const float*)d_in[13];
    const float* Wvale = (const float*)d_in[14];
    const float* bvale = (const float*)d_in[15];
    const float* Wcls = (const float*)d_in[16];
    const float* bcls = (const float*)d_in[17];
    const int* in_src = (const int*)d_in[18];
    const int* in_dst = (const int*)d_in[19];

    float* out = (float*)d_out;
    float* out_fv = out;
    float* out_fe = out + (size_t)Nc * 256;
    float* out_pred = out_fe + (size_t)Ec * 256;

    __half *p_vf16, *p_ch, *p_cl, *p_aggd, *p_wNh, *p_wNl, *p_wEh, *p_wEl;
    float *p_wq1, *p_wk2, *p_wv2, *p_bN, *p_cb1, *p_cb2, *p_swd, *p_ef;
    cudaGetSymbolAddress((void**)&p_vf16, g_vf16);
    cudaGetSymbolAddress((void**)&p_ch, g_ch);
    cudaGetSymbolAddress((void**)&p_cl, g_cl);
    cudaGetSymbolAddress((void**)&p_aggd, g_aggd);
    cudaGetSymbolAddress((void**)&p_wNh, g_wNh);
    cudaGetSymbolAddress((void**)&p_wNl, g_wNl);
    cudaGetSymbolAddress((void**)&p_wEh, g_wEh);
    cudaGetSymbolAddress((void**)&p_wEl, g_wEl);
    cudaGetSymbolAddress((void**)&p_wq1, g_wq1);
    cudaGetSymbolAddress((void**)&p_wk2, g_wk2);
    cudaGetSymbolAddress((void**)&p_wv2, g_wv2);
    cudaGetSymbolAddress((void**)&p_bN, g_bN);
    cudaGetSymbolAddress((void**)&p_cb1, g_cb1);
    cudaGetSymbolAddress((void**)&p_cb2, g_cb2);
    cudaGetSymbolAddress((void**)&p_swd, g_swd);
    cudaGetSymbolAddress((void**)&p_ef, g_efused);

    // CSR build
    zero_cnts_kernel<<<(Nc + 255) / 256, 256>>>();
    hist_kernel<<<(Mc + 255) / 256, 256>>>(in_src, in_dst);
    assign_off_kernel<<<(Nc + 255) / 256, 256>>>();
    scatter_kernel<<<(Mc + 255) / 256, 256>>>(in_src, in_dst);

    // weight composition + splits (tiny)
    compose_w<<<384, 256>>>(Wqv, W1, Wke, Wve, Wvale);
    compose_b<<<48, 256>>>(Wqv, b1, bqv, Wke, Wvale, bve, bke, bvale);
    split_hl<<<(256 * 64 + 255) / 256, 256>>>((const float4*)W1, p_wNh, p_wNl, 256 * 64);
    split_hl<<<(64 * 64 + 255) / 256, 256>>>((const float4*)p_wq1, p_wNh + 256 * 256, p_wNl + 256 * 256, 64 * 64);
    split_hl<<<(256 * 64 + 255) / 256, 256>>>((const float4*)Wve, p_wEh, p_wEl, 256 * 64);
    split_hl<<<(64 * 64 + 255) / 256, 256>>>((const float4*)p_wk2, p_wEh + 256 * 256, p_wEl + 256 * 256, 64 * 64);
    split_hl<<<(256 * 64 + 255) / 256, 256>>>((const float4*)p_wv2, p_wEh + 320 * 256, p_wEl + 320 * 256, 256 * 64);
    // activations: vfeat -> fp16
    conv_h<<<(Nc * 64 + 255) / 256, 256>>>((const float4*)vfeat, p_vf16, Nc * 64);

    const int gN = (Nc + 127) / 128;  // 391
    const int gE = (Ec + 127) / 128;  // 196
    const int SMEM = 2 * (5120 + 80 * 64) * 2;  // 40960 B

    // GEMM-N: [feat_v | q] = vfeat @ [W1; Wqv@W1]^T + [b1; Wqv@b1+bqv]  -> fp16 hi/lo
    gemm_f16<64, 320, 0><<<dim3(gN, 5), 256, SMEM>>>(
        p_vf16, p_wNh, p_wNl, p_bN, nullptr, nullptr, nullptr,
        p_ch, p_cl, nullptr, nullptr, Nc);
    // edge aggregation in feat_v space
    edge_agg_kernel<<<Ec, 256>>>(vrw, ers);
    // GEMM-E: [feat_e | k | v] = aggd @ [Wve; WkeWve; WvaleWve]^T + swd*cb1 + cb2
    gemm_f16<64, 576, 1><<<dim3(gE, 9), 256, SMEM>>>(
        p_aggd, p_wEh, p_wEl, nullptr, p_cb1, p_cb2, p_swd,
        nullptr, nullptr, out_fe, p_ef, Ec);
    // attention -> out_fv
    attn_kernel<<<(Nc + 7) / 8, 256>>>(out_fv);
    // pred
    pred_kernel<<<(Nc + 7) / 8, 256>>>(out_fv, Wcls, bcls, out_pred);
}

// round 8
// speedup vs baseline: 2.5937x; 1.0726x over previous
#include <cuda_runtime.h>
#include <cuda_fp16.h>
#include <math.h>
#include <stdint.h>

#define Nc 50000
#define Ec 25000
#define Mc 300000
// dims: INPUT=VERTEX=EDGE=256, QUERY=64, NUM_CLASS=10

// ---------------- scratch ----------------
__device__ __half g_vf16[(size_t)Nc * 256];                     // vfeat fp16
__device__ __half g_ch[(size_t)Nc * 320];                       // [feat_v|q] hi
__device__ __half g_qlo[(size_t)Nc * 64];                       // q lo correction
__device__ __half g_aggd[(size_t)Ec * 256];                     // aggregated feat_v per edge
__device__ float g_swd[Ec];
__device__ __half g_ef16[(size_t)Ec * 320];                     // cols 0-63 k, 64-319 v (fp16)
// composed weights (fp32 tmp) + fp16 hi/lo fused weight banks
__device__ float g_wq1[64 * 256], g_wk2[64 * 256], g_wv2[256 * 256];
__device__ __half g_wNh[320 * 256], g_wNl[320 * 256];           // [W1; Wqv@W1]
__device__ __half g_wEh[576 * 256], g_wEl[576 * 256];           // [Wve; Wke@Wve; Wvale@Wve]
__device__ float g_bN[320];                                      // [b1; Wqv@b1+bqv]
__device__ float g_cb1[576];                                     // [bve; Wke@bve; Wvale@bve]
__device__ float g_cb2[576];                                     // [0; bke; bvale]
// CSR
__device__ int g_ebeg[Ec], g_vbeg[Nc], g_ecnt[Ec], g_vcnt[Nc];
__device__ int g_ecur[Ec], g_vcur[Nc];
__device__ int g_tote, g_totn;
__device__ int g_elist[Mc], g_vlist[Mc];

// ---------------- CSR build ----------------
__global__ void zero_cnts_kernel() {
    int i = blockIdx.x * blockDim.x + threadIdx.x;
    if (i < Ec) g_ecnt[i] = 0;
    if (i < Nc) g_vcnt[i] = 0;
    if (i == 0) { g_tote = 0; g_totn = 0; }
}

__global__ void hist_kernel(const int* __restrict__ in_src, const int* __restrict__ in_dst) {
    int m = blockIdx.x * blockDim.x + threadIdx.x;
    if (m >= Mc) return;
    atomicAdd(&g_ecnt[in_dst[m]], 1);
    atomicAdd(&g_vcnt[in_src[m]], 1);
}

__global__ void assign_off_kernel() {
    int i = blockIdx.x * blockDim.x + threadIdx.x;
    int lane = threadIdx.x & 31;
    {
        int c = (i < Ec) ? g_ecnt[i] : 0;
        int x = c;
#pragma unroll
        for (int o = 1; o < 32; o <<= 1) {
            int y = __shfl_up_sync(0xffffffffu, x, o);
            if (lane >= o) x += y;
        }
        int wsum = __shfl_sync(0xffffffffu, x, 31);
        int base = 0;
        if (lane == 31 && wsum > 0) base = atomicAdd(&g_tote, wsum);
        base = __shfl_sync(0xffffffffu, base, 31);
        if (i < Ec) { int b = base + x - c; g_ebeg[i] = b; g_ecur[i] = b; }
    }
    {
        int c = (i < Nc) ? g_vcnt[i] : 0;
        int x = c;
#pragma unroll
        for (int o = 1; o < 32; o <<= 1) {
            int y = __shfl_up_sync(0xffffffffu, x, o);
            if (lane >= o) x += y;
        }
        int wsum = __shfl_sync(0xffffffffu, x, 31);
        int base = 0;
        if (lane == 31 && wsum > 0) base = atomicAdd(&g_totn, wsum);
        base = __shfl_sync(0xffffffffu, base, 31);
        if (i < Nc) { int b = base + x - c; g_vbeg[i] = b; g_vcur[i] = b; }
    }
}

__global__ void scatter_kernel(const int* __restrict__ in_src, const int* __restrict__ in_dst) {
    int m = blockIdx.x * blockDim.x + threadIdx.x;
    if (m >= Mc) return;
    int s = in_src[m];
    int e = in_dst[m];
    int pe = atomicAdd(&g_ecur[e], 1);
    g_elist[pe] = s;
    int pv = atomicAdd(&g_vcur[s], 1);
    g_vlist[pv] = e;
}

// ---------------- weight composition (exact fp32 algebra) ----------------
__global__ void compose_w(const float* __restrict__ Wqv, const float* __restrict__ W1,
                          const float* __restrict__ Wke, const float* __restrict__ Wve,
                          const float* __restrict__ Wvale) {
    int r = blockIdx.x, j = threadIdx.x;
    const float* A; const float* B; float* C; int rr;
    if (r < 64) { A = Wqv; B = W1; C = g_wq1; rr = r; }
    else if (r < 128) { A = Wke; B = Wve; C = g_wk2; rr = r - 64; }
    else { A = Wvale; B = Wve; C = g_wv2; rr = r - 128; }
    float acc = 0.f;
    for (int k = 0; k < 256; k++) acc += A[rr * 256 + k] * B[k * 256 + j];
    C[rr * 256 + j] = acc;
}

__global__ void compose_b(const float* __restrict__ Wqv, const float* __restrict__ b1,
                          const float* __restrict__ bqv, const float* __restrict__ Wke,
                          const float* __restrict__ Wvale, const float* __restrict__ bve,
                          const float* __restrict__ bke, const float* __restrict__ bvale) {
    int t = blockIdx.x * blockDim.x + threadIdx.x;
    int gw = t >> 5, lane = t & 31;
    if (gw < 384) {
        const float* M; const float* v; int i; float add = 0.f; float* dst;
        if (gw < 64) { M = Wqv; v = b1; i = gw; add = bqv[i]; dst = &g_bN[256 + i]; }
        else if (gw < 128) { M = Wke; v = bve; i = gw - 64; dst = &g_cb1[256 + i]; }
        else { M = Wvale; v = bve; i = gw - 128; dst = &g_cb1[320 + i]; }
        float s = 0.f;
        for (int k = lane; k < 256; k += 32) s += M[i * 256 + k] * v[k];
#pragma unroll
        for (int o = 16; o; o >>= 1) s += __shfl_xor_sync(0xffffffffu, s, o);
        if (lane == 0) *dst = s + add;
    }
    if (t < 256) { g_bN[t] = b1[t]; g_cb1[t] = bve[t]; g_cb2[t] = 0.f; }
    else if (t < 320) g_cb2[t] = bke[t - 256];
    else if (t < 576) g_cb2[t] = bvale[t - 320];
}

// ---------------- fp32 -> fp16 conversions ----------------
__global__ void split_hl(const float4* __restrict__ src, __half* __restrict__ hi,
                         __half* __restrict__ lo, int n4) {
    int i = blockIdx.x * blockDim.x + threadIdx.x;
    if (i >= n4) return;
    float4 v = src[i];
    __half h0 = __float2half_rn(v.x), h1 = __float2half_rn(v.y);
    __half h2 = __float2half_rn(v.z), h3 = __float2half_rn(v.w);
    __half l0 = __float2half_rn(v.x - __half2float(h0));
    __half l1 = __float2half_rn(v.y - __half2float(h1));
    __half l2 = __float2half_rn(v.z - __half2float(h2));
    __half l3 = __float2half_rn(v.w - __half2float(h3));
    uint2 H, L;
    H.x = ((uint32_t)__half_as_ushort(h1) << 16) | __half_as_ushort(h0);
    H.y = ((uint32_t)__half_as_ushort(h3) << 16) | __half_as_ushort(h2);
    L.x = ((uint32_t)__half_as_ushort(l1) << 16) | __half_as_ushort(l0);
    L.y = ((uint32_t)__half_as_ushort(l3) << 16) | __half_as_ushort(l2);
    *(uint2*)(hi + (size_t)i * 4) = H;
    *(uint2*)(lo + (size_t)i * 4) = L;
}

__global__ void conv_h(const float4* __restrict__ src, __half* __restrict__ dst, int n4) {
    int i = blockIdx.x * blockDim.x + threadIdx.x;
    if (i >= n4) return;
    float4 v = src[i];
    uint2 H;
    H.x = ((uint32_t)__half_as_ushort(__float2half_rn(v.y)) << 16) | __half_as_ushort(__float2half_rn(v.x));
    H.y = ((uint32_t)__half_as_ushort(__float2half_rn(v.w)) << 16) | __half_as_ushort(__float2half_rn(v.z));
    *(uint2*)(dst + (size_t)i * 4) = H;
}

// ---------------- MMA helpers ----------------
__device__ __forceinline__ void mma16816h(float* d, const uint32_t* a, uint32_t b0, uint32_t b1) {
    asm volatile(
        "mma.sync.aligned.m16n8k16.row.col.f32.f16.f16.f32 "
        "{%0,%1,%2,%3},{%4,%5,%6,%7},{%8,%9},{%0,%1,%2,%3};"
        : "+f"(d[0]), "+f"(d[1]), "+f"(d[2]), "+f"(d[3])
        : "r"(a[0]), "r"(a[1]), "r"(a[2]), "r"(a[3]), "r"(b0), "r"(b1));
}

__device__ __forceinline__ void ldsm_x4(uint32_t* r, uint32_t addr) {
    asm volatile("ldmatrix.sync.aligned.m8n8.x4.shared.b16 {%0,%1,%2,%3}, [%4];"
                 : "=r"(r[0]), "=r"(r[1]), "=r"(r[2]), "=r"(r[3]) : "r"(addr));
}

__device__ __forceinline__ uint32_t smem_u32(const void* p) {
    uint32_t a;
    asm("{ .reg .u64 t; cvta.to.shared.u64 t, %1; cvt.u32.u64 %0, t; }" : "=r"(a) : "l"(p));
    return a;
}

__device__ __forceinline__ void cp_async16(uint32_t dst, const void* src, int src_bytes) {
    asm volatile("cp.async.cg.shared.global [%0], [%1], 16, %2;"
                 :: "r"(dst), "l"(src), "r"(src_bytes) : "memory");
}
#define CP_COMMIT() asm volatile("cp.async.commit_group;" ::: "memory")
#define CP_WAIT(n) asm volatile("cp.async.wait_group %0;" :: "n"(n) : "memory")

// ---------------- fp16x2 GEMM: C[M,NOUT] = A[M,256] @ W^T (+epilogue) ----------------
// MODE 0 (GEMM-N): cols all -> chi fp16 [M,320]; cols>=256 also lo correction -> qlo [M,64]
// MODE 1 (GEMM-E): cols<256 -> fp32 outA[M,256] (feat_e); cols>=256 -> fp16 ef16[M,320]
//                  epilogue adds swd[m]*cb1[n] + cb2[n]
template <int BN, int NOUT, int MODE>
__global__ __launch_bounds__(256) void gemm_f16(
    const __half* __restrict__ A,
    const __half* __restrict__ whi, const __half* __restrict__ wlo,
    const float* __restrict__ bias,
    const float* __restrict__ cb1, const float* __restrict__ cb2,
    const float* __restrict__ swd,
    __half* __restrict__ chi, __half* __restrict__ qlo,
    float* __restrict__ outA, __half* __restrict__ ef16,
    int Mrows) {
    constexpr int WN = BN / 2;
    constexpr int NF = WN / 8;
    constexpr int Ao = 0;
    constexpr int Bho = 5120;
    constexpr int Blo_ = 5120 + 40 * BN;
    constexpr int STG = 5120 + 80 * BN;  // halfs per stage
    extern __shared__ __half sm[];
    const uint32_t smb = smem_u32(sm);

    int tid = threadIdx.x;
    int lane = tid & 31, wid = tid >> 5;
    int wm = wid & 3, wn = wid >> 2;
    int qr = lane >> 2, qc = (lane & 3) * 2;
    int bm = blockIdx.x * 128, bn = blockIdx.y * BN;

    int a_row = wm * 32 + (lane & 7) + ((lane >> 3) & 1) * 8;
    int a_col = ((lane >> 4) & 1) * 8;
    int b_col = ((lane >> 3) & 1) * 8;
    int b_rowl = (lane & 7) + ((lane >> 4) & 1) * 8;

    float acc[2][NF][4];
#pragma unroll
    for (int mf = 0; mf < 2; mf++)
#pragma unroll
        for (int nf = 0; nf < NF; nf++)
#pragma unroll
            for (int j = 0; j < 4; j++) acc[mf][nf][j] = 0.f;

    auto load_chunk = [&](int ck, int stage) {
        uint32_t base = smb + (uint32_t)stage * (STG * 2);
#pragma unroll
        for (int i = 0; i < 2; i++) {
            int f = tid + i * 256;
            int row = f >> 2, sg = f & 3;
            int ok = (bm + row < Mrows) ? 16 : 0;
            cp_async16(base + (Ao + row * 40 + sg * 8) * 2,
                       A + (size_t)(bm + row) * 256 + ck * 32 + sg * 8, ok);
        }
        {
            int row = tid >> 2, sg = tid & 3;
            size_t goff = (size_t)(bn + row) * 256 + ck * 32 + sg * 8;
            cp_async16(base + (Bho + row * 40 + sg * 8) * 2, whi + goff, 16);
            cp_async16(base + (Blo_ + row * 40 + sg * 8) * 2, wlo + goff, 16);
        }
    };

    load_chunk(0, 0);
    CP_COMMIT();

    for (int c = 0; c < 8; c++) {
        if (c < 7) {
            load_chunk(c + 1, (c + 1) & 1);
            CP_COMMIT();
            CP_WAIT(1);
        } else {
            CP_WAIT(0);
        }
        __syncthreads();
        uint32_t base = smb + (uint32_t)(c & 1) * (STG * 2);
#pragma unroll
        for (int ks = 0; ks < 32; ks += 16) {
            uint32_t ah[2][4];
#pragma unroll
            for (int mf = 0; mf < 2; mf++) {
                uint32_t off = ((a_row + mf * 16) * 40 + a_col + ks) * 2;
                ldsm_x4(ah[mf], base + Ao * 2 + off);
            }
            uint32_t bh[NF][2], bl[NF][2];
#pragma unroll
            for (int np = 0; np < NF / 2; np++) {
                uint32_t off = ((wn * WN + np * 16 + b_rowl) * 40 + b_col + ks) * 2;
                uint32_t t[4];
                ldsm_x4(t, base + Bho * 2 + off);
                bh[2 * np][0] = t[0]; bh[2 * np][1] = t[1];
                bh[2 * np + 1][0] = t[2]; bh[2 * np + 1][1] = t[3];
                ldsm_x4(t, base + Blo_ * 2 + off);
                bl[2 * np][0] = t[0]; bl[2 * np][1] = t[1];
                bl[2 * np + 1][0] = t[2]; bl[2 * np + 1][1] = t[3];
            }
#pragma unroll
            for (int nf = 0; nf < NF; nf++) {
#pragma unroll
                for (int mf = 0; mf < 2; mf++) {
                    mma16816h(acc[mf][nf], ah[mf], bh[nf][0], bh[nf][1]);
                    mma16816h(acc[mf][nf], ah[mf], bl[nf][0], bl[nf][1]);
                }
            }
        }
        __syncthreads();
    }

    // epilogue
#pragma unroll
    for (int mf = 0; mf < 2; mf++) {
#pragma unroll
        for (int nf = 0; nf < NF; nf++) {
            int m0 = bm + wm * 32 + mf * 16 + qr;
            int n0 = bn + wn * WN + nf * 8 + qc;
            if (MODE == 0) {
                float bv0 = bias[n0], bv1 = bias[n0 + 1];
#pragma unroll
                for (int half_ = 0; half_ < 2; half_++) {
                    int m = m0 + half_ * 8;
                    if (m >= Mrows) continue;
                    float c0 = acc[mf][nf][half_ * 2 + 0] + bv0;
                    float c1 = acc[mf][nf][half_ * 2 + 1] + bv1;
                    __half h0 = __float2half_rn(c0), h1 = __float2half_rn(c1);
                    uint32_t ph = ((uint32_t)__half_as_ushort(h1) << 16) | __half_as_ushort(h0);
                    *(uint32_t*)(chi + (size_t)m * NOUT + n0) = ph;
                    if (n0 >= 256) {
                        uint32_t pl = ((uint32_t)__half_as_ushort(__float2half_rn(c1 - __half2float(h1))) << 16) |
                                      __half_as_ushort(__float2half_rn(c0 - __half2float(h0)));
                        *(uint32_t*)(qlo + (size_t)m * 64 + n0 - 256) = pl;
                    }
                }
            } else {
                float e0 = cb1[n0], e1 = cb1[n0 + 1];
                float f0 = cb2[n0], f1 = cb2[n0 + 1];
#pragma unroll
                for (int half_ = 0; half_ < 2; half_++) {
                    int m = m0 + half_ * 8;
                    if (m >= Mrows) continue;
                    float sw = swd[m];
                    float c0 = acc[mf][nf][half_ * 2 + 0] + sw * e0 + f0;
                    float c1 = acc[mf][nf][half_ * 2 + 1] + sw * e1 + f1;
                    if (n0 < 256) {
                        *(float2*)(outA + (size_t)m * 256 + n0) = make_float2(c0, c1);
                    } else {
                        uint32_t ph = ((uint32_t)__half_as_ushort(__float2half_rn(c1)) << 16) |
                                      __half_as_ushort(__float2half_rn(c0));
                        *(uint32_t*)(ef16 + (size_t)m * 320 + n0 - 256) = ph;
                    }
                }
            }
        }
    }
}

// ---------------- hyperedge aggregation (hi-only fp16 feat_v) ----------------
__global__ __launch_bounds__(256) void edge_agg_kernel(
    const float* __restrict__ vrw, const float* __restrict__ ers) {
    int e = blockIdx.x;
    int t = threadIdx.x;
    int beg = g_ebeg[e], end = beg + g_ecnt[e];
    float acc = 0.f, sw = 0.f;
    for (int i = beg; i < end; i++) {
        int s = g_elist[i];
        float w = vrw[s];
        sw += w;
        acc += w * __half2float(g_ch[(size_t)s * 320 + t]);
    }
    float inv = 1.f / ers[e];
    g_aggd[(size_t)e * 256 + t] = __float2half_rn(acc * inv);
    if (t == 0) g_swd[e] = sw * inv;
}

// ---------------- per-vertex attention: online softmax, fp16 kv ----------------
__global__ __launch_bounds__(256) void attn_kernel(float* __restrict__ out_fv) {
    int gw = (blockIdx.x * blockDim.x + threadIdx.x) >> 5;
    int lane = threadIdx.x & 31;
    if (gw >= Nc) return;
    int n = gw;
    int beg = g_vbeg[n], end = beg + g_vcnt[n];
    float q0 = __half2float(g_ch[(size_t)n * 320 + 256 + lane]) + __half2float(g_qlo[(size_t)n * 64 + lane]);
    float q1 = __half2float(g_ch[(size_t)n * 320 + 288 + lane]) + __half2float(g_qlo[(size_t)n * 64 + 32 + lane]);
    const float scale = 0.125f;

    float m = -1e30f, denom = 0.f;
    float acc[8];
#pragma unroll
    for (int j = 0; j < 8; j++) acc[j] = 0.f;

    for (int i = beg; i < end; i++) {
        int e = g_vlist[i];
        const __half* kv = g_ef16 + (size_t)e * 320;
        float s = q0 * __half2float(kv[lane]) + q1 * __half2float(kv[32 + lane]);
#pragma unroll
        for (int o = 16; o; o >>= 1) s += __shfl_xor_sync(0xffffffffu, s, o);
        s = (s > 0.f ? s : 0.01f * s) * scale;
        float mnew = fmaxf(m, s);
        float corr = __expf(m - mnew);
        float p = __expf(s - mnew);
        m = mnew;
        denom = denom * corr + p;
        // v: 8 contiguous halfs per lane at col 64 + lane*8
        uint4 raw = *(const uint4*)(kv + 64 + lane * 8);
        float2 f0 = __half22float2(*(__half2*)&raw.x);
        float2 f1 = __half22float2(*(__half2*)&raw.y);
        float2 f2 = __half22float2(*(__half2*)&raw.z);
        float2 f3 = __half22float2(*(__half2*)&raw.w);
        acc[0] = acc[0] * corr + p * f0.x; acc[1] = acc[1] * corr + p * f0.y;
        acc[2] = acc[2] * corr + p * f1.x; acc[3] = acc[3] * corr + p * f1.y;
        acc[4] = acc[4] * corr + p * f2.x; acc[5] = acc[5] * corr + p * f2.y;
        acc[6] = acc[6] * corr + p * f3.x; acc[7] = acc[7] * corr + p * f3.y;
    }
    float inv = 1.f / fmaxf(denom, 1e-20f);
#pragma unroll
    for (int j = 0; j < 8; j++) acc[j] *= inv;
    float4* op = (float4*)(out_fv + (size_t)n * 256 + lane * 8);
    op[0] = make_float4(acc[0], acc[1], acc[2], acc[3]);
    op[1] = make_float4(acc[4], acc[5], acc[6], acc[7]);
}

// ---------------- classification head ----------------
__global__ __launch_bounds__(256) void pred_kernel(
    const float* __restrict__ fv, const float* __restrict__ Wc,
    const float* __restrict__ bc, float* __restrict__ pred) {
    __shared__ float sW[10 * 256];
    __shared__ float sb_[10];
    int t = threadIdx.x;
    for (int i = t; i < 2560; i += 256) sW[i] = Wc[i];
    if (t < 10) sb_[t] = bc[t];
    __syncthreads();
    int warp = t >> 5, lane = t & 31;
    int r = blockIdx.x * 8 + warp;
    if (r >= Nc) return;
    float acc[10];
#pragma unroll
    for (int c = 0; c < 10; c++) acc[c] = 0.f;
    for (int kk = lane; kk < 256; kk += 32) {
        float x = fv[(size_t)r * 256 + kk];
#pragma unroll
        for (int c = 0; c < 10; c++) acc[c] += x * sW[c * 256 + kk];
    }
#pragma unroll
    for (int c = 0; c < 10; c++) {
#pragma unroll
        for (int o = 16; o; o >>= 1) acc[c] += __shfl_xor_sync(0xffffffffu, acc[c], o);
    }
    if (lane == 0) {
#pragma unroll
        for (int c = 0; c < 10; c++) pred[(size_t)r * 10 + c] = acc[c] + sb_[c];
    }
}

// ---------------- launch ----------------
extern "C" void kernel_launch(void* const* d_in, const int* in_sizes, int n_in,
                              void* d_out, int out_size) {
    const float* vfeat = (const float*)d_in[0];
    const float* vrw = (const float*)d_in[2];
    const float* ers = (const float*)d_in[5];
    const float* W1 = (const float*)d_in[6];
    const float* b1 = (const float*)d_in[7];
    const float* Wve = (const float*)d_in[8];
    const float* bve = (const float*)d_in[9];
    const float* Wqv = (const float*)d_in[10];
    const float* bqv = (const float*)d_in[11];
    const float* Wke = (const float*)d_in[12];
    const float* bke = (const float*)d_in[13];
    const float* Wvale = (const float*)d_in[14];
    const float* bvale = (const float*)d_in[15];
    const float* Wcls = (const float*)d_in[16];
    const float* bcls = (const float*)d_in[17];
    const int* in_src = (const int*)d_in[18];
    const int* in_dst = (const int*)d_in[19];

    float* out = (float*)d_out;
    float* out_fv = out;
    float* out_fe = out + (size_t)Nc * 256;
    float* out_pred = out_fe + (size_t)Ec * 256;

    __half *p_vf16, *p_ch, *p_qlo, *p_aggd, *p_wNh, *p_wNl, *p_wEh, *p_wEl, *p_ef16;
    float *p_wq1, *p_wk2, *p_wv2, *p_bN, *p_cb1, *p_cb2, *p_swd;
    cudaGetSymbolAddress((void**)&p_vf16, g_vf16);
    cudaGetSymbolAddress((void**)&p_ch, g_ch);
    cudaGetSymbolAddress((void**)&p_qlo, g_qlo);
    cudaGetSymbolAddress((void**)&p_aggd, g_aggd);
    cudaGetSymbolAddress((void**)&p_wNh, g_wNh);
    cudaGetSymbolAddress((void**)&p_wNl, g_wNl);
    cudaGetSymbolAddress((void**)&p_wEh, g_wEh);
    cudaGetSymbolAddress((void**)&p_wEl, g_wEl);
    cudaGetSymbolAddress((void**)&p_ef16, g_ef16);
    cudaGetSymbolAddress((void**)&p_wq1, g_wq1);
    cudaGetSymbolAddress((void**)&p_wk2, g_wk2);
    cudaGetSymbolAddress((void**)&p_wv2, g_wv2);
    cudaGetSymbolAddress((void**)&p_bN, g_bN);
    cudaGetSymbolAddress((void**)&p_cb1, g_cb1);
    cudaGetSymbolAddress((void**)&p_cb2, g_cb2);
    cudaGetSymbolAddress((void**)&p_swd, g_swd);

    // fork/join resources (one-time resource init; no device memory alloc)
    static cudaStream_t s2 = 0;
    static cudaEvent_t ev_fork = 0, ev_csr = 0;
    static int stream_ok = -1;
    if (stream_ok < 0) {
        cudaError_t e1 = cudaStreamCreateWithFlags(&s2, cudaStreamNonBlocking);
        cudaError_t e2 = cudaEventCreateWithFlags(&ev_fork, cudaEventDisableTiming);
        cudaError_t e3 = cudaEventCreateWithFlags(&ev_csr, cudaEventDisableTiming);
        stream_ok = (e1 == cudaSuccess && e2 == cudaSuccess && e3 == cudaSuccess) ? 1 : 0;
    }
    cudaStream_t sb = stream_ok ? s2 : 0;

    if (stream_ok) {
        cudaEventRecord(ev_fork, 0);
        cudaStreamWaitEvent(s2, ev_fork, 0);
    }
    // stream B: CSR build (independent of conv/GEMM-N)
    zero_cnts_kernel<<<(Nc + 255) / 256, 256, 0, sb>>>();
    hist_kernel<<<(Mc + 255) / 256, 256, 0, sb>>>(in_src, in_dst);
    assign_off_kernel<<<(Nc + 255) / 256, 256, 0, sb>>>();
    scatter_kernel<<<(Mc + 255) / 256, 256, 0, sb>>>(in_src, in_dst);
    if (stream_ok) cudaEventRecord(ev_csr, s2);

    // main stream: weight composition + conversions + GEMM-N
    compose_w<<<384, 256>>>(Wqv, W1, Wke, Wve, Wvale);
    compose_b<<<48, 256>>>(Wqv, b1, bqv, Wke, Wvale, bve, bke, bvale);
    split_hl<<<(256 * 64 + 255) / 256, 256>>>((const float4*)W1, p_wNh, p_wNl, 256 * 64);
    split_hl<<<(64 * 64 + 255) / 256, 256>>>((const float4*)p_wq1, p_wNh + 256 * 256, p_wNl + 256 * 256, 64 * 64);
    split_hl<<<(256 * 64 + 255) / 256, 256>>>((const float4*)Wve, p_wEh, p_wEl, 256 * 64);
    split_hl<<<(64 * 64 + 255) / 256, 256>>>((const float4*)p_wk2, p_wEh + 256 * 256, p_wEl + 256 * 256, 64 * 64);
    split_hl<<<(256 * 64 + 255) / 256, 256>>>((const float4*)p_wv2, p_wEh + 320 * 256, p_wEl + 320 * 256, 256 * 64);
    conv_h<<<(Nc * 64 + 255) / 256, 256>>>((const float4*)vfeat, p_vf16, Nc * 64);

    const int gN = (Nc + 127) / 128;  // 391
    const int gE = (Ec + 127) / 128;  // 196
    const int SMEM = 2 * (5120 + 80 * 64) * 2;  // 40960 B

    // GEMM-N: [feat_v | q] = vfeat @ [W1; Wqv@W1]^T + bN  -> fp16 (q with lo correction)
    gemm_f16<64, 320, 0><<<dim3(gN, 5), 256, SMEM>>>(
        p_vf16, p_wNh, p_wNl, p_bN, nullptr, nullptr, nullptr,
        p_ch, p_qlo, nullptr, nullptr, Nc);

    // join: edge_agg needs CSR + GEMM-N output
    if (stream_ok) cudaStreamWaitEvent(0, ev_csr, 0);
    edge_agg_kernel<<<Ec, 256>>>(vrw, ers);
    // GEMM-E: [feat_e | k | v] = aggd @ [Wve; WkeWve; WvaleWve]^T + swd*cb1 + cb2
    gemm_f16<64, 576, 1><<<dim3(gE, 9), 256, SMEM>>>(
        p_aggd, p_wEh, p_wEl, nullptr, p_cb1, p_cb2, p_swd,
        nullptr, nullptr, out_fe, p_ef16, Ec);
    // attention -> out_fv
    attn_kernel<<<(Nc + 7) / 8, 256>>>(out_fv);
    // pred
    pred_kernel<<<(Nc + 7) / 8, 256>>>(out_fv, Wcls, bcls, out_pred);
}

// round 9
// speedup vs baseline: 3.1367x; 1.2094x over previous
#include <cuda_runtime.h>
#include <cuda_fp16.h>
#include <math.h>
#include <stdint.h>

#define Nc 50000
#define Ec 25000
#define Mc 300000
// dims: INPUT=VERTEX=EDGE=256, QUERY=64, NUM_CLASS=10

// ---------------- scratch ----------------
__device__ __half g_vf16[(size_t)Nc * 256];      // vfeat fp16
__device__ float g_qf[(size_t)Nc * 64];          // q fp32
__device__ __half g_aggv[(size_t)Ec * 256];      // aggregated raw vfeat per edge (fp16)
__device__ float g_swd[Ec];
__device__ __half g_ef16[(size_t)Ec * 320];      // cols 0-63 k, 64-319 v (fp16)
// composed weights
__device__ float g_wEf[576 * 256];               // [Wve@W1; Wke@Wve@W1; Wvale@Wve@W1] fp32
__device__ float g_wq1[64 * 256];                // Wqv@W1 fp32
__device__ __half g_wEh[576 * 256], g_wEl[576 * 256];
__device__ __half g_wQh[64 * 256], g_wQl[64 * 256];
__device__ float g_bve1[256];                    // Wve@b1 + bve
__device__ float g_qb[64];                       // Wqv@b1 + bqv
__device__ float g_cb1[576];                     // [bve1; Wke@bve1; Wvale@bve1]
__device__ float g_cb2[576];                     // [0; bke; bvale]
// CSR
__device__ int g_ebeg[Ec], g_vbeg[Nc], g_ecnt[Ec], g_vcnt[Nc];
__device__ int g_ecur[Ec], g_vcur[Nc];
__device__ int g_tote, g_totn;
__device__ int g_elist[Mc], g_vlist[Mc];

// ---------------- CSR build ----------------
__global__ void zero_cnts_kernel() {
    int i = blockIdx.x * blockDim.x + threadIdx.x;
    if (i < Ec) g_ecnt[i] = 0;
    if (i < Nc) g_vcnt[i] = 0;
    if (i == 0) { g_tote = 0; g_totn = 0; }
}

__global__ void hist_kernel(const int* __restrict__ in_src, const int* __restrict__ in_dst) {
    int m = blockIdx.x * blockDim.x + threadIdx.x;
    if (m >= Mc) return;
    atomicAdd(&g_ecnt[in_dst[m]], 1);
    atomicAdd(&g_vcnt[in_src[m]], 1);
}

__global__ void assign_off_kernel() {
    int i = blockIdx.x * blockDim.x + threadIdx.x;
    int lane = threadIdx.x & 31;
    {
        int c = (i < Ec) ? g_ecnt[i] : 0;
        int x = c;
#pragma unroll
        for (int o = 1; o < 32; o <<= 1) {
            int y = __shfl_up_sync(0xffffffffu, x, o);
            if (lane >= o) x += y;
        }
        int wsum = __shfl_sync(0xffffffffu, x, 31);
        int base = 0;
        if (lane == 31 && wsum > 0) base = atomicAdd(&g_tote, wsum);
        base = __shfl_sync(0xffffffffu, base, 31);
        if (i < Ec) { int b = base + x - c; g_ebeg[i] = b; g_ecur[i] = b; }
    }
    {
        int c = (i < Nc) ? g_vcnt[i] : 0;
        int x = c;
#pragma unroll
        for (int o = 1; o < 32; o <<= 1) {
            int y = __shfl_up_sync(0xffffffffu, x, o);
            if (lane >= o) x += y;
        }
        int wsum = __shfl_sync(0xffffffffu, x, 31);
        int base = 0;
        if (lane == 31 && wsum > 0) base = atomicAdd(&g_totn, wsum);
        base = __shfl_sync(0xffffffffu, base, 31);
        if (i < Nc) { int b = base + x - c; g_vbeg[i] = b; g_vcur[i] = b; }
    }
}

__global__ void scatter_kernel(const int* __restrict__ in_src, const int* __restrict__ in_dst) {
    int m = blockIdx.x * blockDim.x + threadIdx.x;
    if (m >= Mc) return;
    int s = in_src[m];
    int e = in_dst[m];
    int pe = atomicAdd(&g_ecur[e], 1);
    g_elist[pe] = s;
    int pv = atomicAdd(&g_vcur[s], 1);
    g_vlist[pv] = e;
}

// ---------------- weight composition (exact fp32) ----------------
// stage 1: rows 0-255: Wve@W1 -> g_wEf[0:256]; rows 256-319: Wqv@W1 -> g_wq1
__global__ void compose1(const float* __restrict__ Wve, const float* __restrict__ Wqv,
                         const float* __restrict__ W1) {
    int r = blockIdx.x, j = threadIdx.x;
    const float* A; float* C; int rr;
    if (r < 256) { A = Wve; C = g_wEf; rr = r; }
    else { A = Wqv; C = g_wq1; rr = r - 256; }
    float acc = 0.f;
    for (int k = 0; k < 256; k++) acc += A[rr * 256 + k] * W1[k * 256 + j];
    C[rr * 256 + j] = acc;
}

// stage 2: rows 0-63: Wke@(WveW1) -> g_wEf[256:320]; rows 64-319: Wvale@(WveW1) -> g_wEf[320:576]
__global__ void compose2(const float* __restrict__ Wke, const float* __restrict__ Wvale) {
    int r = blockIdx.x, j = threadIdx.x;
    const float* A; int rr, outrow;
    if (r < 64) { A = Wke; rr = r; outrow = 256 + r; }
    else { A = Wvale; rr = r - 64; outrow = 320 + rr; }
    float acc = 0.f;
    for (int k = 0; k < 256; k++) acc += A[rr * 256 + k] * g_wEf[k * 256 + j];
    g_wEf[outrow * 256 + j] = acc;
}

// bias stage 1: bve1 = Wve@b1 + bve ; qb = Wqv@b1 + bqv   (320 warps)
__global__ void bias1(const float* __restrict__ Wve, const float* __restrict__ b1,
                      const float* __restrict__ bve, const float* __restrict__ Wqv,
                      const float* __restrict__ bqv) {
    int t = blockIdx.x * blockDim.x + threadIdx.x;
    int gw = t >> 5, lane = t & 31;
    if (gw >= 320) return;
    const float* M; int i; float add; float* dst;
    if (gw < 256) { M = Wve; i = gw; add = bve[i]; dst = &g_bve1[i]; }
    else { M = Wqv; i = gw - 256; add = bqv[i]; dst = &g_qb[i]; }
    float s = 0.f;
    for (int k = lane; k < 256; k += 32) s += M[i * 256 + k] * b1[k];
#pragma unroll
    for (int o = 16; o; o >>= 1) s += __shfl_xor_sync(0xffffffffu, s, o);
    if (lane == 0) *dst = s + add;
}

// bias stage 2: cb1 = [bve1; Wke@bve1; Wvale@bve1], cb2 = [0; bke; bvale]
__global__ void bias2(const float* __restrict__ Wke, const float* __restrict__ Wvale,
                      const float* __restrict__ bke, const float* __restrict__ bvale) {
    int t = blockIdx.x * blockDim.x + threadIdx.x;
    int gw = t >> 5, lane = t & 31;
    if (gw < 320) {
        const float* M; int i; float* dst;
        if (gw < 64) { M = Wke; i = gw; dst = &g_cb1[256 + i]; }
        else { M = Wvale; i = gw - 64; dst = &g_cb1[320 + i]; }
        float s = 0.f;
        for (int k = lane; k < 256; k += 32) s += M[i * 256 + k] * g_bve1[k];
#pragma unroll
        for (int o = 16; o; o >>= 1) s += __shfl_xor_sync(0xffffffffu, s, o);
        if (lane == 0) *dst = s;
    }
    if (t < 256) { g_cb1[t] = g_bve1[t]; g_cb2[t] = 0.f; }
    else if (t < 320) g_cb2[t] = bke[t - 256];
    else if (t < 576) g_cb2[t] = bvale[t - 320];
}

// ---------------- fp32 -> fp16 conversions ----------------
__global__ void split_hl(const float4* __restrict__ src, __half* __restrict__ hi,
                         __half* __restrict__ lo, int n4) {
    int i = blockIdx.x * blockDim.x + threadIdx.x;
    if (i >= n4) return;
    float4 v = src[i];
    __half h0 = __float2half_rn(v.x), h1 = __float2half_rn(v.y);
    __half h2 = __float2half_rn(v.z), h3 = __float2half_rn(v.w);
    __half l0 = __float2half_rn(v.x - __half2float(h0));
    __half l1 = __float2half_rn(v.y - __half2float(h1));
    __half l2 = __float2half_rn(v.z - __half2float(h2));
    __half l3 = __float2half_rn(v.w - __half2float(h3));
    uint2 H, L;
    H.x = ((uint32_t)__half_as_ushort(h1) << 16) | __half_as_ushort(h0);
    H.y = ((uint32_t)__half_as_ushort(h3) << 16) | __half_as_ushort(h2);
    L.x = ((uint32_t)__half_as_ushort(l1) << 16) | __half_as_ushort(l0);
    L.y = ((uint32_t)__half_as_ushort(l3) << 16) | __half_as_ushort(l2);
    *(uint2*)(hi + (size_t)i * 4) = H;
    *(uint2*)(lo + (size_t)i * 4) = L;
}

__global__ void conv_h(const float4* __restrict__ src, __half* __restrict__ dst, int n4) {
    int i = blockIdx.x * blockDim.x + threadIdx.x;
    if (i >= n4) return;
    float4 v = src[i];
    uint2 H;
    H.x = ((uint32_t)__half_as_ushort(__float2half_rn(v.y)) << 16) | __half_as_ushort(__float2half_rn(v.x));
    H.y = ((uint32_t)__half_as_ushort(__float2half_rn(v.w)) << 16) | __half_as_ushort(__float2half_rn(v.z));
    *(uint2*)(dst + (size_t)i * 4) = H;
}

// ---------------- MMA helpers ----------------
__device__ __forceinline__ void mma16816h(float* d, const uint32_t* a, uint32_t b0, uint32_t b1) {
    asm volatile(
        "mma.sync.aligned.m16n8k16.row.col.f32.f16.f16.f32 "
        "{%0,%1,%2,%3},{%4,%5,%6,%7},{%8,%9},{%0,%1,%2,%3};"
        : "+f"(d[0]), "+f"(d[1]), "+f"(d[2]), "+f"(d[3])
        : "r"(a[0]), "r"(a[1]), "r"(a[2]), "r"(a[3]), "r"(b0), "r"(b1));
}

__device__ __forceinline__ void ldsm_x4(uint32_t* r, uint32_t addr) {
    asm volatile("ldmatrix.sync.aligned.m8n8.x4.shared.b16 {%0,%1,%2,%3}, [%4];"
                 : "=r"(r[0]), "=r"(r[1]), "=r"(r[2]), "=r"(r[3]) : "r"(addr));
}

__device__ __forceinline__ uint32_t smem_u32(const void* p) {
    uint32_t a;
    asm("{ .reg .u64 t; cvta.to.shared.u64 t, %1; cvt.u32.u64 %0, t; }" : "=r"(a) : "l"(p));
    return a;
}

__device__ __forceinline__ void cp_async16(uint32_t dst, const void* src, int src_bytes) {
    asm volatile("cp.async.cg.shared.global [%0], [%1], 16, %2;"
                 :: "r"(dst), "l"(src), "r"(src_bytes) : "memory");
}
#define CP_COMMIT() asm volatile("cp.async.commit_group;" ::: "memory")
#define CP_WAIT(n) asm volatile("cp.async.wait_group %0;" :: "n"(n) : "memory")

// ---------------- fp16x2 GEMM: C[M,NOUT] = A[M,256] @ W^T (+epilogue) ----------------
// MODE 0 (q): out fp32 outA[M,NOUT] = acc + bias[n]
// MODE 1 (GEMM-E): acc + swd[m]*cb1[n] + cb2[n]; n<256 -> fp32 outA[M,256]; else fp16 ef16[M,320]
template <int BN, int NOUT, int MODE>
__global__ __launch_bounds__(256) void gemm_f16(
    const __half* __restrict__ A,
    const __half* __restrict__ whi, const __half* __restrict__ wlo,
    const float* __restrict__ bias,
    const float* __restrict__ cb1, const float* __restrict__ cb2,
    const float* __restrict__ swd,
    float* __restrict__ outA, __half* __restrict__ ef16,
    int Mrows) {
    constexpr int WN = BN / 2;
    constexpr int NF = WN / 8;
    constexpr int Ao = 0;
    constexpr int Bho = 5120;
    constexpr int Blo_ = 5120 + 40 * BN;
    constexpr int STG = 5120 + 80 * BN;  // halfs per stage
    extern __shared__ __half sm[];
    const uint32_t smb = smem_u32(sm);

    int tid = threadIdx.x;
    int lane = tid & 31, wid = tid >> 5;
    int wm = wid & 3, wn = wid >> 2;
    int qr = lane >> 2, qc = (lane & 3) * 2;
    int bm = blockIdx.x * 128, bn = blockIdx.y * BN;

    int a_row = wm * 32 + (lane & 7) + ((lane >> 3) & 1) * 8;
    int a_col = ((lane >> 4) & 1) * 8;
    int b_col = ((lane >> 3) & 1) * 8;
    int b_rowl = (lane & 7) + ((lane >> 4) & 1) * 8;

    float acc[2][NF][4];
#pragma unroll
    for (int mf = 0; mf < 2; mf++)
#pragma unroll
        for (int nf = 0; nf < NF; nf++)
#pragma unroll
            for (int j = 0; j < 4; j++) acc[mf][nf][j] = 0.f;

    auto load_chunk = [&](int ck, int stage) {
        uint32_t base = smb + (uint32_t)stage * (STG * 2);
#pragma unroll
        for (int i = 0; i < 2; i++) {
            int f = tid + i * 256;
            int row = f >> 2, sg = f & 3;
            int ok = (bm + row < Mrows) ? 16 : 0;
            cp_async16(base + (Ao + row * 40 + sg * 8) * 2,
                       A + (size_t)(bm + row) * 256 + ck * 32 + sg * 8, ok);
        }
        {
            int row = tid >> 2, sg = tid & 3;
            size_t goff = (size_t)(bn + row) * 256 + ck * 32 + sg * 8;
            cp_async16(base + (Bho + row * 40 + sg * 8) * 2, whi + goff, 16);
            cp_async16(base + (Blo_ + row * 40 + sg * 8) * 2, wlo + goff, 16);
        }
    };

    load_chunk(0, 0);
    CP_COMMIT();

    for (int c = 0; c < 8; c++) {
        if (c < 7) {
            load_chunk(c + 1, (c + 1) & 1);
            CP_COMMIT();
            CP_WAIT(1);
        } else {
            CP_WAIT(0);
        }
        __syncthreads();
        uint32_t base = smb + (uint32_t)(c & 1) * (STG * 2);
#pragma unroll
        for (int ks = 0; ks < 32; ks += 16) {
            uint32_t ah[2][4];
#pragma unroll
            for (int mf = 0; mf < 2; mf++) {
                uint32_t off = ((a_row + mf * 16) * 40 + a_col + ks) * 2;
                ldsm_x4(ah[mf], base + Ao * 2 + off);
            }
            uint32_t bh[NF][2], bl[NF][2];
#pragma unroll
            for (int np = 0; np < NF / 2; np++) {
                uint32_t off = ((wn * WN + np * 16 + b_rowl) * 40 + b_col + ks) * 2;
                uint32_t t[4];
                ldsm_x4(t, base + Bho * 2 + off);
                bh[2 * np][0] = t[0]; bh[2 * np][1] = t[1];
                bh[2 * np + 1][0] = t[2]; bh[2 * np + 1][1] = t[3];
                ldsm_x4(t, base + Blo_ * 2 + off);
                bl[2 * np][0] = t[0]; bl[2 * np][1] = t[1];
                bl[2 * np + 1][0] = t[2]; bl[2 * np + 1][1] = t[3];
            }
#pragma unroll
            for (int nf = 0; nf < NF; nf++) {
#pragma unroll
                for (int mf = 0; mf < 2; mf++) {
                    mma16816h(acc[mf][nf], ah[mf], bh[nf][0], bh[nf][1]);
                    mma16816h(acc[mf][nf], ah[mf], bl[nf][0], bl[nf][1]);
                }
            }
        }
        __syncthreads();
    }

    // epilogue
#pragma unroll
    for (int mf = 0; mf < 2; mf++) {
#pragma unroll
        for (int nf = 0; nf < NF; nf++) {
            int m0 = bm + wm * 32 + mf * 16 + qr;
            int n0 = bn + wn * WN + nf * 8 + qc;
            if (MODE == 0) {
                float bv0 = bias[n0], bv1 = bias[n0 + 1];
#pragma unroll
                for (int h = 0; h < 2; h++) {
                    int m = m0 + h * 8;
                    if (m >= Mrows) continue;
                    *(float2*)(outA + (size_t)m * NOUT + n0) =
                        make_float2(acc[mf][nf][h * 2] + bv0, acc[mf][nf][h * 2 + 1] + bv1);
                }
            } else {
                float e0 = cb1[n0], e1 = cb1[n0 + 1];
                float f0 = cb2[n0], f1 = cb2[n0 + 1];
#pragma unroll
                for (int h = 0; h < 2; h++) {
                    int m = m0 + h * 8;
                    if (m >= Mrows) continue;
                    float sw = swd[m];
                    float c0 = acc[mf][nf][h * 2] + sw * e0 + f0;
                    float c1 = acc[mf][nf][h * 2 + 1] + sw * e1 + f1;
                    if (n0 < 256) {
                        *(float2*)(outA + (size_t)m * 256 + n0) = make_float2(c0, c1);
                    } else {
                        uint32_t ph = ((uint32_t)__half_as_ushort(__float2half_rn(c1)) << 16) |
                                      __half_as_ushort(__float2half_rn(c0));
                        *(uint32_t*)(ef16 + (size_t)m * 320 + n0 - 256) = ph;
                    }
                }
            }
        }
    }
}

// ---------------- hyperedge aggregation of RAW vfeat ----------------
__global__ __launch_bounds__(256) void edge_agg_kernel(
    const float* __restrict__ vrw, const float* __restrict__ ers) {
    int e = blockIdx.x;
    int t = threadIdx.x;
    int beg = g_ebeg[e], end = beg + g_ecnt[e];
    float acc = 0.f, sw = 0.f;
    for (int i = beg; i < end; i++) {
        int s = g_elist[i];
        float w = vrw[s];
        sw += w;
        acc += w * __half2float(g_vf16[(size_t)s * 256 + t]);
    }
    float inv = 1.f / ers[e];
    g_aggv[(size_t)e * 256 + t] = __float2half_rn(acc * inv);
    if (t == 0) g_swd[e] = sw * inv;
}

// ---------------- per-vertex attention: online softmax, fp16 kv, fp32 q ----------------
__global__ __launch_bounds__(256) void attn_kernel(float* __restrict__ out_fv) {
    int gw = (blockIdx.x * blockDim.x + threadIdx.x) >> 5;
    int lane = threadIdx.x & 31;
    if (gw >= Nc) return;
    int n = gw;
    int beg = g_vbeg[n], end = beg + g_vcnt[n];
    float q0 = g_qf[(size_t)n * 64 + lane];
    float q1 = g_qf[(size_t)n * 64 + 32 + lane];
    const float scale = 0.125f;

    float m = -1e30f, denom = 0.f;
    float acc[8];
#pragma unroll
    for (int j = 0; j < 8; j++) acc[j] = 0.f;

    for (int i = beg; i < end; i++) {
        int e = g_vlist[i];
        const __half* kv = g_ef16 + (size_t)e * 320;
        float s = q0 * __half2float(kv[lane]) + q1 * __half2float(kv[32 + lane]);
#pragma unroll
        for (int o = 16; o; o >>= 1) s += __shfl_xor_sync(0xffffffffu, s, o);
        s = (s > 0.f ? s : 0.01f * s) * scale;
        float mnew = fmaxf(m, s);
        float corr = __expf(m - mnew);
        float p = __expf(s - mnew);
        m = mnew;
        denom = denom * corr + p;
        uint4 raw = *(const uint4*)(kv + 64 + lane * 8);
        float2 f0 = __half22float2(*(__half2*)&raw.x);
        float2 f1 = __half22float2(*(__half2*)&raw.y);
        float2 f2 = __half22float2(*(__half2*)&raw.z);
        float2 f3 = __half22float2(*(__half2*)&raw.w);
        acc[0] = acc[0] * corr + p * f0.x; acc[1] = acc[1] * corr + p * f0.y;
        acc[2] = acc[2] * corr + p * f1.x; acc[3] = acc[3] * corr + p * f1.y;
        acc[4] = acc[4] * corr + p * f2.x; acc[5] = acc[5] * corr + p * f2.y;
        acc[6] = acc[6] * corr + p * f3.x; acc[7] = acc[7] * corr + p * f3.y;
    }
    float inv = 1.f / fmaxf(denom, 1e-20f);
#pragma unroll
    for (int j = 0; j < 8; j++) acc[j] *= inv;
    float4* op = (float4*)(out_fv + (size_t)n * 256 + lane * 8);
    op[0] = make_float4(acc[0], acc[1], acc[2], acc[3]);
    op[1] = make_float4(acc[4], acc[5], acc[6], acc[7]);
}

// ---------------- classification head ----------------
__global__ __launch_bounds__(256) void pred_kernel(
    const float* __restrict__ fv, const float* __restrict__ Wc,
    const float* __restrict__ bc, float* __restrict__ pred) {
    __shared__ float sW[10 * 256];
    __shared__ float sb_[10];
    int t = threadIdx.x;
    for (int i = t; i < 2560; i += 256) sW[i] = Wc[i];
    if (t < 10) sb_[t] = bc[t];
    __syncthreads();
    int warp = t >> 5, lane = t & 31;
    int r = blockIdx.x * 8 + warp;
    if (r >= Nc) return;
    float acc[10];
#pragma unroll
    for (int c = 0; c < 10; c++) acc[c] = 0.f;
    for (int kk = lane; kk < 256; kk += 32) {
        float x = fv[(size_t)r * 256 + kk];
#pragma unroll
        for (int c = 0; c < 10; c++) acc[c] += x * sW[c * 256 + kk];
    }
#pragma unroll
    for (int c = 0; c < 10; c++) {
#pragma unroll
        for (int o = 16; o; o >>= 1) acc[c] += __shfl_xor_sync(0xffffffffu, acc[c], o);
    }
    if (lane == 0) {
#pragma unroll
        for (int c = 0; c < 10; c++) pred[(size_t)r * 10 + c] = acc[c] + sb_[c];
    }
}

// ---------------- launch ----------------
extern "C" void kernel_launch(void* const* d_in, const int* in_sizes, int n_in,
                              void* d_out, int out_size) {
    const float* vfeat = (const float*)d_in[0];
    const float* vrw = (const float*)d_in[2];
    const float* ers = (const float*)d_in[5];
    const float* W1 = (const float*)d_in[6];
    const float* b1 = (const float*)d_in[7];
    const float* Wve = (const float*)d_in[8];
    const float* bve = (const float*)d_in[9];
    const float* Wqv = (const float*)d_in[10];
    const float* bqv = (const float*)d_in[11];
    const float* Wke = (const float*)d_in[12];
    const float* bke = (const float*)d_in[13];
    const float* Wvale = (const float*)d_in[14];
    const float* bvale = (const float*)d_in[15];
    const float* Wcls = (const float*)d_in[16];
    const float* bcls = (const float*)d_in[17];
    const int* in_src = (const int*)d_in[18];
    const int* in_dst = (const int*)d_in[19];

    float* out = (float*)d_out;
    float* out_fv = out;
    float* out_fe = out + (size_t)Nc * 256;
    float* out_pred = out_fe + (size_t)Ec * 256;

    __half *p_vf16, *p_aggv, *p_wEh, *p_wEl, *p_wQh, *p_wQl, *p_ef16;
    float *p_wEf, *p_wq1, *p_qf, *p_qb, *p_cb1, *p_cb2, *p_swd;
    cudaGetSymbolAddress((void**)&p_vf16, g_vf16);
    cudaGetSymbolAddress((void**)&p_aggv, g_aggv);
    cudaGetSymbolAddress((void**)&p_wEh, g_wEh);
    cudaGetSymbolAddress((void**)&p_wEl, g_wEl);
    cudaGetSymbolAddress((void**)&p_wQh, g_wQh);
    cudaGetSymbolAddress((void**)&p_wQl, g_wQl);
    cudaGetSymbolAddress((void**)&p_ef16, g_ef16);
    cudaGetSymbolAddress((void**)&p_wEf, g_wEf);
    cudaGetSymbolAddress((void**)&p_wq1, g_wq1);
    cudaGetSymbolAddress((void**)&p_qf, g_qf);
    cudaGetSymbolAddress((void**)&p_qb, g_qb);
    cudaGetSymbolAddress((void**)&p_cb1, g_cb1);
    cudaGetSymbolAddress((void**)&p_cb2, g_cb2);
    cudaGetSymbolAddress((void**)&p_swd, g_swd);

    // fork/join resources (one-time init; no device memory alloc)
    static cudaStream_t sB = 0, sC = 0;
    static cudaEvent_t ev_fork = 0, ev_csr = 0, ev_w = 0, ev_q = 0;
    static int stream_ok = -1;
    if (stream_ok < 0) {
        cudaError_t e1 = cudaStreamCreateWithFlags(&sB, cudaStreamNonBlocking);
        cudaError_t e2 = cudaStreamCreateWithFlags(&sC, cudaStreamNonBlocking);
        cudaError_t e3 = cudaEventCreateWithFlags(&ev_fork, cudaEventDisableTiming);
        cudaError_t e4 = cudaEventCreateWithFlags(&ev_csr, cudaEventDisableTiming);
        cudaError_t e5 = cudaEventCreateWithFlags(&ev_w, cudaEventDisableTiming);
        cudaError_t e6 = cudaEventCreateWithFlags(&ev_q, cudaEventDisableTiming);
        stream_ok = (e1 == cudaSuccess && e2 == cudaSuccess && e3 == cudaSuccess &&
                     e4 == cudaSuccess && e5 == cudaSuccess && e6 == cudaSuccess) ? 1 : 0;
    }
    cudaStream_t sb = stream_ok ? sB : 0;
    cudaStream_t sc = stream_ok ? sC : 0;

    if (stream_ok) {
        cudaEventRecord(ev_fork, 0);
        cudaStreamWaitEvent(sB, ev_fork, 0);
        cudaStreamWaitEvent(sC, ev_fork, 0);
    }

    // stream B: CSR build
    zero_cnts_kernel<<<(Nc + 255) / 256, 256, 0, sb>>>();
    hist_kernel<<<(Mc + 255) / 256, 256, 0, sb>>>(in_src, in_dst);
    assign_off_kernel<<<(Nc + 255) / 256, 256, 0, sb>>>();
    scatter_kernel<<<(Mc + 255) / 256, 256, 0, sb>>>(in_src, in_dst);
    if (stream_ok) cudaEventRecord(ev_csr, sB);

    // stream C: weight composition chain + splits
    compose1<<<320, 256, 0, sc>>>(Wve, Wqv, W1);
    bias1<<<40, 256, 0, sc>>>(Wve, b1, bve, Wqv, bqv);
    compose2<<<320, 256, 0, sc>>>(Wke, Wvale);
    bias2<<<40, 256, 0, sc>>>(Wke, Wvale, bke, bvale);
    split_hl<<<(576 * 64 + 255) / 256, 256, 0, sc>>>((const float4*)p_wEf, p_wEh, p_wEl, 576 * 64);
    split_hl<<<(64 * 64 + 255) / 256, 256, 0, sc>>>((const float4*)p_wq1, p_wQh, p_wQl, 64 * 64);
    if (stream_ok) cudaEventRecord(ev_w, sC);

    // main: vfeat conversion
    conv_h<<<(Nc * 64 + 255) / 256, 256>>>((const float4*)vfeat, p_vf16, Nc * 64);

    const int gN = (Nc + 127) / 128;  // 391
    const int gE = (Ec + 127) / 128;  // 196
    const int SMEM = 2 * (5120 + 80 * 64) * 2;  // 40960 B

    // q GEMM on stream C after weights + needs vf16: run it on main after waiting ev_w
    if (stream_ok) cudaStreamWaitEvent(0, ev_w, 0);
    gemm_f16<64, 64, 0><<<dim3(gN, 1), 256, SMEM>>>(
        p_vf16, p_wQh, p_wQl, p_qb, nullptr, nullptr, nullptr, p_qf, nullptr, Nc);
    if (stream_ok) cudaEventRecord(ev_q, 0);

    // edge aggregation (needs vf16 + CSR)
    if (stream_ok) cudaStreamWaitEvent(0, ev_csr, 0);
    edge_agg_kernel<<<Ec, 256>>>(vrw, ers);
    // GEMM-E: [feat_e | k | v] = aggv @ WE^T + swd*cb1 + cb2
    gemm_f16<64, 576, 1><<<dim3(gE, 9), 256, SMEM>>>(
        p_aggv, p_wEh, p_wEl, nullptr, p_cb1, p_cb2, p_swd, out_fe, p_ef16, Ec);
    // attention -> out_fv (needs q + kv + vertex CSR)
    attn_kernel<<<(Nc + 7) / 8, 256>>>(out_fv);
    // pred
    pred_kernel<<<(Nc + 7) / 8, 256>>>(out_fv, Wcls, bcls, out_pred);
}

// round 11
// speedup vs baseline: 3.2905x; 1.0490x over previous
#include <cuda_runtime.h>
#include <cuda_fp16.h>
#include <math.h>
#include <stdint.h>

#define Nc 50000
#define Ec 25000
#define Mc 300000
// dims: INPUT=VERTEX=EDGE=256, QUERY=64, NUM_CLASS=10

// ---------------- scratch ----------------
__device__ __half g_vf16[(size_t)Nc * 256];      // vfeat fp16
__device__ float g_qf[(size_t)Nc * 64];          // q fp32
__device__ __half g_aggv[(size_t)Ec * 256];      // aggregated raw vfeat per edge (fp16)
__device__ float g_swd[Ec];
__device__ __half g_ef16[(size_t)Ec * 320];      // cols 0-63 k, 64-319 v (fp16)
__device__ float g_attn[Mc];                     // precomputed attention scores (vlist order)
// composed weights
__device__ float g_wEf[576 * 256];               // [Wve@W1; Wke@Wve@W1; Wvale@Wve@W1] fp32
__device__ float g_wq1[64 * 256];                // Wqv@W1 fp32
__device__ __half g_wEh[576 * 256], g_wEl[576 * 256];
__device__ __half g_wQh[64 * 256], g_wQl[64 * 256];
__device__ float g_bve1[256];                    // Wve@b1 + bve
__device__ float g_qb[64];                       // Wqv@b1 + bqv
__device__ float g_cb1[576];                     // [bve1; Wke@bve1; Wvale@bve1]
__device__ float g_cb2[576];                     // [0; bke; bvale]
// CSR
__device__ int g_ebeg[Ec], g_vbeg[Nc], g_ecnt[Ec], g_vcnt[Nc];
__device__ int g_ecur[Ec], g_vcur[Nc];
__device__ int g_tote, g_totn;
__device__ int g_elist[Mc], g_vlist[Mc], g_vsrc[Mc];

// ---------------- CSR build ----------------
__global__ void zero_cnts_kernel() {
    int i = blockIdx.x * blockDim.x + threadIdx.x;
    if (i < Ec) g_ecnt[i] = 0;
    if (i < Nc) g_vcnt[i] = 0;
    if (i == 0) { g_tote = 0; g_totn = 0; }
}

__global__ void hist_kernel(const int* __restrict__ in_src, const int* __restrict__ in_dst) {
    int m = blockIdx.x * blockDim.x + threadIdx.x;
    if (m >= Mc) return;
    atomicAdd(&g_ecnt[in_dst[m]], 1);
    atomicAdd(&g_vcnt[in_src[m]], 1);
}

__global__ void assign_off_kernel() {
    int i = blockIdx.x * blockDim.x + threadIdx.x;
    int lane = threadIdx.x & 31;
    {
        int c = (i < Ec) ? g_ecnt[i] : 0;
        int x = c;
#pragma unroll
        for (int o = 1; o < 32; o <<= 1) {
            int y = __shfl_up_sync(0xffffffffu, x, o);
            if (lane >= o) x += y;
        }
        int wsum = __shfl_sync(0xffffffffu, x, 31);
        int base = 0;
        if (lane == 31 && wsum > 0) base = atomicAdd(&g_tote, wsum);
        base = __shfl_sync(0xffffffffu, base, 31);
        if (i < Ec) { int b = base + x - c; g_ebeg[i] = b; g_ecur[i] = b; }
    }
    {
        int c = (i < Nc) ? g_vcnt[i] : 0;
        int x = c;
#pragma unroll
        for (int o = 1; o < 32; o <<= 1) {
            int y = __shfl_up_sync(0xffffffffu, x, o);
            if (lane >= o) x += y;
        }
        int wsum = __shfl_sync(0xffffffffu, x, 31);
        int base = 0;
        if (lane == 31 && wsum > 0) base = atomicAdd(&g_totn, wsum);
        base = __shfl_sync(0xffffffffu, base, 31);
        if (i < Nc) { int b = base + x - c; g_vbeg[i] = b; g_vcur[i] = b; }
    }
}

__global__ void scatter_kernel(const int* __restrict__ in_src, const int* __restrict__ in_dst) {
    int m = blockIdx.x * blockDim.x + threadIdx.x;
    if (m >= Mc) return;
    int s = in_src[m];
    int e = in_dst[m];
    int pe = atomicAdd(&g_ecur[e], 1);
    g_elist[pe] = s;
    int pv = atomicAdd(&g_vcur[s], 1);
    g_vlist[pv] = e;
    g_vsrc[pv] = s;
}

// ---------------- weight composition (exact fp32) ----------------
__global__ void compose1(const float* __restrict__ Wve, const float* __restrict__ Wqv,
                         const float* __restrict__ W1) {
    int r = blockIdx.x, j = threadIdx.x;
    const float* A; float* C; int rr;
    if (r < 256) { A = Wve; C = g_wEf; rr = r; }
    else { A = Wqv; C = g_wq1; rr = r - 256; }
    float acc = 0.f;
    for (int k = 0; k < 256; k++) acc += A[rr * 256 + k] * W1[k * 256 + j];
    C[rr * 256 + j] = acc;
}

__global__ void compose2(const float* __restrict__ Wke, const float* __restrict__ Wvale) {
    int r = blockIdx.x, j = threadIdx.x;
    const float* A; int rr, outrow;
    if (r < 64) { A = Wke; rr = r; outrow = 256 + r; }
    else { A = Wvale; rr = r - 64; outrow = 320 + rr; }
    float acc = 0.f;
    for (int k = 0; k < 256; k++) acc += A[rr * 256 + k] * g_wEf[k * 256 + j];
    g_wEf[outrow * 256 + j] = acc;
}

__global__ void bias1(const float* __restrict__ Wve, const float* __restrict__ b1,
                      const float* __restrict__ bve, const float* __restrict__ Wqv,
                      const float* __restrict__ bqv) {
    int t = blockIdx.x * blockDim.x + threadIdx.x;
    int gw = t >> 5, lane = t & 31;
    if (gw >= 320) return;
    const float* M; int i; float add; float* dst;
    if (gw < 256) { M = Wve; i = gw; add = bve[i]; dst = &g_bve1[i]; }
    else { M = Wqv; i = gw - 256; add = bqv[i]; dst = &g_qb[i]; }
    float s = 0.f;
    for (int k = lane; k < 256; k += 32) s += M[i * 256 + k] * b1[k];
#pragma unroll
    for (int o = 16; o; o >>= 1) s += __shfl_xor_sync(0xffffffffu, s, o);
    if (lane == 0) *dst = s + add;
}

__global__ void bias2(const float* __restrict__ Wke, const float* __restrict__ Wvale,
                      const float* __restrict__ bke, const float* __restrict__ bvale) {
    int t = blockIdx.x * blockDim.x + threadIdx.x;
    int gw = t >> 5, lane = t & 31;
    if (gw < 320) {
        const float* M; int i; float* dst;
        if (gw < 64) { M = Wke; i = gw; dst = &g_cb1[256 + i]; }
        else { M = Wvale; i = gw - 64; dst = &g_cb1[320 + i]; }
        float s = 0.f;
        for (int k = lane; k < 256; k += 32) s += M[i * 256 + k] * g_bve1[k];
#pragma unroll
        for (int o = 16; o; o >>= 1) s += __shfl_xor_sync(0xffffffffu, s, o);
        if (lane == 0) *dst = s;
    }
    if (t < 256) { g_cb1[t] = g_bve1[t]; g_cb2[t] = 0.f; }
    else if (t < 320) g_cb2[t] = bke[t - 256];
    else if (t < 576) g_cb2[t] = bvale[t - 320];
}

// ---------------- fp32 -> fp16 conversions ----------------
__global__ void split_hl(const float4* __restrict__ src, __half* __restrict__ hi,
                         __half* __restrict__ lo, int n4) {
    int i = blockIdx.x * blockDim.x + threadIdx.x;
    if (i >= n4) return;
    float4 v = src[i];
    __half h0 = __float2half_rn(v.x), h1 = __float2half_rn(v.y);
    __half h2 = __float2half_rn(v.z), h3 = __float2half_rn(v.w);
    __half l0 = __float2half_rn(v.x - __half2float(h0));
    __half l1 = __float2half_rn(v.y - __half2float(h1));
    __half l2 = __float2half_rn(v.z - __half2float(h2));
    __half l3 = __float2half_rn(v.w - __half2float(h3));
    uint2 H, L;
    H.x = ((uint32_t)__half_as_ushort(h1) << 16) | __half_as_ushort(h0);
    H.y = ((uint32_t)__half_as_ushort(h3) << 16) | __half_as_ushort(h2);
    L.x = ((uint32_t)__half_as_ushort(l1) << 16) | __half_as_ushort(l0);
    L.y = ((uint32_t)__half_as_ushort(l3) << 16) | __half_as_ushort(l2);
    *(uint2*)(hi + (size_t)i * 4) = H;
    *(uint2*)(lo + (size_t)i * 4) = L;
}

__global__ void conv_h(const float4* __restrict__ src, __half* __restrict__ dst, int n4) {
    int i = blockIdx.x * blockDim.x + threadIdx.x;
    if (i >= n4) return;
    float4 v = src[i];
    uint2 H;
    H.x = ((uint32_t)__half_as_ushort(__float2half_rn(v.y)) << 16) | __half_as_ushort(__float2half_rn(v.x));
    H.y = ((uint32_t)__half_as_ushort(__float2half_rn(v.w)) << 16) | __half_as_ushort(__float2half_rn(v.z));
    *(uint2*)(dst + (size_t)i * 4) = H;
}

// ---------------- MMA helpers ----------------
__device__ __forceinline__ void mma16816h(float* d, const uint32_t* a, uint32_t b0, uint32_t b1) {
    asm volatile(
        "mma.sync.aligned.m16n8k16.row.col.f32.f16.f16.f32 "
        "{%0,%1,%2,%3},{%4,%5,%6,%7},{%8,%9},{%0,%1,%2,%3};"
        : "+f"(d[0]), "+f"(d[1]), "+f"(d[2]), "+f"(d[3])
        : "r"(a[0]), "r"(a[1]), "r"(a[2]), "r"(a[3]), "r"(b0), "r"(b1));
}

__device__ __forceinline__ void ldsm_x4(uint32_t* r, uint32_t addr) {
    asm volatile("ldmatrix.sync.aligned.m8n8.x4.shared.b16 {%0,%1,%2,%3}, [%4];"
                 : "=r"(r[0]), "=r"(r[1]), "=r"(r[2]), "=r"(r[3]) : "r"(addr));
}

__device__ __forceinline__ uint32_t smem_u32(const void* p) {
    uint32_t a;
    asm("{ .reg .u64 t; cvta.to.shared.u64 t, %1; cvt.u32.u64 %0, t; }" : "=r"(a) : "l"(p));
    return a;
}

__device__ __forceinline__ void cp_async16(uint32_t dst, const void* src, int src_bytes) {
    asm volatile("cp.async.cg.shared.global [%0], [%1], 16, %2;"
                 :: "r"(dst), "l"(src), "r"(src_bytes) : "memory");
}
#define CP_COMMIT() asm volatile("cp.async.commit_group;" ::: "memory")
#define CP_WAIT(n) asm volatile("cp.async.wait_group %0;" :: "n"(n) : "memory")

// ---------------- fp16x2 GEMM: C[M,NOUT] = A[M,256] @ W^T (+epilogue) ----------------
template <int BN, int NOUT, int MODE>
__global__ __launch_bounds__(256) void gemm_f16(
    const __half* __restrict__ A,
    const __half* __restrict__ whi, const __half* __restrict__ wlo,
    const float* __restrict__ bias,
    const float* __restrict__ cb1, const float* __restrict__ cb2,
    const float* __restrict__ swd,
    float* __restrict__ outA, __half* __restrict__ ef16,
    int Mrows) {
    constexpr int WN = BN / 2;
    constexpr int NF = WN / 8;
    constexpr int Ao = 0;
    constexpr int Bho = 5120;
    constexpr int Blo_ = 5120 + 40 * BN;
    constexpr int STG = 5120 + 80 * BN;
    extern __shared__ __half sm[];
    const uint32_t smb = smem_u32(sm);

    int tid = threadIdx.x;
    int lane = tid & 31, wid = tid >> 5;
    int wm = wid & 3, wn = wid >> 2;
    int qr = lane >> 2, qc = (lane & 3) * 2;
    int bm = blockIdx.x * 128, bn = blockIdx.y * BN;

    int a_row = wm * 32 + (lane & 7) + ((lane >> 3) & 1) * 8;
    int a_col = ((lane >> 4) & 1) * 8;
    int b_col = ((lane >> 3) & 1) * 8;
    int b_rowl = (lane & 7) + ((lane >> 4) & 1) * 8;

    float acc[2][NF][4];
#pragma unroll
    for (int mf = 0; mf < 2; mf++)
#pragma unroll
        for (int nf = 0; nf < NF; nf++)
#pragma unroll
            for (int j = 0; j < 4; j++) acc[mf][nf][j] = 0.f;

    auto load_chunk = [&](int ck, int stage) {
        uint32_t base = smb + (uint32_t)stage * (STG * 2);
#pragma unroll
        for (int i = 0; i < 2; i++) {
            int f = tid + i * 256;
            int row = f >> 2, sg = f & 3;
            int ok = (bm + row < Mrows) ? 16 : 0;
            cp_async16(base + (Ao + row * 40 + sg * 8) * 2,
                       A + (size_t)(bm + row) * 256 + ck * 32 + sg * 8, ok);
        }
        {
            int row = tid >> 2, sg = tid & 3;
            size_t goff = (size_t)(bn + row) * 256 + ck * 32 + sg * 8;
            cp_async16(base + (Bho + row * 40 + sg * 8) * 2, whi + goff, 16);
            cp_async16(base + (Blo_ + row * 40 + sg * 8) * 2, wlo + goff, 16);
        }
    };

    load_chunk(0, 0);
    CP_COMMIT();

    for (int c = 0; c < 8; c++) {
        if (c < 7) {
            load_chunk(c + 1, (c + 1) & 1);
            CP_COMMIT();
            CP_WAIT(1);
        } else {
            CP_WAIT(0);
        }
        __syncthreads();
        uint32_t base = smb + (uint32_t)(c & 1) * (STG * 2);
#pragma unroll
        for (int ks = 0; ks < 32; ks += 16) {
            uint32_t ah[2][4];
#pragma unroll
            for (int mf = 0; mf < 2; mf++) {
                uint32_t off = ((a_row + mf * 16) * 40 + a_col + ks) * 2;
                ldsm_x4(ah[mf], base + Ao * 2 + off);
            }
            uint32_t bh[NF][2], bl[NF][2];
#pragma unroll
            for (int np = 0; np < NF / 2; np++) {
                uint32_t off = ((wn * WN + np * 16 + b_rowl) * 40 + b_col + ks) * 2;
                uint32_t t[4];
                ldsm_x4(t, base + Bho * 2 + off);
                bh[2 * np][0] = t[0]; bh[2 * np][1] = t[1];
                bh[2 * np + 1][0] = t[2]; bh[2 * np + 1][1] = t[3];
                ldsm_x4(t, base + Blo_ * 2 + off);
                bl[2 * np][0] = t[0]; bl[2 * np][1] = t[1];
                bl[2 * np + 1][0] = t[2]; bl[2 * np + 1][1] = t[3];
            }
#pragma unroll
            for (int nf = 0; nf < NF; nf++) {
#pragma unroll
                for (int mf = 0; mf < 2; mf++) {
                    mma16816h(acc[mf][nf], ah[mf], bh[nf][0], bh[nf][1]);
                    mma16816h(acc[mf][nf], ah[mf], bl[nf][0], bl[nf][1]);
                }
            }
        }
        __syncthreads();
    }

#pragma unroll
    for (int mf = 0; mf < 2; mf++) {
#pragma unroll
        for (int nf = 0; nf < NF; nf++) {
            int m0 = bm + wm * 32 + mf * 16 + qr;
            int n0 = bn + wn * WN + nf * 8 + qc;
            if (MODE == 0) {
                float bv0 = bias[n0], bv1 = bias[n0 + 1];
#pragma unroll
                for (int h = 0; h < 2; h++) {
                    int m = m0 + h * 8;
                    if (m >= Mrows) continue;
                    *(float2*)(outA + (size_t)m * NOUT + n0) =
                        make_float2(acc[mf][nf][h * 2] + bv0, acc[mf][nf][h * 2 + 1] + bv1);
                }
            } else {
                float e0 = cb1[n0], e1 = cb1[n0 + 1];
                float f0 = cb2[n0], f1 = cb2[n0 + 1];
#pragma unroll
                for (int h = 0; h < 2; h++) {
                    int m = m0 + h * 8;
                    if (m >= Mrows) continue;
                    float sw = swd[m];
                    float c0 = acc[mf][nf][h * 2] + sw * e0 + f0;
                    float c1 = acc[mf][nf][h * 2 + 1] + sw * e1 + f1;
                    if (n0 < 256) {
                        *(float2*)(outA + (size_t)m * 256 + n0) = make_float2(c0, c1);
                    } else {
                        uint32_t ph = ((uint32_t)__half_as_ushort(__float2half_rn(c1)) << 16) |
                                      __half_as_ushort(__float2half_rn(c0));
                        *(uint32_t*)(ef16 + (size_t)m * 320 + n0 - 256) = ph;
                    }
                }
            }
        }
    }
}

// ---------------- hyperedge aggregation of RAW vfeat ----------------
__global__ __launch_bounds__(256) void edge_agg_kernel(
    const float* __restrict__ vrw, const float* __restrict__ ers) {
    int e = blockIdx.x;
    int t = threadIdx.x;
    int beg = g_ebeg[e], end = beg + g_ecnt[e];
    float acc = 0.f, sw = 0.f;
    for (int i = beg; i < end; i++) {
        int s = g_elist[i];
        float w = vrw[s];
        sw += w;
        acc += w * __half2float(g_vf16[(size_t)s * 256 + t]);
    }
    float inv = 1.f / ers[e];
    g_aggv[(size_t)e * 256 + t] = __float2half_rn(acc * inv);
    if (t == 0) g_swd[e] = sw * inv;
}

// ---------------- attention scores: edge-parallel (8 lanes/edge) ----------------
__global__ __launch_bounds__(256) void attn_score_kernel() {
    int t = blockIdx.x * 256 + threadIdx.x;
    int warp = t >> 5, lane = t & 31;
    int grp = lane >> 3, sub = lane & 7;
    int i = warp * 4 + grp;
    if (i >= Mc) return;
    int s = g_vsrc[i];
    int e = g_vlist[i];
    const float* q = g_qf + (size_t)s * 64 + sub * 8;
    float4 qa = *(const float4*)q;
    float4 qb = *(const float4*)(q + 4);
    uint4 kr = *(const uint4*)(g_ef16 + (size_t)e * 320 + sub * 8);
    float2 k0 = __half22float2(*(__half2*)&kr.x);
    float2 k1 = __half22float2(*(__half2*)&kr.y);
    float2 k2 = __half22float2(*(__half2*)&kr.z);
    float2 k3 = __half22float2(*(__half2*)&kr.w);
    float d = qa.x * k0.x + qa.y * k0.y + qa.z * k1.x + qa.w * k1.y +
              qb.x * k2.x + qb.y * k2.y + qb.z * k3.x + qb.w * k3.y;
    d += __shfl_xor_sync(0xffffffffu, d, 1);
    d += __shfl_xor_sync(0xffffffffu, d, 2);
    d += __shfl_xor_sync(0xffffffffu, d, 4);
    if (sub == 0) {
        d = (d > 0.f ? d : 0.01f * d) * 0.125f;
        g_attn[i] = d;
    }
}

// ---------------- attention accumulate: one warp/vertex, no shfl in loop ----------
__global__ __launch_bounds__(256) void attn_accum_kernel(float* __restrict__ out_fv) {
    int gw = (blockIdx.x * blockDim.x + threadIdx.x) >> 5;
    int lane = threadIdx.x & 31;
    if (gw >= Nc) return;
    int beg = g_vbeg[gw], cnt = g_vcnt[gw];

    float mx = -1e30f;
    for (int base = 0; base < cnt; base += 32) {
        int i = base + lane;
        if (i < cnt) mx = fmaxf(mx, g_attn[beg + i]);
    }
#pragma unroll
    for (int o = 16; o; o >>= 1) mx = fmaxf(mx, __shfl_xor_sync(0xffffffffu, mx, o));

    float denom = 0.f;
    float acc[8];
#pragma unroll
    for (int j = 0; j < 8; j++) acc[j] = 0.f;
    for (int i = beg; i < beg + cnt; i++) {
        float p = __expf(g_attn[i] - mx);
        denom += p;
        int e = g_vlist[i];
        uint4 raw = *(const uint4*)(g_ef16 + (size_t)e * 320 + 64 + lane * 8);
        float2 f0 = __half22float2(*(__half2*)&raw.x);
        float2 f1 = __half22float2(*(__half2*)&raw.y);
        float2 f2 = __half22float2(*(__half2*)&raw.z);
        float2 f3 = __half22float2(*(__half2*)&raw.w);
        acc[0] += p * f0.x; acc[1] += p * f0.y;
        acc[2] += p * f1.x; acc[3] += p * f1.y;
        acc[4] += p * f2.x; acc[5] += p * f2.y;
        acc[6] += p * f3.x; acc[7] += p * f3.y;
    }
    float inv = 1.f / fmaxf(denom, 1e-20f);
#pragma unroll
    for (int j = 0; j < 8; j++) acc[j] *= inv;
    float4* op = (float4*)(out_fv + (size_t)gw * 256 + lane * 8);
    op[0] = make_float4(acc[0], acc[1], acc[2], acc[3]);
    op[1] = make_float4(acc[4], acc[5], acc[6], acc[7]);
}

// ---------------- classification head ----------------
__global__ __launch_bounds__(256) void pred_kernel(
    const float* __restrict__ fv, const float* __restrict__ Wc,
    const float* __restrict__ bc, float* __restrict__ pred) {
    __shared__ float sW[10 * 256];
    __shared__ float sb_[10];
    int t = threadIdx.x;
    for (int i = t; i < 2560; i += 256) sW[i] = Wc[i];
    if (t < 10) sb_[t] = bc[t];
    __syncthreads();
    int warp = t >> 5, lane = t & 31;
    int r = blockIdx.x * 8 + warp;
    if (r >= Nc) return;
    float acc[10];
#pragma unroll
    for (int c = 0; c < 10; c++) acc[c] = 0.f;
    for (int kk = lane; kk < 256; kk += 32) {
        float x = fv[(size_t)r * 256 + kk];
#pragma unroll
        for (int c = 0; c < 10; c++) acc[c] += x * sW[c * 256 + kk];
    }
#pragma unroll
    for (int c = 0; c < 10; c++) {
#pragma unroll
        for (int o = 16; o; o >>= 1) acc[c] += __shfl_xor_sync(0xffffffffu, acc[c], o);
    }
    if (lane == 0) {
#pragma unroll
        for (int c = 0; c < 10; c++) pred[(size_t)r * 10 + c] = acc[c] + sb_[c];
    }
}

// ---------------- launch ----------------
extern "C" void kernel_launch(void* const* d_in, const int* in_sizes, int n_in,
                              void* d_out, int out_size) {
    const float* vfeat = (const float*)d_in[0];
    const float* vrw = (const float*)d_in[2];
    const float* ers = (const float*)d_in[5];
    const float* W1 = (const float*)d_in[6];
    const float* b1 = (const float*)d_in[7];
    const float* Wve = (const float*)d_in[8];
    const float* bve = (const float*)d_in[9];
    const float* Wqv = (const float*)d_in[10];
    const float* bqv = (const float*)d_in[11];
    const float* Wke = (const float*)d_in[12];
    const float* bke = (const float*)d_in[13];
    const float* Wvale = (const float*)d_in[14];
    const float* bvale = (const float*)d_in[15];
    const float* Wcls = (const float*)d_in[16];
    const float* bcls = (const float*)d_in[17];
    const int* in_src = (const int*)d_in[18];
    const int* in_dst = (const int*)d_in[19];

    float* out = (float*)d_out;
    float* out_fv = out;
    float* out_fe = out + (size_t)Nc * 256;
    float* out_pred = out_fe + (size_t)Ec * 256;

    __half *p_vf16, *p_aggv, *p_wEh, *p_wEl, *p_wQh, *p_wQl, *p_ef16;
    float *p_wEf, *p_wq1, *p_qf, *p_qb, *p_cb1, *p_cb2, *p_swd;
    cudaGetSymbolAddress((void**)&p_vf16, g_vf16);
    cudaGetSymbolAddress((void**)&p_aggv, g_aggv);
    cudaGetSymbolAddress((void**)&p_wEh, g_wEh);
    cudaGetSymbolAddress((void**)&p_wEl, g_wEl);
    cudaGetSymbolAddress((void**)&p_wQh, g_wQh);
    cudaGetSymbolAddress((void**)&p_wQl, g_wQl);
    cudaGetSymbolAddress((void**)&p_ef16, g_ef16);
    cudaGetSymbolAddress((void**)&p_wEf, g_wEf);
    cudaGetSymbolAddress((void**)&p_wq1, g_wq1);
    cudaGetSymbolAddress((void**)&p_qf, g_qf);
    cudaGetSymbolAddress((void**)&p_qb, g_qb);
    cudaGetSymbolAddress((void**)&p_cb1, g_cb1);
    cudaGetSymbolAddress((void**)&p_cb2, g_cb2);
    cudaGetSymbolAddress((void**)&p_swd, g_swd);

    static cudaStream_t sB = 0, sC = 0;
    static cudaEvent_t ev_fork = 0, ev_csr = 0, ev_conv = 0, ev_w = 0, ev_q = 0;
    static int stream_ok = -1;
    if (stream_ok < 0) {
        cudaError_t e1 = cudaStreamCreateWithFlags(&sB, cudaStreamNonBlocking);
        cudaError_t e2 = cudaStreamCreateWithFlags(&sC, cudaStreamNonBlocking);
        cudaError_t e3 = cudaEventCreateWithFlags(&ev_fork, cudaEventDisableTiming);
        cudaError_t e4 = cudaEventCreateWithFlags(&ev_csr, cudaEventDisableTiming);
        cudaError_t e5 = cudaEventCreateWithFlags(&ev_conv, cudaEventDisableTiming);
        cudaError_t e6 = cudaEventCreateWithFlags(&ev_w, cudaEventDisableTiming);
        cudaError_t e7 = cudaEventCreateWithFlags(&ev_q, cudaEventDisableTiming);
        stream_ok = (e1 == cudaSuccess && e2 == cudaSuccess && e3 == cudaSuccess &&
                     e4 == cudaSuccess && e5 == cudaSuccess && e6 == cudaSuccess &&
                     e7 == cudaSuccess) ? 1 : 0;
    }
    cudaStream_t sb = stream_ok ? sB : 0;
    cudaStream_t sc = stream_ok ? sC : 0;

    if (stream_ok) {
        cudaEventRecord(ev_fork, 0);
        cudaStreamWaitEvent(sB, ev_fork, 0);
        cudaStreamWaitEvent(sC, ev_fork, 0);
    }

    // stream B: CSR build
    zero_cnts_kernel<<<(Nc + 255) / 256, 256, 0, sb>>>();
    hist_kernel<<<(Mc + 255) / 256, 256, 0, sb>>>(in_src, in_dst);
    assign_off_kernel<<<(Nc + 255) / 256, 256, 0, sb>>>();
    scatter_kernel<<<(Mc + 255) / 256, 256, 0, sb>>>(in_src, in_dst);
    if (stream_ok) cudaEventRecord(ev_csr, sB);

    const int gN = (Nc + 127) / 128;  // 391
    const int gE = (Ec + 127) / 128;  // 196
    const int SMEM = 2 * (5120 + 80 * 64) * 2;  // 40960 B

    // main: vfeat conversion
    conv_h<<<(Nc * 64 + 255) / 256, 256>>>((const float4*)vfeat, p_vf16, Nc * 64);
    if (stream_ok) cudaEventRecord(ev_conv, 0);

    // stream C: weight composition + splits; record ev_w (GEMM-E weight readiness),
    // then q GEMM (overlaps main's edge_agg/GEMM-E)
    compose1<<<320, 256, 0, sc>>>(Wve, Wqv, W1);
    bias1<<<40, 256, 0, sc>>>(Wve, b1, bve, Wqv, bqv);
    compose2<<<320, 256, 0, sc>>>(Wke, Wvale);
    bias2<<<40, 256, 0, sc>>>(Wke, Wvale, bke, bvale);
    split_hl<<<(576 * 64 + 255) / 256, 256, 0, sc>>>((const float4*)p_wEf, p_wEh, p_wEl, 576 * 64);
    split_hl<<<(64 * 64 + 255) / 256, 256, 0, sc>>>((const float4*)p_wq1, p_wQh, p_wQl, 64 * 64);
    if (stream_ok) cudaEventRecord(ev_w, sC);
    if (stream_ok) cudaStreamWaitEvent(sC, ev_conv, 0);
    gemm_f16<64, 64, 0><<<dim3(gN, 1), 256, SMEM, sc>>>(
        p_vf16, p_wQh, p_wQl, p_qb, nullptr, nullptr, nullptr, p_qf, nullptr, Nc);
    if (stream_ok) cudaEventRecord(ev_q, sC);

    // main: edge aggregation (needs vf16 + CSR)
    if (stream_ok) cudaStreamWaitEvent(0, ev_csr, 0);
    edge_agg_kernel<<<Ec, 256>>>(vrw, ers);
    // GEMM-E needs composed/split weights: wait ev_w (THE R10 BUG: this wait was missing)
    if (stream_ok) cudaStreamWaitEvent(0, ev_w, 0);
    gemm_f16<64, 576, 1><<<dim3(gE, 9), 256, SMEM>>>(
        p_aggv, p_wEh, p_wEl, nullptr, p_cb1, p_cb2, p_swd, out_fe, p_ef16, Ec);
    // attention: scores (needs q from sC + k from GEMM-E) then accumulate
    if (stream_ok) cudaStreamWaitEvent(0, ev_q, 0);
    attn_score_kernel<<<(Mc + 31) / 32, 256>>>();
    attn_accum_kernel<<<(Nc + 7) / 8, 256>>>(out_fv);
    // pred
    pred_kernel<<<(Nc + 7) / 8, 256>>>(out_fv, Wcls, bcls, out_pred);
}

// round 13
// speedup vs baseline: 4.0974x; 1.2452x over previous
#include <cuda_runtime.h>
#include <cuda_fp16.h>
#include <math.h>
#include <stdint.h>

#define Nc 50000
#define Ec 25000
#define Mc 300000
// dims: INPUT=VERTEX=EDGE=256, QUERY=64, NUM_CLASS=10

// ---------------- scratch ----------------
__device__ __half g_vf16[(size_t)Nc * 256];      // vfeat fp16
__device__ float g_qf[(size_t)Nc * 64];          // q fp32
__device__ __half g_aggv[(size_t)Ec * 256];      // aggregated raw vfeat per edge (fp16)
__device__ float g_swd[Ec];
__device__ __half g_ef16[(size_t)Ec * 320];      // cols 0-63 k, 64-319 v (fp16)
__device__ float g_attn[Mc];                     // precomputed attention scores (vlist order)
// composed weights
__device__ float g_wEf[576 * 256];               // [Wve@W1; Wke@Wve@W1; Wvale@Wve@W1] fp32
__device__ float g_wq1[64 * 256];                // Wqv@W1 fp32
__device__ __half g_wEh[576 * 256], g_wEl[576 * 256];
__device__ __half g_wQh[64 * 256], g_wQl[64 * 256];
__device__ float g_bve1[256];                    // Wve@b1 + bve
__device__ float g_qb[64];                       // Wqv@b1 + bqv
__device__ float g_cb1[576];                     // [bve1; Wke@bve1; Wvale@bve1]
__device__ float g_cb2[576];                     // [0; bke; bvale]
// CSR
__device__ int g_ebeg[Ec], g_vbeg[Nc], g_ecnt[Ec], g_vcnt[Nc];
__device__ int g_ecur[Ec], g_vcur[Nc];
__device__ int g_tote, g_totn;
__device__ int g_elist[Mc], g_vlist[Mc], g_vsrc[Mc];

// ---------------- CSR build ----------------
__global__ void zero_cnts_kernel() {
    int i = blockIdx.x * blockDim.x + threadIdx.x;
    if (i < Ec) g_ecnt[i] = 0;
    if (i < Nc) g_vcnt[i] = 0;
    if (i == 0) { g_tote = 0; g_totn = 0; }
}

__global__ void hist_kernel(const int* __restrict__ in_src, const int* __restrict__ in_dst) {
    int m = blockIdx.x * blockDim.x + threadIdx.x;
    if (m >= Mc) return;
    atomicAdd(&g_ecnt[in_dst[m]], 1);
    atomicAdd(&g_vcnt[in_src[m]], 1);
}

__global__ void assign_off_kernel() {
    int i = blockIdx.x * blockDim.x + threadIdx.x;
    int lane = threadIdx.x & 31;
    {
        int c = (i < Ec) ? g_ecnt[i] : 0;
        int x = c;
#pragma unroll
        for (int o = 1; o < 32; o <<= 1) {
            int y = __shfl_up_sync(0xffffffffu, x, o);
            if (lane >= o) x += y;
        }
        int wsum = __shfl_sync(0xffffffffu, x, 31);
        int base = 0;
        if (lane == 31 && wsum > 0) base = atomicAdd(&g_tote, wsum);
        base = __shfl_sync(0xffffffffu, base, 31);
        if (i < Ec) { int b = base + x - c; g_ebeg[i] = b; g_ecur[i] = b; }
    }
    {
        int c = (i < Nc) ? g_vcnt[i] : 0;
        int x = c;
#pragma unroll
        for (int o = 1; o < 32; o <<= 1) {
            int y = __shfl_up_sync(0xffffffffu, x, o);
            if (lane >= o) x += y;
        }
        int wsum = __shfl_sync(0xffffffffu, x, 31);
        int base = 0;
        if (lane == 31 && wsum > 0) base = atomicAdd(&g_totn, wsum);
        base = __shfl_sync(0xffffffffu, base, 31);
        if (i < Nc) { int b = base + x - c; g_vbeg[i] = b; g_vcur[i] = b; }
    }
}

__global__ void scatter_kernel(const int* __restrict__ in_src, const int* __restrict__ in_dst) {
    int m = blockIdx.x * blockDim.x + threadIdx.x;
    if (m >= Mc) return;
    int s = in_src[m];
    int e = in_dst[m];
    int pe = atomicAdd(&g_ecur[e], 1);
    g_elist[pe] = s;
    int pv = atomicAdd(&g_vcur[s], 1);
    g_vlist[pv] = e;
    g_vsrc[pv] = s;
}

// ---------------- weight composition (exact fp32) ----------------
__global__ void compose1(const float* __restrict__ Wve, const float* __restrict__ Wqv,
                         const float* __restrict__ W1) {
    int r = blockIdx.x, j = threadIdx.x;
    const float* A; float* C; int rr;
    if (r < 256) { A = Wve; C = g_wEf; rr = r; }
    else { A = Wqv; C = g_wq1; rr = r - 256; }
    float acc = 0.f;
    for (int k = 0; k < 256; k++) acc += A[rr * 256 + k] * W1[k * 256 + j];
    C[rr * 256 + j] = acc;
}

__global__ void compose2(const float* __restrict__ Wke, const float* __restrict__ Wvale) {
    int r = blockIdx.x, j = threadIdx.x;
    const float* A; int rr, outrow;
    if (r < 64) { A = Wke; rr = r; outrow = 256 + r; }
    else { A = Wvale; rr = r - 64; outrow = 320 + rr; }
    float acc = 0.f;
    for (int k = 0; k < 256; k++) acc += A[rr * 256 + k] * g_wEf[k * 256 + j];
    g_wEf[outrow * 256 + j] = acc;
}

__global__ void bias1(const float* __restrict__ Wve, const float* __restrict__ b1,
                      const float* __restrict__ bve, const float* __restrict__ Wqv,
                      const float* __restrict__ bqv) {
    int t = blockIdx.x * blockDim.x + threadIdx.x;
    int gw = t >> 5, lane = t & 31;
    if (gw >= 320) return;
    const float* M; int i; float add; float* dst;
    if (gw < 256) { M = Wve; i = gw; add = bve[i]; dst = &g_bve1[i]; }
    else { M = Wqv; i = gw - 256; add = bqv[i]; dst = &g_qb[i]; }
    float s = 0.f;
    for (int k = lane; k < 256; k += 32) s += M[i * 256 + k] * b1[k];
#pragma unroll
    for (int o = 16; o; o >>= 1) s += __shfl_xor_sync(0xffffffffu, s, o);
    if (lane == 0) *dst = s + add;
}

__global__ void bias2(const float* __restrict__ Wke, const float* __restrict__ Wvale,
                      const float* __restrict__ bke, const float* __restrict__ bvale) {
    int t = blockIdx.x * blockDim.x + threadIdx.x;
    int gw = t >> 5, lane = t & 31;
    if (gw < 320) {
        const float* M; int i; float* dst;
        if (gw < 64) { M = Wke; i = gw; dst = &g_cb1[256 + i]; }
        else { M = Wvale; i = gw - 64; dst = &g_cb1[320 + i]; }
        float s = 0.f;
        for (int k = lane; k < 256; k += 32) s += M[i * 256 + k] * g_bve1[k];
#pragma unroll
        for (int o = 16; o; o >>= 1) s += __shfl_xor_sync(0xffffffffu, s, o);
        if (lane == 0) *dst = s;
    }
    if (t < 256) { g_cb1[t] = g_bve1[t]; g_cb2[t] = 0.f; }
    else if (t < 320) g_cb2[t] = bke[t - 256];
    else if (t < 576) g_cb2[t] = bvale[t - 320];
}

// ---------------- fp32 -> fp16 conversions ----------------
__global__ void split_hl(const float4* __restrict__ src, __half* __restrict__ hi,
                         __half* __restrict__ lo, int n4) {
    int i = blockIdx.x * blockDim.x + threadIdx.x;
    if (i >= n4) return;
    float4 v = src[i];
    __half h0 = __float2half_rn(v.x), h1 = __float2half_rn(v.y);
    __half h2 = __float2half_rn(v.z), h3 = __float2half_rn(v.w);
    __half l0 = __float2half_rn(v.x - __half2float(h0));
    __half l1 = __float2half_rn(v.y - __half2float(h1));
    __half l2 = __float2half_rn(v.z - __half2float(h2));
    __half l3 = __float2half_rn(v.w - __half2float(h3));
    uint2 H, L;
    H.x = ((uint32_t)__half_as_ushort(h1) << 16) | __half_as_ushort(h0);
    H.y = ((uint32_t)__half_as_ushort(h3) << 16) | __half_as_ushort(h2);
    L.x = ((uint32_t)__half_as_ushort(l1) << 16) | __half_as_ushort(l0);
    L.y = ((uint32_t)__half_as_ushort(l3) << 16) | __half_as_ushort(l2);
    *(uint2*)(hi + (size_t)i * 4) = H;
    *(uint2*)(lo + (size_t)i * 4) = L;
}

__global__ void conv_h(const float4* __restrict__ src, __half* __restrict__ dst, int n4) {
    int i = blockIdx.x * blockDim.x + threadIdx.x;
    if (i >= n4) return;
    float4 v = src[i];
    uint2 H;
    H.x = ((uint32_t)__half_as_ushort(__float2half_rn(v.y)) << 16) | __half_as_ushort(__float2half_rn(v.x));
    H.y = ((uint32_t)__half_as_ushort(__float2half_rn(v.w)) << 16) | __half_as_ushort(__float2half_rn(v.z));
    *(uint2*)(dst + (size_t)i * 4) = H;
}

// ---------------- MMA helpers ----------------
__device__ __forceinline__ void mma16816h(float* d, const uint32_t* a, uint32_t b0, uint32_t b1) {
    asm volatile(
        "mma.sync.aligned.m16n8k16.row.col.f32.f16.f16.f32 "
        "{%0,%1,%2,%3},{%4,%5,%6,%7},{%8,%9},{%0,%1,%2,%3};"
        : "+f"(d[0]), "+f"(d[1]), "+f"(d[2]), "+f"(d[3])
        : "r"(a[0]), "r"(a[1]), "r"(a[2]), "r"(a[3]), "r"(b0), "r"(b1));
}

__device__ __forceinline__ void ldsm_x4(uint32_t* r, uint32_t addr) {
    asm volatile("ldmatrix.sync.aligned.m8n8.x4.shared.b16 {%0,%1,%2,%3}, [%4];"
                 : "=r"(r[0]), "=r"(r[1]), "=r"(r[2]), "=r"(r[3]) : "r"(addr));
}

__device__ __forceinline__ uint32_t smem_u32(const void* p) {
    uint32_t a;
    asm("{ .reg .u64 t; cvta.to.shared.u64 t, %1; cvt.u32.u64 %0, t; }" : "=r"(a) : "l"(p));
    return a;
}

__device__ __forceinline__ void cp_async16(uint32_t dst, const void* src, int src_bytes) {
    asm volatile("cp.async.cg.shared.global [%0], [%1], 16, %2;"
                 :: "r"(dst), "l"(src), "r"(src_bytes) : "memory");
}
#define CP_COMMIT() asm volatile("cp.async.commit_group;" ::: "memory")
#define CP_WAIT(n) asm volatile("cp.async.wait_group %0;" :: "n"(n) : "memory")

// ---------------- fp16x2 GEMM: C[M,NOUT] = A[M,256] @ W^T (+epilogue) ----------------
template <int BN, int NOUT, int MODE>
__global__ __launch_bounds__(256) void gemm_f16(
    const __half* __restrict__ A,
    const __half* __restrict__ whi, const __half* __restrict__ wlo,
    const float* __restrict__ bias,
    const float* __restrict__ cb1, const float* __restrict__ cb2,
    const float* __restrict__ swd,
    float* __restrict__ outA, __half* __restrict__ ef16,
    int Mrows) {
    constexpr int WN = BN / 2;
    constexpr int NF = WN / 8;
    constexpr int Ao = 0;
    constexpr int Bho = 5120;
    constexpr int Blo_ = 5120 + 40 * BN;
    constexpr int STG = 5120 + 80 * BN;
    extern __shared__ __half sm[];
    const uint32_t smb = smem_u32(sm);

    int tid = threadIdx.x;
    int lane = tid & 31, wid = tid >> 5;
    int wm = wid & 3, wn = wid >> 2;
    int qr = lane >> 2, qc = (lane & 3) * 2;
    int bm = blockIdx.x * 128, bn = blockIdx.y * BN;

    int a_row = wm * 32 + (lane & 7) + ((lane >> 3) & 1) * 8;
    int a_col = ((lane >> 4) & 1) * 8;
    int b_col = ((lane >> 3) & 1) * 8;
    int b_rowl = (lane & 7) + ((lane >> 4) & 1) * 8;

    float acc[2][NF][4];
#pragma unroll
    for (int mf = 0; mf < 2; mf++)
#pragma unroll
        for (int nf = 0; nf < NF; nf++)
#pragma unroll
            for (int j = 0; j < 4; j++) acc[mf][nf][j] = 0.f;

    auto load_chunk = [&](int ck, int stage) {
        uint32_t base = smb + (uint32_t)stage * (STG * 2);
#pragma unroll
        for (int i = 0; i < 2; i++) {
            int f = tid + i * 256;
            int row = f >> 2, sg = f & 3;
            int ok = (bm + row < Mrows) ? 16 : 0;
            cp_async16(base + (Ao + row * 40 + sg * 8) * 2,
                       A + (size_t)(bm + row) * 256 + ck * 32 + sg * 8, ok);
        }
        for (int f = tid; f < BN * 4; f += 256) {
            int row = f >> 2, sg = f & 3;
            size_t goff = (size_t)(bn + row) * 256 + ck * 32 + sg * 8;
            cp_async16(base + (Bho + row * 40 + sg * 8) * 2, whi + goff, 16);
            cp_async16(base + (Blo_ + row * 40 + sg * 8) * 2, wlo + goff, 16);
        }
    };

    load_chunk(0, 0);
    CP_COMMIT();

    for (int c = 0; c < 8; c++) {
        if (c < 7) {
            load_chunk(c + 1, (c + 1) & 1);
            CP_COMMIT();
            CP_WAIT(1);
        } else {
            CP_WAIT(0);
        }
        __syncthreads();
        uint32_t base = smb + (uint32_t)(c & 1) * (STG * 2);
#pragma unroll
        for (int ks = 0; ks < 32; ks += 16) {
            uint32_t ah[2][4];
#pragma unroll
            for (int mf = 0; mf < 2; mf++) {
                uint32_t off = ((a_row + mf * 16) * 40 + a_col + ks) * 2;
                ldsm_x4(ah[mf], base + Ao * 2 + off);
            }
            uint32_t bh[NF][2], bl[NF][2];
#pragma unroll
            for (int np = 0; np < NF / 2; np++) {
                uint32_t off = ((wn * WN + np * 16 + b_rowl) * 40 + b_col + ks) * 2;
                uint32_t t[4];
                ldsm_x4(t, base + Bho * 2 + off);
                bh[2 * np][0] = t[0]; bh[2 * np][1] = t[1];
                bh[2 * np + 1][0] = t[2]; bh[2 * np + 1][1] = t[3];
                ldsm_x4(t, base + Blo_ * 2 + off);
                bl[2 * np][0] = t[0]; bl[2 * np][1] = t[1];
                bl[2 * np + 1][0] = t[2]; bl[2 * np + 1][1] = t[3];
            }
#pragma unroll
            for (int nf = 0; nf < NF; nf++) {
#pragma unroll
                for (int mf = 0; mf < 2; mf++) {
                    mma16816h(acc[mf][nf], ah[mf], bh[nf][0], bh[nf][1]);
                    mma16816h(acc[mf][nf], ah[mf], bl[nf][0], bl[nf][1]);
                }
            }
        }
        __syncthreads();
    }

#pragma unroll
    for (int mf = 0; mf < 2; mf++) {
#pragma unroll
        for (int nf = 0; nf < NF; nf++) {
            int m0 = bm + wm * 32 + mf * 16 + qr;
            int n0 = bn + wn * WN + nf * 8 + qc;
            if (MODE == 0) {
                float bv0 = bias[n0], bv1 = bias[n0 + 1];
#pragma unroll
                for (int h = 0; h < 2; h++) {
                    int m = m0 + h * 8;
                    if (m >= Mrows) continue;
                    *(float2*)(outA + (size_t)m * NOUT + n0) =
                        make_float2(acc[mf][nf][h * 2] + bv0, acc[mf][nf][h * 2 + 1] + bv1);
                }
            } else {
                float e0 = cb1[n0], e1 = cb1[n0 + 1];
                float f0 = cb2[n0], f1 = cb2[n0 + 1];
#pragma unroll
                for (int h = 0; h < 2; h++) {
                    int m = m0 + h * 8;
                    if (m >= Mrows) continue;
                    float sw = swd[m];
                    float c0 = acc[mf][nf][h * 2] + sw * e0 + f0;
                    float c1 = acc[mf][nf][h * 2 + 1] + sw * e1 + f1;
                    if (n0 < 256) {
                        *(float2*)(outA + (size_t)m * 256 + n0) = make_float2(c0, c1);
                    } else {
                        uint32_t ph = ((uint32_t)__half_as_ushort(__float2half_rn(c1)) << 16) |
                                      __half_as_ushort(__float2half_rn(c0));
                        *(uint32_t*)(ef16 + (size_t)m * 320 + n0 - 256) = ph;
                    }
                }
            }
        }
    }
}

// ---------------- hyperedge aggregation: one warp per edge, uint4 loads ----------------
__global__ __launch_bounds__(256) void edge_agg_kernel(
    const float* __restrict__ vrw, const float* __restrict__ ers) {
    int e = (blockIdx.x * blockDim.x + threadIdx.x) >> 5;
    int lane = threadIdx.x & 31;
    if (e >= Ec) return;
    int beg = g_ebeg[e], cnt = g_ecnt[e];
    float acc[8];
#pragma unroll
    for (int j = 0; j < 8; j++) acc[j] = 0.f;
    float sw = 0.f;
    for (int i = beg; i < beg + cnt; i++) {
        int s = g_elist[i];
        float w = vrw[s];
        sw += w;
        uint4 raw = *(const uint4*)(g_vf16 + (size_t)s * 256 + lane * 8);
        float2 f0 = __half22float2(*(__half2*)&raw.x);
        float2 f1 = __half22float2(*(__half2*)&raw.y);
        float2 f2 = __half22float2(*(__half2*)&raw.z);
        float2 f3 = __half22float2(*(__half2*)&raw.w);
        acc[0] += w * f0.x; acc[1] += w * f0.y;
        acc[2] += w * f1.x; acc[3] += w * f1.y;
        acc[4] += w * f2.x; acc[5] += w * f2.y;
        acc[6] += w * f3.x; acc[7] += w * f3.y;
    }
    float inv = 1.f / ers[e];
    __half2 o[4];
#pragma unroll
    for (int j = 0; j < 4; j++)
        o[j] = __floats2half2_rn(acc[2 * j] * inv, acc[2 * j + 1] * inv);
    *(uint4*)(g_aggv + (size_t)e * 256 + lane * 8) = *(uint4*)o;
    if (lane == 0) g_swd[e] = sw * inv;
}

// ---------------- attention scores: edge-parallel (8 lanes/edge) ----------------
__global__ __launch_bounds__(256) void attn_score_kernel() {
    int t = blockIdx.x * 256 + threadIdx.x;
    int warp = t >> 5, lane = t & 31;
    int grp = lane >> 3, sub = lane & 7;
    int i = warp * 4 + grp;
    if (i >= Mc) return;
    int s = g_vsrc[i];
    int e = g_vlist[i];
    const float* q = g_qf + (size_t)s * 64 + sub * 8;
    float4 qa = *(const float4*)q;
    float4 qb = *(const float4*)(q + 4);
    uint4 kr = *(const uint4*)(g_ef16 + (size_t)e * 320 + sub * 8);
    float2 k0 = __half22float2(*(__half2*)&kr.x);
    float2 k1 = __half22float2(*(__half2*)&kr.y);
    float2 k2 = __half22float2(*(__half2*)&kr.z);
    float2 k3 = __half22float2(*(__half2*)&kr.w);
    float d = qa.x * k0.x + qa.y * k0.y + qa.z * k1.x + qa.w * k1.y +
              qb.x * k2.x + qb.y * k2.y + qb.z * k3.x + qb.w * k3.y;
    d += __shfl_xor_sync(0xffffffffu, d, 1);
    d += __shfl_xor_sync(0xffffffffu, d, 2);
    d += __shfl_xor_sync(0xffffffffu, d, 4);
    if (sub == 0) {
        d = (d > 0.f ? d : 0.01f * d) * 0.125f;
        g_attn[i] = d;
    }
}

// ---------------- attention accumulate: one warp/vertex, no shfl in loop ----------
__global__ __launch_bounds__(256) void attn_accum_kernel(float* __restrict__ out_fv) {
    int gw = (blockIdx.x * blockDim.x + threadIdx.x) >> 5;
    int lane = threadIdx.x & 31;
    if (gw >= Nc) return;
    int beg = g_vbeg[gw], cnt = g_vcnt[gw];

    float mx = -1e30f;
    for (int base = 0; base < cnt; base += 32) {
        int i = base + lane;
        if (i < cnt) mx = fmaxf(mx, g_attn[beg + i]);
    }
#pragma unroll
    for (int o = 16; o; o >>= 1) mx = fmaxf(mx, __shfl_xor_sync(0xffffffffu, mx, o));

    float denom = 0.f;
    float acc[8];
#pragma unroll
    for (int j = 0; j < 8; j++) acc[j] = 0.f;
#pragma unroll 2
    for (int i = beg; i < beg + cnt; i++) {
        float p = __expf(g_attn[i] - mx);
        denom += p;
        int e = g_vlist[i];
        uint4 raw = *(const uint4*)(g_ef16 + (size_t)e * 320 + 64 + lane * 8);
        float2 f0 = __half22float2(*(__half2*)&raw.x);
        float2 f1 = __half22float2(*(__half2*)&raw.y);
        float2 f2 = __half22float2(*(__half2*)&raw.z);
        float2 f3 = __half22float2(*(__half2*)&raw.w);
        acc[0] += p * f0.x; acc[1] += p * f0.y;
        acc[2] += p * f1.x; acc[3] += p * f1.y;
        acc[4] += p * f2.x; acc[5] += p * f2.y;
        acc[6] += p * f3.x; acc[7] += p * f3.y;
    }
    float inv = 1.f / fmaxf(denom, 1e-20f);
#pragma unroll
    for (int j = 0; j < 8; j++) acc[j] *= inv;
    float4* op = (float4*)(out_fv + (size_t)gw * 256 + lane * 8);
    op[0] = make_float4(acc[0], acc[1], acc[2], acc[3]);
    op[1] = make_float4(acc[4], acc[5], acc[6], acc[7]);
}

// ---------------- classification head ----------------
__global__ __launch_bounds__(256) void pred_kernel(
    const float* __restrict__ fv, const float* __restrict__ Wc,
    const float* __restrict__ bc, float* __restrict__ pred) {
    __shared__ float sW[10 * 256];
    __shared__ float sb_[10];
    int t = threadIdx.x;
    for (int i = t; i < 2560; i += 256) sW[i] = Wc[i];
    if (t < 10) sb_[t] = bc[t];
    __syncthreads();
    int warp = t >> 5, lane = t & 31;
    int r = blockIdx.x * 8 + warp;
    if (r >= Nc) return;
    float acc[10];
#pragma unroll
    for (int c = 0; c < 10; c++) acc[c] = 0.f;
    for (int kk = lane; kk < 256; kk += 32) {
        float x = fv[(size_t)r * 256 + kk];
#pragma unroll
        for (int c = 0; c < 10; c++) acc[c] += x * sW[c * 256 + kk];
    }
#pragma unroll
    for (int c = 0; c < 10; c++) {
#pragma unroll
        for (int o = 16; o; o >>= 1) acc[c] += __shfl_xor_sync(0xffffffffu, acc[c], o);
    }
    if (lane == 0) {
#pragma unroll
        for (int c = 0; c < 10; c++) pred[(size_t)r * 10 + c] = acc[c] + sb_[c];
    }
}

// ---------------- launch ----------------
extern "C" void kernel_launch(void* const* d_in, const int* in_sizes, int n_in,
                              void* d_out, int out_size) {
    const float* vfeat = (const float*)d_in[0];
    const float* vrw = (const float*)d_in[2];
    const float* ers = (const float*)d_in[5];
    const float* W1 = (const float*)d_in[6];
    const float* b1 = (const float*)d_in[7];
    const float* Wve = (const float*)d_in[8];
    const float* bve = (const float*)d_in[9];
    const float* Wqv = (const float*)d_in[10];
    const float* bqv = (const float*)d_in[11];
    const float* Wke = (const float*)d_in[12];
    const float* bke = (const float*)d_in[13];
    const float* Wvale = (const float*)d_in[14];
    const float* bvale = (const float*)d_in[15];
    const float* Wcls = (const float*)d_in[16];
    const float* bcls = (const float*)d_in[17];
    const int* in_src = (const int*)d_in[18];
    const int* in_dst = (const int*)d_in[19];

    float* out = (float*)d_out;
    float* out_fv = out;
    float* out_fe = out + (size_t)Nc * 256;
    float* out_pred = out_fe + (size_t)Ec * 256;

    __half *p_vf16, *p_aggv, *p_wEh, *p_wEl, *p_wQh, *p_wQl, *p_ef16;
    float *p_wEf, *p_wq1, *p_qf, *p_qb, *p_cb1, *p_cb2, *p_swd;
    cudaGetSymbolAddress((void**)&p_vf16, g_vf16);
    cudaGetSymbolAddress((void**)&p_aggv, g_aggv);
    cudaGetSymbolAddress((void**)&p_wEh, g_wEh);
    cudaGetSymbolAddress((void**)&p_wEl, g_wEl);
    cudaGetSymbolAddress((void**)&p_wQh, g_wQh);
    cudaGetSymbolAddress((void**)&p_wQl, g_wQl);
    cudaGetSymbolAddress((void**)&p_ef16, g_ef16);
    cudaGetSymbolAddress((void**)&p_wEf, g_wEf);
    cudaGetSymbolAddress((void**)&p_wq1, g_wq1);
    cudaGetSymbolAddress((void**)&p_qf, g_qf);
    cudaGetSymbolAddress((void**)&p_qb, g_qb);
    cudaGetSymbolAddress((void**)&p_cb1, g_cb1);
    cudaGetSymbolAddress((void**)&p_cb2, g_cb2);
    cudaGetSymbolAddress((void**)&p_swd, g_swd);

    const int SMEM64 = 2 * (5120 + 80 * 64) * 2;   // 40960 B
    const int SMEM96 = 2 * (5120 + 80 * 96) * 2;   // 51200 B (> 48KB default: needs attr)

    static cudaStream_t sB = 0, sC = 0;
    static cudaEvent_t ev_fork = 0, ev_csr = 0, ev_conv = 0, ev_w = 0, ev_q = 0;
    static int stream_ok = -1;
    if (stream_ok < 0) {
        // one-time resource + attribute setup (R12 bug: missing smem attribute for BN=96)
        cudaFuncSetAttribute(gemm_f16<96, 576, 1>, cudaFuncAttributeMaxDynamicSharedMemorySize, SMEM96);
        cudaFuncSetAttribute(gemm_f16<64, 64, 0>, cudaFuncAttributeMaxDynamicSharedMemorySize, SMEM64);
        cudaError_t e1 = cudaStreamCreateWithFlags(&sB, cudaStreamNonBlocking);
        cudaError_t e2 = cudaStreamCreateWithFlags(&sC, cudaStreamNonBlocking);
        cudaError_t e3 = cudaEventCreateWithFlags(&ev_fork, cudaEventDisableTiming);
        cudaError_t e4 = cudaEventCreateWithFlags(&ev_csr, cudaEventDisableTiming);
        cudaError_t e5 = cudaEventCreateWithFlags(&ev_conv, cudaEventDisableTiming);
        cudaError_t e6 = cudaEventCreateWithFlags(&ev_w, cudaEventDisableTiming);
        cudaError_t e7 = cudaEventCreateWithFlags(&ev_q, cudaEventDisableTiming);
        stream_ok = (e1 == cudaSuccess && e2 == cudaSuccess && e3 == cudaSuccess &&
                     e4 == cudaSuccess && e5 == cudaSuccess && e6 == cudaSuccess &&
                     e7 == cudaSuccess) ? 1 : 0;
    }
    cudaStream_t sb = stream_ok ? sB : 0;
    cudaStream_t sc = stream_ok ? sC : 0;

    if (stream_ok) {
        cudaEventRecord(ev_fork, 0);
        cudaStreamWaitEvent(sB, ev_fork, 0);
        cudaStreamWaitEvent(sC, ev_fork, 0);
    }

    // stream B: CSR build
    zero_cnts_kernel<<<(Nc + 255) / 256, 256, 0, sb>>>();
    hist_kernel<<<(Mc + 255) / 256, 256, 0, sb>>>(in_src, in_dst);
    assign_off_kernel<<<(Nc + 255) / 256, 256, 0, sb>>>();
    scatter_kernel<<<(Mc + 255) / 256, 256, 0, sb>>>(in_src, in_dst);
    if (stream_ok) cudaEventRecord(ev_csr, sB);

    const int gN = (Nc + 127) / 128;  // 391
    const int gE = (Ec + 127) / 128;  // 196

    // main: vfeat conversion
    conv_h<<<(Nc * 64 + 255) / 256, 256>>>((const float4*)vfeat, p_vf16, Nc * 64);
    if (stream_ok) cudaEventRecord(ev_conv, 0);

    // stream C: weight composition + splits; record ev_w, then q GEMM
    compose1<<<320, 256, 0, sc>>>(Wve, Wqv, W1);
    bias1<<<40, 256, 0, sc>>>(Wve, b1, bve, Wqv, bqv);
    compose2<<<320, 256, 0, sc>>>(Wke, Wvale);
    bias2<<<40, 256, 0, sc>>>(Wke, Wvale, bke, bvale);
    split_hl<<<(576 * 64 + 255) / 256, 256, 0, sc>>>((const float4*)p_wEf, p_wEh, p_wEl, 576 * 64);
    split_hl<<<(64 * 64 + 255) / 256, 256, 0, sc>>>((const float4*)p_wq1, p_wQh, p_wQl, 64 * 64);
    if (stream_ok) cudaEventRecord(ev_w, sC);
    if (stream_ok) cudaStreamWaitEvent(sC, ev_conv, 0);
    gemm_f16<64, 64, 0><<<dim3(gN, 1), 256, SMEM64, sc>>>(
        p_vf16, p_wQh, p_wQl, p_qb, nullptr, nullptr, nullptr, p_qf, nullptr, Nc);
    if (stream_ok) cudaEventRecord(ev_q, sC);

    // main: edge aggregation (needs vf16 + CSR); warp per edge
    if (stream_ok) cudaStreamWaitEvent(0, ev_csr, 0);
    edge_agg_kernel<<<(Ec * 32 + 255) / 256, 256>>>(vrw, ers);
    // GEMM-E needs composed/split weights
    if (stream_ok) cudaStreamWaitEvent(0, ev_w, 0);
    gemm_f16<96, 576, 1><<<dim3(gE, 6), 256, SMEM96>>>(
        p_aggv, p_wEh, p_wEl, nullptr, p_cb1, p_cb2, p_swd, out_fe, p_ef16, Ec);
    // attention: scores then accumulate
    if (stream_ok) cudaStreamWaitEvent(0, ev_q, 0);
    attn_score_kernel<<<(Mc + 31) / 32, 256>>>();
    attn_accum_kernel<<<(Nc + 7) / 8, 256>>>(out_fv);
    // pred
    pred_kernel<<<(Nc + 7) / 8, 256>>>(out_fv, Wcls, bcls, out_pred);
}